// round 1
// baseline (speedup 1.0000x reference)
#include <cuda_runtime.h>
#include <math.h>

#define EMB   768
#define HEADS 8
#define HD    96
#define BATCH 4
#define SEQ   2048
#define BHN   (BATCH*HEADS)
#define MTOT  (BATCH*SEQ)

// Scratch (module-load allocated, not counted against runtime alloc guards)
__device__ float g_Q[(size_t)BHN * HD * SEQ];   // [bh][d][n]  d-major
__device__ float g_K[(size_t)BHN * HD * SEQ];   // [bh][d][n]  d-major
__device__ float g_V[(size_t)BHN * SEQ * HD];   // [bh][n][d]  n-major
__device__ float g_O[(size_t)MTOT * EMB];       // [b*n][e]    natural

// ---------------------------------------------------------------------------
// SGEMM: out = X[M,768] @ W[768,768] + bias, with layout-remapping epilogue.
// Tile 128x128x8, 256 threads, 8x8 micro-tile per thread.
// mode 0: write d-major  [bh][d][n]   (Q, K)
// mode 1: write n-major  [bh][n][d]   (V)
// mode 2: write natural  [m][c]       (attention out / final out)
// ---------------------------------------------------------------------------
__global__ __launch_bounds__(256) void gemm_proj(
    const float* __restrict__ X, const float* __restrict__ W,
    const float* __restrict__ bias, float* __restrict__ out, int mode)
{
    __shared__ float As[8][128];
    __shared__ float Bs[8][128];

    const int tid = threadIdx.x;
    const int bx  = blockIdx.x;          // n-tile  (0..5)
    const int by  = blockIdx.y;          // m-tile  (0..63)

    const int a_row = tid >> 1;          // 0..127
    const int a_kc  = (tid & 1) * 4;     // 0 or 4
    const int b_kr  = tid >> 5;          // 0..7
    const int b_nc  = (tid & 31) * 4;    // 0..124

    const int ty = tid >> 4;             // 0..15 -> rows ty*8..ty*8+7
    const int tx = tid & 15;             // 0..15 -> cols tx*8..tx*8+7

    float acc[8][8];
    #pragma unroll
    for (int i = 0; i < 8; i++)
        #pragma unroll
        for (int j = 0; j < 8; j++) acc[i][j] = 0.f;

    const float* Xp = X + (size_t)(by * 128 + a_row) * EMB;
    const float* Wp = W + bx * 128 + b_nc;

    for (int k0 = 0; k0 < EMB; k0 += 8) {
        float4 av = *(const float4*)(Xp + k0 + a_kc);
        As[a_kc + 0][a_row] = av.x;
        As[a_kc + 1][a_row] = av.y;
        As[a_kc + 2][a_row] = av.z;
        As[a_kc + 3][a_row] = av.w;
        *(float4*)&Bs[b_kr][b_nc] = *(const float4*)(Wp + (size_t)(k0 + b_kr) * EMB);
        __syncthreads();

        #pragma unroll
        for (int kk = 0; kk < 8; kk++) {
            float a[8], b[8];
            *(float4*)(a)     = *(float4*)&As[kk][ty * 8];
            *(float4*)(a + 4) = *(float4*)&As[kk][ty * 8 + 4];
            *(float4*)(b)     = *(float4*)&Bs[kk][tx * 8];
            *(float4*)(b + 4) = *(float4*)&Bs[kk][tx * 8 + 4];
            #pragma unroll
            for (int i = 0; i < 8; i++)
                #pragma unroll
                for (int j = 0; j < 8; j++)
                    acc[i][j] = fmaf(a[i], b[j], acc[i][j]);
        }
        __syncthreads();
    }

    // Epilogue with layout remap
    #pragma unroll
    for (int i = 0; i < 8; i++) {
        const int m  = by * 128 + ty * 8 + i;
        const int bb = m >> 11;          // m / SEQ
        const int n  = m & (SEQ - 1);    // m % SEQ
        #pragma unroll
        for (int j = 0; j < 8; j++) {
            const int c = bx * 128 + tx * 8 + j;
            const float v = acc[i][j] + bias[c];
            if (mode == 0) {
                const int h = c / HD, d = c % HD;
                out[((size_t)(bb * HEADS + h) * HD + d) * SEQ + n] = v;
            } else if (mode == 1) {
                const int h = c / HD, d = c % HD;
                out[((size_t)(bb * HEADS + h) * SEQ + n) * HD + d] = v;
            } else {
                out[(size_t)m * EMB + c] = v;
            }
        }
    }
}

// ---------------------------------------------------------------------------
// Flash attention, fp32. 64 q-rows per CTA, 64-key tiles, online softmax.
// Thread grid 16x16: ty -> 4 q-rows, tx -> 4 k-cols (S) / 6 strided d-cols (O).
// Ref semantics: softmax(UNSCALED logits) then /sqrt(96), folded into epilogue.
// ---------------------------------------------------------------------------
__global__ __launch_bounds__(256) void attn_kernel()
{
    extern __shared__ float sm[];
    float* Qs = sm;                 // [96][64]  24KB
    float* Ks = sm + 96 * 64;       // [96][64]  24KB
    float* Vs = sm + 2 * 96 * 64;   // [64][96]  24KB
    float* Ps = sm + 3 * 96 * 64;   // [64][64]  16KB  (k-major, row contiguous)

    const int tid = threadIdx.x;
    const int ty  = tid >> 4;       // 0..15
    const int tx  = tid & 15;       // 0..15
    const int q0  = blockIdx.x * 64;
    const int bh  = blockIdx.y;

    const float* Qbh = g_Q + (size_t)bh * HD * SEQ;
    const float* Kbh = g_K + (size_t)bh * HD * SEQ;
    const float* Vbh = g_V + (size_t)bh * SEQ * HD;

    // Load Q tile: Qs[d][r]
    for (int i = tid; i < 96 * 16; i += 256) {
        const int d = i >> 4, r4 = (i & 15) * 4;
        *(float4*)&Qs[d * 64 + r4] = *(const float4*)(Qbh + (size_t)d * SEQ + q0 + r4);
    }

    float m_i[4], l_i[4], o[4][6];
    #pragma unroll
    for (int i = 0; i < 4; i++) {
        m_i[i] = -INFINITY; l_i[i] = 0.f;
        #pragma unroll
        for (int j = 0; j < 6; j++) o[i][j] = 0.f;
    }

    for (int kt = 0; kt < SEQ; kt += 64) {
        // Load K tile (d-major) and V tile (n-major, flat copy)
        for (int i = tid; i < 96 * 16; i += 256) {
            const int d = i >> 4, r4 = (i & 15) * 4;
            *(float4*)&Ks[d * 64 + r4] = *(const float4*)(Kbh + (size_t)d * SEQ + kt + r4);
        }
        const float4* vsrc = (const float4*)(Vbh + (size_t)kt * HD);
        for (int i = tid; i < 64 * 24; i += 256)
            ((float4*)Vs)[i] = vsrc[i];
        __syncthreads();

        // S = Q @ K^T  (64x64, 4x4 per thread)
        float s[4][4];
        #pragma unroll
        for (int i = 0; i < 4; i++)
            #pragma unroll
            for (int j = 0; j < 4; j++) s[i][j] = 0.f;

        #pragma unroll 4
        for (int d = 0; d < 96; ++d) {
            float4 q4 = *(float4*)&Qs[d * 64 + ty * 4];
            float4 k4 = *(float4*)&Ks[d * 64 + tx * 4];
            float qa[4] = {q4.x, q4.y, q4.z, q4.w};
            float ka[4] = {k4.x, k4.y, k4.z, k4.w};
            #pragma unroll
            for (int i = 0; i < 4; i++)
                #pragma unroll
                for (int j = 0; j < 4; j++)
                    s[i][j] = fmaf(qa[i], ka[j], s[i][j]);
        }

        // Online softmax (row stats across 16 tx lanes, aligned 16-lane groups)
        #pragma unroll
        for (int i = 0; i < 4; i++) {
            float mx = fmaxf(fmaxf(s[i][0], s[i][1]), fmaxf(s[i][2], s[i][3]));
            mx = fmaxf(mx, __shfl_xor_sync(0xffffffffu, mx, 1));
            mx = fmaxf(mx, __shfl_xor_sync(0xffffffffu, mx, 2));
            mx = fmaxf(mx, __shfl_xor_sync(0xffffffffu, mx, 4));
            mx = fmaxf(mx, __shfl_xor_sync(0xffffffffu, mx, 8));
            const float mnew  = fmaxf(m_i[i], mx);
            const float alpha = __expf(m_i[i] - mnew);   // first tile: exp(-inf)=0
            m_i[i] = mnew;
            float rs = 0.f;
            #pragma unroll
            for (int j = 0; j < 4; j++) {
                s[i][j] = __expf(s[i][j] - mnew);
                rs += s[i][j];
            }
            rs += __shfl_xor_sync(0xffffffffu, rs, 1);
            rs += __shfl_xor_sync(0xffffffffu, rs, 2);
            rs += __shfl_xor_sync(0xffffffffu, rs, 4);
            rs += __shfl_xor_sync(0xffffffffu, rs, 8);
            l_i[i] = l_i[i] * alpha + rs;
            #pragma unroll
            for (int j = 0; j < 6; j++) o[i][j] *= alpha;
        }

        // Stage P to smem (k-major so PV reads are float4 over rows)
        #pragma unroll
        for (int j = 0; j < 4; j++) {
            float4 pv = make_float4(s[0][j], s[1][j], s[2][j], s[3][j]);
            *(float4*)&Ps[(tx * 4 + j) * 64 + ty * 4] = pv;
        }
        __syncthreads();

        // O += P @ V   (rows ty*4.., cols tx+16j)
        #pragma unroll 4
        for (int k = 0; k < 64; k++) {
            float4 pv = *(float4*)&Ps[k * 64 + ty * 4];
            const float* vr = &Vs[k * 96];
            #pragma unroll
            for (int j = 0; j < 6; j++) {
                const float vv = vr[tx + 16 * j];
                o[0][j] = fmaf(pv.x, vv, o[0][j]);
                o[1][j] = fmaf(pv.y, vv, o[1][j]);
                o[2][j] = fmaf(pv.z, vv, o[2][j]);
                o[3][j] = fmaf(pv.w, vv, o[3][j]);
            }
        }
        __syncthreads();
    }

    // Epilogue: /(l * sqrt(96)), write natural layout [b][n][h*96+d]
    const int bb = bh >> 3, h = bh & 7;
    #pragma unroll
    for (int i = 0; i < 4; i++) {
        const float scale = 0.10206207261596577f / l_i[i];
        const int row = q0 + ty * 4 + i;
        float* op = g_O + ((size_t)bb * SEQ + row) * EMB + h * HD;
        #pragma unroll
        for (int j = 0; j < 6; j++) op[tx + 16 * j] = o[i][j] * scale;
    }
}

// ---------------------------------------------------------------------------
extern "C" void kernel_launch(void* const* d_in, const int* in_sizes, int n_in,
                              void* d_out, int out_size)
{
    const float* x  = (const float*)d_in[0];
    const float* Wq = (const float*)d_in[1];
    const float* bq = (const float*)d_in[2];
    const float* Wk = (const float*)d_in[3];
    const float* bk = (const float*)d_in[4];
    const float* Wv = (const float*)d_in[5];
    const float* bv = (const float*)d_in[6];
    const float* Wo = (const float*)d_in[7];
    const float* bo = (const float*)d_in[8];
    float* out = (float*)d_out;

    float *qb, *kb, *vb, *ob;
    cudaGetSymbolAddress((void**)&qb, g_Q);
    cudaGetSymbolAddress((void**)&kb, g_K);
    cudaGetSymbolAddress((void**)&vb, g_V);
    cudaGetSymbolAddress((void**)&ob, g_O);

    const dim3 gg(EMB / 128, MTOT / 128);   // (6, 64)

    gemm_proj<<<gg, 256>>>(x, Wq, bq, qb, 0);
    gemm_proj<<<gg, 256>>>(x, Wk, bk, kb, 0);
    gemm_proj<<<gg, 256>>>(x, Wv, bv, vb, 1);

    const int attn_smem = (3 * 96 * 64 + 64 * 64) * (int)sizeof(float);  // 90112 B
    cudaFuncSetAttribute(attn_kernel, cudaFuncAttributeMaxDynamicSharedMemorySize, attn_smem);
    attn_kernel<<<dim3(SEQ / 64, BHN), 256, attn_smem>>>();

    gemm_proj<<<gg, 256>>>(ob, Wo, bo, out, 2);
}

// round 3
// speedup vs baseline: 2.6483x; 2.6483x over previous
#include <cuda_runtime.h>
#include <cuda_bf16.h>
#include <cstdint>
#include <math.h>

#define EMB   768
#define HEADS 8
#define HD    96
#define BATCH 4
#define SEQ   2048
#define BHN   (BATCH*HEADS)
#define MTOT  (BATCH*SEQ)
#define KCAT  (3*EMB)        // 2304

// ---------------- scratch globals (module-load allocated) -------------------
__device__ __nv_bfloat16 g_Xc[(size_t)MTOT * KCAT];    // x split-concat  (hi,lo,hi)
__device__ __nv_bfloat16 g_Oc[(size_t)MTOT * KCAT];    // attn-out split-concat
__device__ __nv_bfloat16 g_Wc[4][(size_t)EMB * KCAT];  // W^T split-concat (hi,hi,lo)
__device__ __nv_bfloat16 g_Qh[(size_t)BHN * SEQ * HD];
__device__ __nv_bfloat16 g_Ql[(size_t)BHN * SEQ * HD];
__device__ __nv_bfloat16 g_Kh[(size_t)BHN * SEQ * HD];
__device__ __nv_bfloat16 g_Kl[(size_t)BHN * SEQ * HD];
__device__ __nv_bfloat16 g_Vh[(size_t)BHN * SEQ * HD];
__device__ __nv_bfloat16 g_Vl[(size_t)BHN * SEQ * HD];
__device__ float g_O[(size_t)MTOT * EMB];

// ---------------- helpers ---------------------------------------------------
__device__ __forceinline__ uint32_t smem_u32(const void* p) {
    uint32_t a;
    asm("{ .reg .u64 t; cvta.to.shared.u64 t, %1; cvt.u32.u64 %0, t; }" : "=r"(a) : "l"(p));
    return a;
}
__device__ __forceinline__ void cpa16(uint32_t d, const void* s) {
    asm volatile("cp.async.cg.shared.global [%0], [%1], 16;" :: "r"(d), "l"(s));
}
#define CP_COMMIT() asm volatile("cp.async.commit_group;")
#define CP_WAIT0()  asm volatile("cp.async.wait_group 0;")
#define CP_WAIT1()  asm volatile("cp.async.wait_group 1;")

__device__ __forceinline__ void ldm4(uint32_t* r, uint32_t addr) {
    asm volatile("ldmatrix.sync.aligned.m8n8.x4.shared.b16 {%0,%1,%2,%3}, [%4];"
        : "=r"(r[0]), "=r"(r[1]), "=r"(r[2]), "=r"(r[3]) : "r"(addr));
}
__device__ __forceinline__ void ldm4t(uint32_t* r, uint32_t addr) {
    asm volatile("ldmatrix.sync.aligned.m8n8.x4.trans.shared.b16 {%0,%1,%2,%3}, [%4];"
        : "=r"(r[0]), "=r"(r[1]), "=r"(r[2]), "=r"(r[3]) : "r"(addr));
}
__device__ __forceinline__ void mma_bf16(float* c, const uint32_t* a, uint32_t b0, uint32_t b1) {
    asm volatile("mma.sync.aligned.m16n8k16.row.col.f32.bf16.bf16.f32 "
        "{%0,%1,%2,%3}, {%4,%5,%6,%7}, {%8,%9}, {%0,%1,%2,%3};"
        : "+f"(c[0]), "+f"(c[1]), "+f"(c[2]), "+f"(c[3])
        : "r"(a[0]), "r"(a[1]), "r"(a[2]), "r"(a[3]), "r"(b0), "r"(b1));
}
__device__ __forceinline__ void split2(float x, float y, uint32_t& hi, uint32_t& lo) {
    __nv_bfloat162 h, l;
    h.x = __float2bfloat16(x);
    h.y = __float2bfloat16(y);
    l.x = __float2bfloat16(x - __bfloat162float(h.x));
    l.y = __float2bfloat16(y - __bfloat162float(h.y));
    hi = *(uint32_t*)&h;
    lo = *(uint32_t*)&l;
}

// ===========================================================================
// convert: fp32 [M][768] -> bf16 [M][2304] segments (hi, lo, hi)  (A operand)
// ===========================================================================
__global__ __launch_bounds__(256) void convert_cat(
    const float* __restrict__ in, __nv_bfloat16* __restrict__ out)
{
    const int i = blockIdx.x * 256 + threadIdx.x;   // < MTOT*192
    const int row = i / 192, c = (i % 192) * 4;
    const float4 v = ((const float4*)in)[i];
    __nv_bfloat16 h[4], l[4];
    const float vv[4] = {v.x, v.y, v.z, v.w};
    #pragma unroll
    for (int j = 0; j < 4; j++) {
        h[j] = __float2bfloat16(vv[j]);
        l[j] = __float2bfloat16(vv[j] - __bfloat162float(h[j]));
    }
    __nv_bfloat16* o = out + (size_t)row * KCAT + c;
    *(uint2*)(o)        = *(uint2*)h;
    *(uint2*)(o + EMB)  = *(uint2*)l;
    *(uint2*)(o + 2*EMB)= *(uint2*)h;
}

// ===========================================================================
// weight transpose + split: W [k][n] fp32 -> Wc [n][2304] bf16 (hi, hi, lo)
// ===========================================================================
__global__ void wconvert(const float* __restrict__ W, __nv_bfloat16* __restrict__ out)
{
    __shared__ float t[32][33];
    const int tx = threadIdx.x, ty = threadIdx.y;
    const int x = blockIdx.x * 32 + tx;
    const int y0 = blockIdx.y * 32;
    #pragma unroll
    for (int i = ty; i < 32; i += 8)
        t[i][tx] = W[(size_t)(y0 + i) * EMB + x];
    __syncthreads();
    #pragma unroll
    for (int i = ty; i < 32; i += 8) {
        const int n = blockIdx.x * 32 + i;
        const int k = y0 + tx;
        const float v = t[tx][i];
        const __nv_bfloat16 h = __float2bfloat16(v);
        const __nv_bfloat16 l = __float2bfloat16(v - __bfloat162float(h));
        __nv_bfloat16* o = out + (size_t)n * KCAT + k;
        o[0]      = h;
        o[EMB]    = h;
        o[2*EMB]  = l;
    }
}

// ===========================================================================
// bf16 tensor-core GEMM:  C[m][n] = sum_{k<2304} A[m][k']*B[n][k'] + bias[n]
// CTA 128x128, 8 warps (2m x 4n), warp tile 64x32, k-chunk 32, double buffer.
// mode 0: split epilogue -> outh/outl bf16 [bh][n][96]
// mode 2: fp32 natural [m][768] -> outf
// ===========================================================================
#define GPAD 40
__global__ __launch_bounds__(256) void gemm_bf16(
    const __nv_bfloat16* __restrict__ A, const __nv_bfloat16* __restrict__ B,
    const float* __restrict__ bias, float* __restrict__ outf,
    __nv_bfloat16* __restrict__ outh, __nv_bfloat16* __restrict__ outl, int mode)
{
    __shared__ __nv_bfloat16 As[2][128 * GPAD];
    __shared__ __nv_bfloat16 Bs[2][128 * GPAD];

    const int tid = threadIdx.x;
    const int wid = tid >> 5, lane = tid & 31;
    const int midx = lane >> 3, lrow = lane & 7;
    const int m0 = blockIdx.y * 128, n0 = blockIdx.x * 128;
    const int wm = (wid & 1) * 64, wn = (wid >> 1) * 32;

    const uint32_t sA = smem_u32(As), sB = smem_u32(Bs);
    const uint32_t BUFB = 128 * GPAD * 2;

    float acc[4][4][4];
    #pragma unroll
    for (int a = 0; a < 4; a++)
        #pragma unroll
        for (int b = 0; b < 4; b++)
            #pragma unroll
            for (int c = 0; c < 4; c++) acc[a][b][c] = 0.f;

    const int lr = tid >> 2, ls = tid & 3;

    auto load_chunk = [&](int buf, int kc) {
        const uint32_t so = (uint32_t)buf * BUFB + (lr * GPAD + ls * 8) * 2;
        const __nv_bfloat16* ga = A + (size_t)(m0 + lr) * KCAT + kc + ls * 8;
        const __nv_bfloat16* gb = B + (size_t)(n0 + lr) * KCAT + kc + ls * 8;
        cpa16(sA + so, ga);
        cpa16(sB + so, gb);
        cpa16(sA + so + 64 * GPAD * 2, ga + (size_t)64 * KCAT);
        cpa16(sB + so + 64 * GPAD * 2, gb + (size_t)64 * KCAT);
    };

    auto compute = [&](int buf) {
        const uint32_t base = (uint32_t)buf * BUFB;
        #pragma unroll
        for (int kk = 0; kk < 32; kk += 16) {
            uint32_t af[4][4];
            #pragma unroll
            for (int mt = 0; mt < 4; mt++) {
                const uint32_t addr = sA + base +
                    ((wm + mt * 16 + (midx & 1) * 8 + lrow) * GPAD + kk + (midx >> 1) * 8) * 2;
                ldm4(af[mt], addr);
            }
            #pragma unroll
            for (int np = 0; np < 2; np++) {
                uint32_t bf4[4];
                const uint32_t addr = sB + base +
                    ((wn + np * 16 + (midx >> 1) * 8 + lrow) * GPAD + kk + (midx & 1) * 8) * 2;
                ldm4(bf4, addr);
                #pragma unroll
                for (int h2 = 0; h2 < 2; h2++) {
                    const int nt = np * 2 + h2;
                    #pragma unroll
                    for (int mt = 0; mt < 4; mt++)
                        mma_bf16(acc[mt][nt], af[mt], bf4[h2 * 2], bf4[h2 * 2 + 1]);
                }
            }
        }
    };

    load_chunk(0, 0);
    CP_COMMIT();
    int buf = 0;
    for (int c = 0; c < KCAT / 32; c++) {
        if (c < KCAT / 32 - 1) {
            load_chunk(buf ^ 1, (c + 1) * 32);
            CP_COMMIT();
            CP_WAIT1();
        } else {
            CP_WAIT0();
        }
        __syncthreads();
        compute(buf);
        __syncthreads();
        buf ^= 1;
    }

    // epilogue
    #pragma unroll
    for (int mt = 0; mt < 4; mt++) {
        #pragma unroll
        for (int nt = 0; nt < 4; nt++) {
            const int r  = wm + mt * 16 + (lane >> 2);
            const int cc = n0 + wn + nt * 8 + (lane & 3) * 2;
            #pragma unroll
            for (int half = 0; half < 2; half++) {        // rows r, r+8
                const int m = m0 + r + half * 8;
                const float v0 = acc[mt][nt][half * 2]     + bias[cc];
                const float v1 = acc[mt][nt][half * 2 + 1] + bias[cc + 1];
                if (mode == 0) {
                    const int bb = m >> 11, nn = m & (SEQ - 1);
                    const int h0 = cc / HD, d0 = cc % HD;
                    const int h1 = (cc + 1) / HD, d1 = (cc + 1) % HD;
                    const size_t i0 = ((size_t)(bb * HEADS + h0) * SEQ + nn) * HD + d0;
                    const size_t i1 = ((size_t)(bb * HEADS + h1) * SEQ + nn) * HD + d1;
                    __nv_bfloat16 h, l;
                    h = __float2bfloat16(v0); l = __float2bfloat16(v0 - __bfloat162float(h));
                    outh[i0] = h; outl[i0] = l;
                    h = __float2bfloat16(v1); l = __float2bfloat16(v1 - __bfloat162float(h));
                    outh[i1] = h; outl[i1] = l;
                } else {
                    float2 w = make_float2(v0, v1);
                    *(float2*)(outf + (size_t)m * EMB + cc) = w;
                }
            }
        }
    }
}

// ===========================================================================
// Flash attention on tensor cores (bf16 split, 3-product).
// CTA: 128 q-rows, 8 warps x 16 q-rows, key tiles of 64.
// ===========================================================================
#define APAD 104
#define ATTN_SMEM ((2*128*APAD + 4*64*APAD) * 2)   // 106496 B

__global__ __launch_bounds__(256) void attn_mma()
{
    extern __shared__ __nv_bfloat16 asm_[];
    const uint32_t sQh = smem_u32(asm_);
    const uint32_t sQl = sQh + 128 * APAD * 2;
    const uint32_t sKh = sQl + 128 * APAD * 2;
    const uint32_t sKl = sKh + 64 * APAD * 2;
    const uint32_t sVh = sKl + 64 * APAD * 2;
    const uint32_t sVl = sVh + 64 * APAD * 2;

    const int tid = threadIdx.x;
    const int wid = tid >> 5, lane = tid & 31;
    const int midx = lane >> 3, lrow = lane & 7;
    const int q0 = blockIdx.x * 128;
    const int bh = blockIdx.y;

    const __nv_bfloat16* bQh = g_Qh + (size_t)bh * SEQ * HD;
    const __nv_bfloat16* bQl = g_Ql + (size_t)bh * SEQ * HD;
    const __nv_bfloat16* bKh = g_Kh + (size_t)bh * SEQ * HD;
    const __nv_bfloat16* bKl = g_Kl + (size_t)bh * SEQ * HD;
    const __nv_bfloat16* bVh = g_Vh + (size_t)bh * SEQ * HD;
    const __nv_bfloat16* bVl = g_Vl + (size_t)bh * SEQ * HD;

    // load Q tiles (128 rows x 96 = 12 x 16B segs, x2 arrays)
    for (int i = tid; i < 1536; i += 256) {
        const int r = i / 12, s = i % 12;
        const size_t go = (size_t)(q0 + r) * HD + s * 8;
        const uint32_t so = (r * APAD + s * 8) * 2;
        cpa16(sQh + so, bQh + go);
        cpa16(sQl + so, bQl + go);
    }
    CP_COMMIT();

    float m0v = -INFINITY, m1v = -INFINITY, l0 = 0.f, l1 = 0.f;
    float oacc[12][4];
    #pragma unroll
    for (int d = 0; d < 12; d++)
        #pragma unroll
        for (int c = 0; c < 4; c++) oacc[d][c] = 0.f;

    for (int kt = 0; kt < SEQ / 64; kt++) {
        // load K/V tiles (64 rows x 12 segs x 4 arrays)
        for (int i = tid; i < 768; i += 256) {
            const int r = i / 12, s = i % 12;
            const size_t go = (size_t)(kt * 64 + r) * HD + s * 8;
            const uint32_t so = (r * APAD + s * 8) * 2;
            cpa16(sKh + so, bKh + go);
            cpa16(sKl + so, bKl + go);
            cpa16(sVh + so, bVh + go);
            cpa16(sVl + so, bVl + go);
        }
        CP_COMMIT();
        CP_WAIT0();
        __syncthreads();

        // ---- S = Q K^T (64 kcols, 8 n-tiles) ----
        float sacc[8][4];
        #pragma unroll
        for (int n = 0; n < 8; n++)
            #pragma unroll
            for (int c = 0; c < 4; c++) sacc[n][c] = 0.f;

        #pragma unroll
        for (int kd = 0; kd < HD; kd += 16) {
            uint32_t qh4[4], ql4[4];
            const uint32_t qoff =
                ((wid * 16 + (midx & 1) * 8 + lrow) * APAD + kd + (midx >> 1) * 8) * 2;
            ldm4(qh4, sQh + qoff);
            ldm4(ql4, sQl + qoff);
            #pragma unroll
            for (int np = 0; np < 4; np++) {
                uint32_t kh4[4], kl4[4];
                const uint32_t koff =
                    ((np * 16 + (midx >> 1) * 8 + lrow) * APAD + kd + (midx & 1) * 8) * 2;
                ldm4(kh4, sKh + koff);
                ldm4(kl4, sKl + koff);
                #pragma unroll
                for (int h2 = 0; h2 < 2; h2++) {
                    const int nt = np * 2 + h2;
                    mma_bf16(sacc[nt], qh4, kh4[h2 * 2], kh4[h2 * 2 + 1]);
                    mma_bf16(sacc[nt], ql4, kh4[h2 * 2], kh4[h2 * 2 + 1]);
                    mma_bf16(sacc[nt], qh4, kl4[h2 * 2], kl4[h2 * 2 + 1]);
                }
            }
        }

        // ---- online softmax (row stats over 4-lane groups) ----
        float mx0 = -INFINITY, mx1 = -INFINITY;
        #pragma unroll
        for (int n = 0; n < 8; n++) {
            mx0 = fmaxf(mx0, fmaxf(sacc[n][0], sacc[n][1]));
            mx1 = fmaxf(mx1, fmaxf(sacc[n][2], sacc[n][3]));
        }
        mx0 = fmaxf(mx0, __shfl_xor_sync(0xffffffffu, mx0, 1));
        mx0 = fmaxf(mx0, __shfl_xor_sync(0xffffffffu, mx0, 2));
        mx1 = fmaxf(mx1, __shfl_xor_sync(0xffffffffu, mx1, 1));
        mx1 = fmaxf(mx1, __shfl_xor_sync(0xffffffffu, mx1, 2));

        const float mn0 = fmaxf(m0v, mx0), a0v = __expf(m0v - mn0);
        const float mn1 = fmaxf(m1v, mx1), a1v = __expf(m1v - mn1);
        m0v = mn0; m1v = mn1;

        float rs0 = 0.f, rs1 = 0.f;
        #pragma unroll
        for (int n = 0; n < 8; n++) {
            sacc[n][0] = __expf(sacc[n][0] - mn0); rs0 += sacc[n][0];
            sacc[n][1] = __expf(sacc[n][1] - mn0); rs0 += sacc[n][1];
            sacc[n][2] = __expf(sacc[n][2] - mn1); rs1 += sacc[n][2];
            sacc[n][3] = __expf(sacc[n][3] - mn1); rs1 += sacc[n][3];
        }
        rs0 += __shfl_xor_sync(0xffffffffu, rs0, 1);
        rs0 += __shfl_xor_sync(0xffffffffu, rs0, 2);
        rs1 += __shfl_xor_sync(0xffffffffu, rs1, 1);
        rs1 += __shfl_xor_sync(0xffffffffu, rs1, 2);
        l0 = l0 * a0v + rs0;
        l1 = l1 * a1v + rs1;

        #pragma unroll
        for (int d = 0; d < 12; d++) {
            oacc[d][0] *= a0v; oacc[d][1] *= a0v;
            oacc[d][2] *= a1v; oacc[d][3] *= a1v;
        }

        // ---- O += P V  (P fragments in-register from sacc) ----
        #pragma unroll
        for (int s = 0; s < 4; s++) {
            uint32_t ph[4], pl[4];
            split2(sacc[2*s][0],   sacc[2*s][1],   ph[0], pl[0]);
            split2(sacc[2*s][2],   sacc[2*s][3],   ph[1], pl[1]);
            split2(sacc[2*s+1][0], sacc[2*s+1][1], ph[2], pl[2]);
            split2(sacc[2*s+1][2], sacc[2*s+1][3], ph[3], pl[3]);
            #pragma unroll
            for (int dp = 0; dp < 6; dp++) {
                uint32_t vh4[4], vl4[4];
                const uint32_t voff =
                    ((s * 16 + (midx & 1) * 8 + lrow) * APAD + dp * 16 + (midx >> 1) * 8) * 2;
                ldm4t(vh4, sVh + voff);
                ldm4t(vl4, sVl + voff);
                mma_bf16(oacc[dp*2],   ph, vh4[0], vh4[1]);
                mma_bf16(oacc[dp*2],   pl, vh4[0], vh4[1]);
                mma_bf16(oacc[dp*2],   ph, vl4[0], vl4[1]);
                mma_bf16(oacc[dp*2+1], ph, vh4[2], vh4[3]);
                mma_bf16(oacc[dp*2+1], pl, vh4[2], vh4[3]);
                mma_bf16(oacc[dp*2+1], ph, vl4[2], vl4[3]);
            }
        }
        __syncthreads();
    }

    // epilogue: /(l * sqrt(96)), natural fp32 layout
    const float inv0 = 0.10206207261596577f / l0;
    const float inv1 = 0.10206207261596577f / l1;
    const int bb = bh >> 3, h = bh & 7;
    const int row0 = q0 + wid * 16 + (lane >> 2);
    float* o0 = g_O + ((size_t)bb * SEQ + row0) * EMB + h * HD + (lane & 3) * 2;
    float* o1 = o0 + (size_t)8 * EMB;
    #pragma unroll
    for (int dp = 0; dp < 12; dp++) {
        *(float2*)(o0 + dp * 8) = make_float2(oacc[dp][0] * inv0, oacc[dp][1] * inv0);
        *(float2*)(o1 + dp * 8) = make_float2(oacc[dp][2] * inv1, oacc[dp][3] * inv1);
    }
}

// ---------------------------------------------------------------------------
extern "C" void kernel_launch(void* const* d_in, const int* in_sizes, int n_in,
                              void* d_out, int out_size)
{
    const float* x  = (const float*)d_in[0];
    const float* Wq = (const float*)d_in[1];
    const float* bq = (const float*)d_in[2];
    const float* Wk = (const float*)d_in[3];
    const float* bk = (const float*)d_in[4];
    const float* Wv = (const float*)d_in[5];
    const float* bv = (const float*)d_in[6];
    const float* Wo = (const float*)d_in[7];
    const float* bo = (const float*)d_in[8];
    float* out = (float*)d_out;

    __nv_bfloat16 *xc, *oc, *wc, *qh, *ql, *kh, *kl, *vh, *vl;
    float* ob;
    cudaGetSymbolAddress((void**)&xc, g_Xc);
    cudaGetSymbolAddress((void**)&oc, g_Oc);
    cudaGetSymbolAddress((void**)&wc, g_Wc);
    cudaGetSymbolAddress((void**)&qh, g_Qh);
    cudaGetSymbolAddress((void**)&ql, g_Ql);
    cudaGetSymbolAddress((void**)&kh, g_Kh);
    cudaGetSymbolAddress((void**)&kl, g_Kl);
    cudaGetSymbolAddress((void**)&vh, g_Vh);
    cudaGetSymbolAddress((void**)&vl, g_Vl);
    cudaGetSymbolAddress((void**)&ob, g_O);

    __nv_bfloat16* wcq = wc;
    __nv_bfloat16* wck = wc + (size_t)EMB * KCAT;
    __nv_bfloat16* wcv = wc + (size_t)2 * EMB * KCAT;
    __nv_bfloat16* wco = wc + (size_t)3 * EMB * KCAT;

    convert_cat<<<MTOT * 192 / 256, 256>>>(x, xc);
    const dim3 wg(EMB / 32, EMB / 32);
    wconvert<<<wg, dim3(32, 8)>>>(Wq, wcq);
    wconvert<<<wg, dim3(32, 8)>>>(Wk, wck);
    wconvert<<<wg, dim3(32, 8)>>>(Wv, wcv);
    wconvert<<<wg, dim3(32, 8)>>>(Wo, wco);

    const dim3 gg(EMB / 128, MTOT / 128);   // (6, 64)
    gemm_bf16<<<gg, 256>>>(xc, wcq, bq, nullptr, qh, ql, 0);
    gemm_bf16<<<gg, 256>>>(xc, wck, bk, nullptr, kh, kl, 0);
    gemm_bf16<<<gg, 256>>>(xc, wcv, bv, nullptr, vh, vl, 0);

    cudaFuncSetAttribute(attn_mma, cudaFuncAttributeMaxDynamicSharedMemorySize, ATTN_SMEM);
    attn_mma<<<dim3(SEQ / 128, BHN), 256, ATTN_SMEM>>>();

    convert_cat<<<MTOT * 192 / 256, 256>>>(ob, oc);
    gemm_bf16<<<gg, 256>>>(oc, wco, bo, out, nullptr, nullptr, 2);
}

// round 4
// speedup vs baseline: 3.8946x; 1.4706x over previous
#include <cuda_runtime.h>
#include <cuda_fp16.h>
#include <cstdint>
#include <math.h>

#define EMB   768
#define HEADS 8
#define HD    96
#define BATCH 4
#define SEQ   2048
#define BHN   (BATCH*HEADS)
#define MTOT  (BATCH*SEQ)
#define KC3   (3*EMB)        // 2304 (3-segment operands)
#define KC2   (2*EMB)        // 1536 (2-segment operands)

// ---------------- scratch globals (module-load allocated) -------------------
__device__ __half g_Xc[(size_t)MTOT * KC3];    // x split-concat [ah, al, ah]
__device__ __half g_Oc[(size_t)MTOT * KC2];    // attn-out split [oh, ol]
__device__ __half g_Wc[4][(size_t)EMB * KC3];  // W^T segs: QK=[bh,bh,bl], VO=[bh,bh]
__device__ __half g_Qh[(size_t)BHN * SEQ * HD];
__device__ __half g_Ql[(size_t)BHN * SEQ * HD];
__device__ __half g_Kh[(size_t)BHN * SEQ * HD];
__device__ __half g_Kl[(size_t)BHN * SEQ * HD];
__device__ __half g_Vh[(size_t)BHN * SEQ * HD];

// ---------------- helpers ---------------------------------------------------
__device__ __forceinline__ uint32_t smem_u32(const void* p) {
    uint32_t a;
    asm("{ .reg .u64 t; cvta.to.shared.u64 t, %1; cvt.u32.u64 %0, t; }" : "=r"(a) : "l"(p));
    return a;
}
__device__ __forceinline__ void cpa16(uint32_t d, const void* s) {
    asm volatile("cp.async.cg.shared.global [%0], [%1], 16;" :: "r"(d), "l"(s));
}
#define CP_COMMIT() asm volatile("cp.async.commit_group;")
#define CP_WAIT0()  asm volatile("cp.async.wait_group 0;")
#define CP_WAIT1()  asm volatile("cp.async.wait_group 1;")

__device__ __forceinline__ void ldm4(uint32_t* r, uint32_t addr) {
    asm volatile("ldmatrix.sync.aligned.m8n8.x4.shared.b16 {%0,%1,%2,%3}, [%4];"
        : "=r"(r[0]), "=r"(r[1]), "=r"(r[2]), "=r"(r[3]) : "r"(addr));
}
__device__ __forceinline__ void ldm4t(uint32_t* r, uint32_t addr) {
    asm volatile("ldmatrix.sync.aligned.m8n8.x4.trans.shared.b16 {%0,%1,%2,%3}, [%4];"
        : "=r"(r[0]), "=r"(r[1]), "=r"(r[2]), "=r"(r[3]) : "r"(addr));
}
__device__ __forceinline__ void mma_f16(float* c, const uint32_t* a, uint32_t b0, uint32_t b1) {
    asm volatile("mma.sync.aligned.m16n8k16.row.col.f32.f16.f16.f32 "
        "{%0,%1,%2,%3}, {%4,%5,%6,%7}, {%8,%9}, {%0,%1,%2,%3};"
        : "+f"(c[0]), "+f"(c[1]), "+f"(c[2]), "+f"(c[3])
        : "r"(a[0]), "r"(a[1]), "r"(a[2]), "r"(a[3]), "r"(b0), "r"(b1));
}
__device__ __forceinline__ void split2h(float x, float y, uint32_t& hi, uint32_t& lo) {
    __half2 h, l;
    h.x = __float2half(x);
    h.y = __float2half(y);
    l.x = __float2half(x - __half2float(h.x));
    l.y = __float2half(y - __half2float(h.y));
    hi = *(uint32_t*)&h;
    lo = *(uint32_t*)&l;
}

// ===========================================================================
// convert x: fp32 [M][768] -> fp16 [M][2304] segments (ah, al, ah)
// ===========================================================================
__global__ __launch_bounds__(256) void convert_cat(
    const float* __restrict__ in, __half* __restrict__ out)
{
    const int i = blockIdx.x * 256 + threadIdx.x;   // < MTOT*192
    const int row = i / 192, c = (i % 192) * 4;
    const float4 v = ((const float4*)in)[i];
    __half h[4], l[4];
    const float vv[4] = {v.x, v.y, v.z, v.w};
    #pragma unroll
    for (int j = 0; j < 4; j++) {
        h[j] = __float2half(vv[j]);
        l[j] = __float2half(vv[j] - __half2float(h[j]));
    }
    __half* o = out + (size_t)row * KC3 + c;
    *(uint2*)(o)         = *(uint2*)h;
    *(uint2*)(o + EMB)   = *(uint2*)l;
    *(uint2*)(o + 2*EMB) = *(uint2*)h;
}

// ===========================================================================
// weight transpose + split: W [k][n] fp32 -> Wc [n][stride] fp16
// nseg 3: (bh, bh, bl) stride 2304 ; nseg 2: (bh, bh) stride 1536
// ===========================================================================
__global__ void wconvert(const float* __restrict__ W, __half* __restrict__ out,
                         int nseg, int stride)
{
    __shared__ float t[32][33];
    const int tx = threadIdx.x, ty = threadIdx.y;
    const int x = blockIdx.x * 32 + tx;
    const int y0 = blockIdx.y * 32;
    #pragma unroll
    for (int i = ty; i < 32; i += 8)
        t[i][tx] = W[(size_t)(y0 + i) * EMB + x];
    __syncthreads();
    #pragma unroll
    for (int i = ty; i < 32; i += 8) {
        const int n = blockIdx.x * 32 + i;
        const int k = y0 + tx;
        const float v = t[tx][i];
        const __half h = __float2half(v);
        __half* o = out + (size_t)n * stride + k;
        o[0]   = h;
        o[EMB] = h;
        if (nseg == 3)
            o[2*EMB] = __float2half(v - __half2float(h));
    }
}

// ===========================================================================
// fp16 tensor-core GEMM: C[m][n] = sum_k A[m][k]*B[n][k] + bias[n]
// CTA 128x128, 8 warps (2m x 4n), warp 64x32, k-chunk 32, 3-stage cp.async.
// mode 0: split epilogue -> out0/out1 fp16 [bh][n][96]   (Q, K)
// mode 1: hi-only epilogue -> out0 fp16 [bh][n][96]      (V)
// mode 2: fp32 natural [m][768] -> outf                  (final)
// ===========================================================================
#define GPAD 40
#define GEMM_STAGE (256 * GPAD * 2)           // 20480 B per stage (A+B)
#define GEMM_SMEM  (3 * GEMM_STAGE)           // 61440 B

__global__ __launch_bounds__(256, 2) void gemm_fp16(
    const __half* __restrict__ A, const __half* __restrict__ B,
    const float* __restrict__ bias, float* __restrict__ outf,
    __half* __restrict__ out0, __half* __restrict__ out1,
    int strideA, int strideB, int ktot, int mode)
{
    extern __shared__ __half gsm[];
    const uint32_t sbA = smem_u32(gsm);                 // per stage: A then B
    const uint32_t BOFF = 128 * GPAD * 2;               // 10240

    const int tid = threadIdx.x;
    const int wid = tid >> 5, lane = tid & 31;
    const int midx = lane >> 3, lrow = lane & 7;
    const int m0 = blockIdx.y * 128, n0 = blockIdx.x * 128;
    const int wm = (wid & 1) * 64, wn = (wid >> 1) * 32;

    float acc[4][4][4];
    #pragma unroll
    for (int a = 0; a < 4; a++)
        #pragma unroll
        for (int b = 0; b < 4; b++)
            #pragma unroll
            for (int c = 0; c < 4; c++) acc[a][b][c] = 0.f;

    auto load_chunk = [&](int c, int s) {
        const uint32_t base = sbA + s * GEMM_STAGE;
        const __half* ga = A + (size_t)m0 * strideA + c * 32;
        const __half* gb = B + (size_t)n0 * strideB + c * 32;
        #pragma unroll
        for (int t = 0; t < 2; t++) {
            const int idx = tid + t * 256;          // < 512
            const int row = idx >> 2, seg = idx & 3;
            const uint32_t so = (row * GPAD + seg * 8) * 2;
            cpa16(base + so,        ga + (size_t)row * strideA + seg * 8);
            cpa16(base + BOFF + so, gb + (size_t)row * strideB + seg * 8);
        }
    };

    auto compute = [&](int s) {
        const uint32_t base = sbA + s * GEMM_STAGE;
        #pragma unroll
        for (int kk = 0; kk < 32; kk += 16) {
            uint32_t af[4][4];
            #pragma unroll
            for (int mt = 0; mt < 4; mt++) {
                const uint32_t addr = base +
                    ((wm + mt * 16 + (midx & 1) * 8 + lrow) * GPAD + kk + (midx >> 1) * 8) * 2;
                ldm4(af[mt], addr);
            }
            #pragma unroll
            for (int np = 0; np < 2; np++) {
                uint32_t bf4[4];
                const uint32_t addr = base + BOFF +
                    ((wn + np * 16 + (midx >> 1) * 8 + lrow) * GPAD + kk + (midx & 1) * 8) * 2;
                ldm4(bf4, addr);
                #pragma unroll
                for (int h2 = 0; h2 < 2; h2++) {
                    const int nt = np * 2 + h2;
                    #pragma unroll
                    for (int mt = 0; mt < 4; mt++)
                        mma_f16(acc[mt][nt], af[mt], bf4[h2 * 2], bf4[h2 * 2 + 1]);
                }
            }
        }
    };

    const int nch = ktot / 32;
    load_chunk(0, 0); CP_COMMIT();
    load_chunk(1, 1); CP_COMMIT();
    for (int c = 0; c < nch; c++) {
        CP_WAIT1();
        __syncthreads();
        if (c + 2 < nch) load_chunk(c + 2, (c + 2) % 3);
        CP_COMMIT();
        compute(c % 3);
    }

    // epilogue
    #pragma unroll
    for (int mt = 0; mt < 4; mt++) {
        #pragma unroll
        for (int nt = 0; nt < 4; nt++) {
            const int r  = wm + mt * 16 + (lane >> 2);
            const int cc = n0 + wn + nt * 8 + (lane & 3) * 2;
            #pragma unroll
            for (int half = 0; half < 2; half++) {       // rows r, r+8
                const int m = m0 + r + half * 8;
                const float v0 = acc[mt][nt][half * 2]     + bias[cc];
                const float v1 = acc[mt][nt][half * 2 + 1] + bias[cc + 1];
                if (mode == 2) {
                    *(float2*)(outf + (size_t)m * EMB + cc) = make_float2(v0, v1);
                } else {
                    const int bb = m >> 11, nn = m & (SEQ - 1);
                    const int h = cc / HD, d = cc % HD;   // pair stays in one head
                    const size_t i0 = ((size_t)(bb * HEADS + h) * SEQ + nn) * HD + d;
                    __half2 hh;
                    hh.x = __float2half(v0);
                    hh.y = __float2half(v1);
                    *(__half2*)(out0 + i0) = hh;
                    if (mode == 0) {
                        __half2 ll;
                        ll.x = __float2half(v0 - __half2float(hh.x));
                        ll.y = __float2half(v1 - __half2float(hh.y));
                        *(__half2*)(out1 + i0) = ll;
                    }
                }
            }
        }
    }
}

// ===========================================================================
// Flash attention on tensor cores (fp16 split).
// S = (qh+ql)(kh+kl) via 3 products; PV = (ph+pl)*vh via 2 products.
// CTA: 128 q-rows, 8 warps x 16 q-rows, key tiles of 64, K/V double-buffered.
// ===========================================================================
#define APAD 104
#define KV_STAGE (3 * 64 * APAD * 2)                     // kh,kl,vh: 39936 B
#define ATTN_SMEM (2 * 128 * APAD * 2 + 2 * KV_STAGE)    // 133120 B

__global__ __launch_bounds__(256, 1) void attn_mma()
{
    extern __shared__ __half asmem[];
    const uint32_t sQh = smem_u32(asmem);
    const uint32_t sQl = sQh + 128 * APAD * 2;
    const uint32_t sKV = sQl + 128 * APAD * 2;           // stage s at sKV + s*KV_STAGE

    const int tid = threadIdx.x;
    const int wid = tid >> 5, lane = tid & 31;
    const int midx = lane >> 3, lrow = lane & 7;
    const int q0 = blockIdx.x * 128;
    const int bh = blockIdx.y;

    const __half* bQh = g_Qh + (size_t)bh * SEQ * HD;
    const __half* bQl = g_Ql + (size_t)bh * SEQ * HD;
    const __half* bKh = g_Kh + (size_t)bh * SEQ * HD;
    const __half* bKl = g_Kl + (size_t)bh * SEQ * HD;
    const __half* bVh = g_Vh + (size_t)bh * SEQ * HD;

    auto loadKV = [&](int kt, int s) {
        const uint32_t base = sKV + s * KV_STAGE;
        #pragma unroll
        for (int t = 0; t < 9; t++) {
            const int i = tid + t * 256;                 // < 2304
            const int arr = i / 768, rem = i % 768;
            const int r = rem / 12, seg = rem % 12;
            const __half* src = (arr == 0 ? bKh : arr == 1 ? bKl : bVh)
                                + (size_t)(kt * 64 + r) * HD + seg * 8;
            cpa16(base + arr * (64 * APAD * 2) + (r * APAD + seg * 8) * 2, src);
        }
    };

    // Q tiles (128 rows x 12 segs x 2 arrays)
    #pragma unroll
    for (int t = 0; t < 12; t++) {
        const int i = tid + t * 256;                     // < 3072
        const int arr = i / 1536, rem = i % 1536;
        const int r = rem / 12, seg = rem % 12;
        const __half* src = (arr == 0 ? bQh : bQl) + (size_t)(q0 + r) * HD + seg * 8;
        cpa16((arr == 0 ? sQh : sQl) + (r * APAD + seg * 8) * 2, src);
    }
    loadKV(0, 0);
    CP_COMMIT();

    float m0v = -INFINITY, m1v = -INFINITY, l0 = 0.f, l1 = 0.f;
    float oacc[12][4];
    #pragma unroll
    for (int d = 0; d < 12; d++)
        #pragma unroll
        for (int c = 0; c < 4; c++) oacc[d][c] = 0.f;

    for (int kt = 0; kt < SEQ / 64; kt++) {
        const int s = kt & 1;
        CP_WAIT0();
        __syncthreads();
        if (kt + 1 < SEQ / 64) loadKV(kt + 1, s ^ 1);
        CP_COMMIT();

        const uint32_t sKh = sKV + s * KV_STAGE;
        const uint32_t sKl = sKh + 64 * APAD * 2;
        const uint32_t sVh = sKl + 64 * APAD * 2;

        // ---- S = Q K^T (3 products) ----
        float sacc[8][4];
        #pragma unroll
        for (int n = 0; n < 8; n++)
            #pragma unroll
            for (int c = 0; c < 4; c++) sacc[n][c] = 0.f;

        #pragma unroll
        for (int kd = 0; kd < HD; kd += 16) {
            uint32_t qh4[4], ql4[4];
            const uint32_t qoff =
                ((wid * 16 + (midx & 1) * 8 + lrow) * APAD + kd + (midx >> 1) * 8) * 2;
            ldm4(qh4, sQh + qoff);
            ldm4(ql4, sQl + qoff);
            #pragma unroll
            for (int np = 0; np < 4; np++) {
                uint32_t kh4[4], kl4[4];
                const uint32_t koff =
                    ((np * 16 + (midx >> 1) * 8 + lrow) * APAD + kd + (midx & 1) * 8) * 2;
                ldm4(kh4, sKh + koff);
                ldm4(kl4, sKl + koff);
                #pragma unroll
                for (int h2 = 0; h2 < 2; h2++) {
                    const int nt = np * 2 + h2;
                    mma_f16(sacc[nt], qh4, kh4[h2 * 2], kh4[h2 * 2 + 1]);
                    mma_f16(sacc[nt], ql4, kh4[h2 * 2], kh4[h2 * 2 + 1]);
                    mma_f16(sacc[nt], qh4, kl4[h2 * 2], kl4[h2 * 2 + 1]);
                }
            }
        }

        // ---- online softmax (4-lane row groups) ----
        float mx0 = -INFINITY, mx1 = -INFINITY;
        #pragma unroll
        for (int n = 0; n < 8; n++) {
            mx0 = fmaxf(mx0, fmaxf(sacc[n][0], sacc[n][1]));
            mx1 = fmaxf(mx1, fmaxf(sacc[n][2], sacc[n][3]));
        }
        mx0 = fmaxf(mx0, __shfl_xor_sync(0xffffffffu, mx0, 1));
        mx0 = fmaxf(mx0, __shfl_xor_sync(0xffffffffu, mx0, 2));
        mx1 = fmaxf(mx1, __shfl_xor_sync(0xffffffffu, mx1, 1));
        mx1 = fmaxf(mx1, __shfl_xor_sync(0xffffffffu, mx1, 2));

        const float mn0 = fmaxf(m0v, mx0), a0v = __expf(m0v - mn0);
        const float mn1 = fmaxf(m1v, mx1), a1v = __expf(m1v - mn1);
        m0v = mn0; m1v = mn1;

        float rs0 = 0.f, rs1 = 0.f;
        #pragma unroll
        for (int n = 0; n < 8; n++) {
            sacc[n][0] = __expf(sacc[n][0] - mn0); rs0 += sacc[n][0];
            sacc[n][1] = __expf(sacc[n][1] - mn0); rs0 += sacc[n][1];
            sacc[n][2] = __expf(sacc[n][2] - mn1); rs1 += sacc[n][2];
            sacc[n][3] = __expf(sacc[n][3] - mn1); rs1 += sacc[n][3];
        }
        rs0 += __shfl_xor_sync(0xffffffffu, rs0, 1);
        rs0 += __shfl_xor_sync(0xffffffffu, rs0, 2);
        rs1 += __shfl_xor_sync(0xffffffffu, rs1, 1);
        rs1 += __shfl_xor_sync(0xffffffffu, rs1, 2);
        l0 = l0 * a0v + rs0;
        l1 = l1 * a1v + rs1;

        #pragma unroll
        for (int d = 0; d < 12; d++) {
            oacc[d][0] *= a0v; oacc[d][1] *= a0v;
            oacc[d][2] *= a1v; oacc[d][3] *= a1v;
        }

        // ---- O += P V  (2 products, P split in-register) ----
        #pragma unroll
        for (int st = 0; st < 4; st++) {
            uint32_t ph[4], pl[4];
            split2h(sacc[2*st][0],   sacc[2*st][1],   ph[0], pl[0]);
            split2h(sacc[2*st][2],   sacc[2*st][3],   ph[1], pl[1]);
            split2h(sacc[2*st+1][0], sacc[2*st+1][1], ph[2], pl[2]);
            split2h(sacc[2*st+1][2], sacc[2*st+1][3], ph[3], pl[3]);
            #pragma unroll
            for (int dp = 0; dp < 6; dp++) {
                uint32_t vh4[4];
                const uint32_t voff =
                    ((st * 16 + (midx & 1) * 8 + lrow) * APAD + dp * 16 + (midx >> 1) * 8) * 2;
                ldm4t(vh4, sVh + voff);
                mma_f16(oacc[dp*2],   ph, vh4[0], vh4[1]);
                mma_f16(oacc[dp*2],   pl, vh4[0], vh4[1]);
                mma_f16(oacc[dp*2+1], ph, vh4[2], vh4[3]);
                mma_f16(oacc[dp*2+1], pl, vh4[2], vh4[3]);
            }
        }
    }

    // epilogue: /(l*sqrt(96)), write fp16 split directly into O-proj operand
    const float inv0 = 0.10206207261596577f / l0;
    const float inv1 = 0.10206207261596577f / l1;
    const int bb = bh >> 3, h = bh & 7;
    const int row0 = q0 + wid * 16 + (lane >> 2);
    __half* o0 = g_Oc + (size_t)(bb * SEQ + row0) * KC2 + h * HD + (lane & 3) * 2;
    __half* o1 = o0 + (size_t)8 * KC2;
    #pragma unroll
    for (int dp = 0; dp < 12; dp++) {
        float v0 = oacc[dp][0] * inv0, v1 = oacc[dp][1] * inv0;
        __half2 hh, ll;
        hh.x = __float2half(v0); hh.y = __float2half(v1);
        ll.x = __float2half(v0 - __half2float(hh.x));
        ll.y = __float2half(v1 - __half2float(hh.y));
        *(__half2*)(o0 + dp * 8)       = hh;
        *(__half2*)(o0 + EMB + dp * 8) = ll;
        v0 = oacc[dp][2] * inv1; v1 = oacc[dp][3] * inv1;
        hh.x = __float2half(v0); hh.y = __float2half(v1);
        ll.x = __float2half(v0 - __half2float(hh.x));
        ll.y = __float2half(v1 - __half2float(hh.y));
        *(__half2*)(o1 + dp * 8)       = hh;
        *(__half2*)(o1 + EMB + dp * 8) = ll;
    }
}

// ---------------------------------------------------------------------------
extern "C" void kernel_launch(void* const* d_in, const int* in_sizes, int n_in,
                              void* d_out, int out_size)
{
    const float* x  = (const float*)d_in[0];
    const float* Wq = (const float*)d_in[1];
    const float* bq = (const float*)d_in[2];
    const float* Wk = (const float*)d_in[3];
    const float* bk = (const float*)d_in[4];
    const float* Wv = (const float*)d_in[5];
    const float* bv = (const float*)d_in[6];
    const float* Wo = (const float*)d_in[7];
    const float* bo = (const float*)d_in[8];
    float* out = (float*)d_out;

    __half *xc, *oc, *wc, *qh, *ql, *kh, *kl, *vh;
    cudaGetSymbolAddress((void**)&xc, g_Xc);
    cudaGetSymbolAddress((void**)&oc, g_Oc);
    cudaGetSymbolAddress((void**)&wc, g_Wc);
    cudaGetSymbolAddress((void**)&qh, g_Qh);
    cudaGetSymbolAddress((void**)&ql, g_Ql);
    cudaGetSymbolAddress((void**)&kh, g_Kh);
    cudaGetSymbolAddress((void**)&kl, g_Kl);
    cudaGetSymbolAddress((void**)&vh, g_Vh);

    __half* wcq = wc;
    __half* wck = wc + (size_t)EMB * KC3;
    __half* wcv = wc + (size_t)2 * EMB * KC3;
    __half* wco = wc + (size_t)3 * EMB * KC3;

    convert_cat<<<MTOT * 192 / 256, 256>>>(x, xc);
    const dim3 wg(EMB / 32, EMB / 32);
    wconvert<<<wg, dim3(32, 8)>>>(Wq, wcq, 3, KC3);
    wconvert<<<wg, dim3(32, 8)>>>(Wk, wck, 3, KC3);
    wconvert<<<wg, dim3(32, 8)>>>(Wv, wcv, 2, KC2);
    wconvert<<<wg, dim3(32, 8)>>>(Wo, wco, 2, KC2);

    cudaFuncSetAttribute(gemm_fp16, cudaFuncAttributeMaxDynamicSharedMemorySize, GEMM_SMEM);
    const dim3 gg(EMB / 128, MTOT / 128);   // (6, 64)

    gemm_fp16<<<gg, 256, GEMM_SMEM>>>(xc, wcq, bq, nullptr, qh, ql, KC3, KC3, KC3, 0);
    gemm_fp16<<<gg, 256, GEMM_SMEM>>>(xc, wck, bk, nullptr, kh, kl, KC3, KC3, KC3, 0);
    gemm_fp16<<<gg, 256, GEMM_SMEM>>>(xc, wcv, bv, nullptr, vh, nullptr, KC3, KC2, KC2, 1);

    cudaFuncSetAttribute(attn_mma, cudaFuncAttributeMaxDynamicSharedMemorySize, ATTN_SMEM);
    attn_mma<<<dim3(SEQ / 128, BHN), 256, ATTN_SMEM>>>();

    gemm_fp16<<<gg, 256, GEMM_SMEM>>>(oc, wco, bo, out, nullptr, nullptr, KC2, KC2, KC2, 2);
}

// round 5
// speedup vs baseline: 4.2601x; 1.0938x over previous
#include <cuda_runtime.h>
#include <cuda_fp16.h>
#include <cstdint>
#include <math.h>

#define EMB   768
#define HEADS 8
#define HD    96
#define BATCH 4
#define SEQ   2048
#define BHN   (BATCH*HEADS)
#define MTOT  (BATCH*SEQ)
#define KC3   (3*EMB)        // 2304 (3-segment operands)
#define KC2   (2*EMB)        // 1536 (2-segment operands)
#define LOG2E 1.4426950408889634f

// ---------------- scratch globals (module-load allocated) -------------------
__device__ __half g_Xc[(size_t)MTOT * KC3];    // x split-concat [ah, al, ah]
__device__ __half g_Oc[(size_t)MTOT * KC2];    // attn-out split [oh, ol]
__device__ __half g_Wc[4][(size_t)EMB * KC3];  // W^T segs: QK=[bh,bh,bl], VO=[bh,bh]
__device__ __half g_Qh[(size_t)BHN * SEQ * HD];
__device__ __half g_Ql[(size_t)BHN * SEQ * HD];
__device__ __half g_Kh[(size_t)BHN * SEQ * HD];
__device__ __half g_Kl[(size_t)BHN * SEQ * HD];
__device__ __half g_Vh[(size_t)BHN * SEQ * HD];

// ---------------- helpers ---------------------------------------------------
__device__ __forceinline__ uint32_t smem_u32(const void* p) {
    uint32_t a;
    asm("{ .reg .u64 t; cvta.to.shared.u64 t, %1; cvt.u32.u64 %0, t; }" : "=r"(a) : "l"(p));
    return a;
}
__device__ __forceinline__ void cpa16(uint32_t d, const void* s) {
    asm volatile("cp.async.cg.shared.global [%0], [%1], 16;" :: "r"(d), "l"(s));
}
#define CP_COMMIT() asm volatile("cp.async.commit_group;")
#define CP_WAIT0()  asm volatile("cp.async.wait_group 0;")
#define CP_WAIT1()  asm volatile("cp.async.wait_group 1;")

__device__ __forceinline__ void ldm4(uint32_t* r, uint32_t addr) {
    asm volatile("ldmatrix.sync.aligned.m8n8.x4.shared.b16 {%0,%1,%2,%3}, [%4];"
        : "=r"(r[0]), "=r"(r[1]), "=r"(r[2]), "=r"(r[3]) : "r"(addr));
}
__device__ __forceinline__ void ldm4t(uint32_t* r, uint32_t addr) {
    asm volatile("ldmatrix.sync.aligned.m8n8.x4.trans.shared.b16 {%0,%1,%2,%3}, [%4];"
        : "=r"(r[0]), "=r"(r[1]), "=r"(r[2]), "=r"(r[3]) : "r"(addr));
}
__device__ __forceinline__ void mma_f16(float* c, const uint32_t* a, uint32_t b0, uint32_t b1) {
    asm volatile("mma.sync.aligned.m16n8k16.row.col.f32.f16.f16.f32 "
        "{%0,%1,%2,%3}, {%4,%5,%6,%7}, {%8,%9}, {%0,%1,%2,%3};"
        : "+f"(c[0]), "+f"(c[1]), "+f"(c[2]), "+f"(c[3])
        : "r"(a[0]), "r"(a[1]), "r"(a[2]), "r"(a[3]), "r"(b0), "r"(b1));
}
__device__ __forceinline__ void split2h(float x, float y, uint32_t& hi, uint32_t& lo) {
    __half2 h, l;
    h.x = __float2half(x);
    h.y = __float2half(y);
    l.x = __float2half(x - __half2float(h.x));
    l.y = __float2half(y - __half2float(h.y));
    hi = *(uint32_t*)&h;
    lo = *(uint32_t*)&l;
}

// ===========================================================================
// convert x: fp32 [M][768] -> fp16 [M][2304] segments (ah, al, ah)
// ===========================================================================
__global__ __launch_bounds__(256) void convert_cat(
    const float* __restrict__ in, __half* __restrict__ out)
{
    const int i = blockIdx.x * 256 + threadIdx.x;   // < MTOT*192
    const int row = i / 192, c = (i % 192) * 4;
    const float4 v = ((const float4*)in)[i];
    __half h[4], l[4];
    const float vv[4] = {v.x, v.y, v.z, v.w};
    #pragma unroll
    for (int j = 0; j < 4; j++) {
        h[j] = __float2half(vv[j]);
        l[j] = __float2half(vv[j] - __half2float(h[j]));
    }
    __half* o = out + (size_t)row * KC3 + c;
    *(uint2*)(o)         = *(uint2*)h;
    *(uint2*)(o + EMB)   = *(uint2*)l;
    *(uint2*)(o + 2*EMB) = *(uint2*)h;
}

// ===========================================================================
// all-weight transpose + split (z selects Wq/Wk/Wv/Wo)
// z<2: (bh, bh, bl) stride 2304 ; z>=2: (bh, bh) stride 1536
// ===========================================================================
__global__ void wconvert_all(const float* __restrict__ Wq, const float* __restrict__ Wk,
                             const float* __restrict__ Wv, const float* __restrict__ Wo,
                             __half* __restrict__ wc)
{
    __shared__ float t[32][33];
    const int z = blockIdx.z;
    const float* W = (z == 0) ? Wq : (z == 1) ? Wk : (z == 2) ? Wv : Wo;
    __half* out = wc + (size_t)z * EMB * KC3;
    const int nseg = (z < 2) ? 3 : 2;
    const int stride = (z < 2) ? KC3 : KC2;

    const int tx = threadIdx.x, ty = threadIdx.y;
    const int x = blockIdx.x * 32 + tx;
    const int y0 = blockIdx.y * 32;
    #pragma unroll
    for (int i = ty; i < 32; i += 8)
        t[i][tx] = W[(size_t)(y0 + i) * EMB + x];
    __syncthreads();
    #pragma unroll
    for (int i = ty; i < 32; i += 8) {
        const int n = blockIdx.x * 32 + i;
        const int k = y0 + tx;
        const float v = t[tx][i];
        const __half h = __float2half(v);
        __half* o = out + (size_t)n * stride + k;
        o[0]   = h;
        o[EMB] = h;
        if (nseg == 3)
            o[2*EMB] = __float2half(v - __half2float(h));
    }
}

// ===========================================================================
// shared GEMM core: acc += A[128 rows @ m0] * B[128 rows @ n0]^T over ktot
// 8 warps (2m x 4n), warp 64x32, k-chunk 32, 3-stage cp.async pipeline.
// ===========================================================================
#define GPAD 40
#define GEMM_STAGE (256 * GPAD * 2)           // 20480 B per stage (A+B)
#define GEMM_SMEM  (3 * GEMM_STAGE)           // 61440 B

__device__ __forceinline__ void gemm_core(
    const __half* __restrict__ A, const __half* __restrict__ B,
    int strideA, int strideB, int ktot, uint32_t sbA,
    int tid, int wm, int wn, int midx, int lrow, int m0, int n0,
    float acc[4][4][4])
{
    const uint32_t BOFF = 128 * GPAD * 2;

    auto load_chunk = [&](int c, int s) {
        const uint32_t base = sbA + s * GEMM_STAGE;
        const __half* ga = A + (size_t)m0 * strideA + c * 32;
        const __half* gb = B + (size_t)n0 * strideB + c * 32;
        #pragma unroll
        for (int t = 0; t < 2; t++) {
            const int idx = tid + t * 256;          // < 512
            const int row = idx >> 2, seg = idx & 3;
            const uint32_t so = (row * GPAD + seg * 8) * 2;
            cpa16(base + so,        ga + (size_t)row * strideA + seg * 8);
            cpa16(base + BOFF + so, gb + (size_t)row * strideB + seg * 8);
        }
    };

    auto compute = [&](int s) {
        const uint32_t base = sbA + s * GEMM_STAGE;
        #pragma unroll
        for (int kk = 0; kk < 32; kk += 16) {
            uint32_t af[4][4];
            #pragma unroll
            for (int mt = 0; mt < 4; mt++) {
                const uint32_t addr = base +
                    ((wm + mt * 16 + (midx & 1) * 8 + lrow) * GPAD + kk + (midx >> 1) * 8) * 2;
                ldm4(af[mt], addr);
            }
            #pragma unroll
            for (int np = 0; np < 2; np++) {
                uint32_t bf4[4];
                const uint32_t addr = base + BOFF +
                    ((wn + np * 16 + (midx >> 1) * 8 + lrow) * GPAD + kk + (midx & 1) * 8) * 2;
                ldm4(bf4, addr);
                #pragma unroll
                for (int h2 = 0; h2 < 2; h2++) {
                    const int nt = np * 2 + h2;
                    #pragma unroll
                    for (int mt = 0; mt < 4; mt++)
                        mma_f16(acc[mt][nt], af[mt], bf4[h2 * 2], bf4[h2 * 2 + 1]);
                }
            }
        }
    };

    const int nch = ktot / 32;
    load_chunk(0, 0); CP_COMMIT();
    load_chunk(1, 1); CP_COMMIT();
    for (int c = 0; c < nch; c++) {
        CP_WAIT1();
        __syncthreads();
        if (c + 2 < nch) load_chunk(c + 2, (c + 2) % 3);
        CP_COMMIT();
        compute(c % 3);
    }
}

// ===========================================================================
// fused QKV projection: blockIdx.z = {0:Q, 1:K, 2:V}
// Q epilogue pre-scales by log2(e) (softmax uses exp2); Q/K write hi+lo,
// V writes hi only.
// ===========================================================================
__global__ __launch_bounds__(256, 2) void gemm_qkv(
    const __half* __restrict__ A, const __half* __restrict__ wc,
    const float* __restrict__ bq, const float* __restrict__ bk,
    const float* __restrict__ bv,
    __half* __restrict__ qh, __half* __restrict__ ql,
    __half* __restrict__ kh, __half* __restrict__ kl,
    __half* __restrict__ vh)
{
    extern __shared__ __half gsm[];
    const uint32_t sbA = smem_u32(gsm);
    const int tid = threadIdx.x;
    const int wid = tid >> 5, lane = tid & 31;
    const int midx = lane >> 3, lrow = lane & 7;
    const int m0 = blockIdx.y * 128, n0 = blockIdx.x * 128;
    const int wm = (wid & 1) * 64, wn = (wid >> 1) * 32;
    const int z = blockIdx.z;

    const __half* B = wc + (size_t)z * EMB * KC3;
    const int strideB = (z < 2) ? KC3 : KC2;
    const int ktot    = (z < 2) ? KC3 : KC2;
    const float* bias = (z == 0) ? bq : (z == 1) ? bk : bv;
    __half* out0 = (z == 0) ? qh : (z == 1) ? kh : vh;
    __half* out1 = (z == 0) ? ql : kl;                  // unused for z==2
    const float scale = (z == 0) ? LOG2E : 1.0f;

    float acc[4][4][4];
    #pragma unroll
    for (int a = 0; a < 4; a++)
        #pragma unroll
        for (int b = 0; b < 4; b++)
            #pragma unroll
            for (int c = 0; c < 4; c++) acc[a][b][c] = 0.f;

    gemm_core(A, B, KC3, strideB, ktot, sbA, tid, wm, wn, midx, lrow, m0, n0, acc);

    #pragma unroll
    for (int mt = 0; mt < 4; mt++) {
        #pragma unroll
        for (int nt = 0; nt < 4; nt++) {
            const int r  = wm + mt * 16 + (lane >> 2);
            const int cc = n0 + wn + nt * 8 + (lane & 3) * 2;
            #pragma unroll
            for (int half = 0; half < 2; half++) {       // rows r, r+8
                const int m = m0 + r + half * 8;
                const float v0 = (acc[mt][nt][half * 2]     + bias[cc])     * scale;
                const float v1 = (acc[mt][nt][half * 2 + 1] + bias[cc + 1]) * scale;
                const int bb = m >> 11, nn = m & (SEQ - 1);
                const int h = cc / HD, d = cc % HD;       // pair stays in one head
                const size_t i0 = ((size_t)(bb * HEADS + h) * SEQ + nn) * HD + d;
                __half2 hh;
                hh.x = __float2half(v0);
                hh.y = __float2half(v1);
                *(__half2*)(out0 + i0) = hh;
                if (z < 2) {
                    __half2 ll;
                    ll.x = __float2half(v0 - __half2float(hh.x));
                    ll.y = __float2half(v1 - __half2float(hh.y));
                    *(__half2*)(out1 + i0) = ll;
                }
            }
        }
    }
}

// ===========================================================================
// output projection: fp32 natural [m][768]
// ===========================================================================
__global__ __launch_bounds__(256, 2) void gemm_o(
    const __half* __restrict__ A, const __half* __restrict__ B,
    const float* __restrict__ bias, float* __restrict__ outf)
{
    extern __shared__ __half gsm[];
    const uint32_t sbA = smem_u32(gsm);
    const int tid = threadIdx.x;
    const int wid = tid >> 5, lane = tid & 31;
    const int midx = lane >> 3, lrow = lane & 7;
    const int m0 = blockIdx.y * 128, n0 = blockIdx.x * 128;
    const int wm = (wid & 1) * 64, wn = (wid >> 1) * 32;

    float acc[4][4][4];
    #pragma unroll
    for (int a = 0; a < 4; a++)
        #pragma unroll
        for (int b = 0; b < 4; b++)
            #pragma unroll
            for (int c = 0; c < 4; c++) acc[a][b][c] = 0.f;

    gemm_core(A, B, KC2, KC2, KC2, sbA, tid, wm, wn, midx, lrow, m0, n0, acc);

    #pragma unroll
    for (int mt = 0; mt < 4; mt++) {
        #pragma unroll
        for (int nt = 0; nt < 4; nt++) {
            const int r  = wm + mt * 16 + (lane >> 2);
            const int cc = n0 + wn + nt * 8 + (lane & 3) * 2;
            #pragma unroll
            for (int half = 0; half < 2; half++) {
                const int m = m0 + r + half * 8;
                *(float2*)(outf + (size_t)m * EMB + cc) = make_float2(
                    acc[mt][nt][half * 2] + bias[cc],
                    acc[mt][nt][half * 2 + 1] + bias[cc + 1]);
            }
        }
    }
}

// ===========================================================================
// Flash attention on tensor cores (fp16 split, exp2 softmax).
// CTA: 128 q-rows, 8 warps x 16 q-rows, key tiles of 64.
// Single-stage KV buffer; latency hidden by occupancy 2 (cross-CTA overlap).
// ===========================================================================
#define APAD 104
#define KV_BYTES (3 * 64 * APAD * 2)                     // kh,kl,vh: 39936 B
#define ATTN_SMEM (2 * 128 * APAD * 2 + KV_BYTES)        // 93184 B

__global__ __launch_bounds__(256, 2) void attn_mma()
{
    extern __shared__ __half asmem[];
    const uint32_t sQh = smem_u32(asmem);
    const uint32_t sQl = sQh + 128 * APAD * 2;
    const uint32_t sKh = sQl + 128 * APAD * 2;
    const uint32_t sKl = sKh + 64 * APAD * 2;
    const uint32_t sVh = sKl + 64 * APAD * 2;

    const int tid = threadIdx.x;
    const int wid = tid >> 5, lane = tid & 31;
    const int midx = lane >> 3, lrow = lane & 7;
    const int q0 = blockIdx.x * 128;
    const int bh = blockIdx.y;

    const __half* bQh = g_Qh + (size_t)bh * SEQ * HD;
    const __half* bQl = g_Ql + (size_t)bh * SEQ * HD;
    const __half* bKh = g_Kh + (size_t)bh * SEQ * HD;
    const __half* bKl = g_Kl + (size_t)bh * SEQ * HD;
    const __half* bVh = g_Vh + (size_t)bh * SEQ * HD;

    auto loadKV = [&](int kt) {
        #pragma unroll
        for (int t = 0; t < 9; t++) {
            const int i = tid + t * 256;                 // < 2304
            const int arr = i / 768, rem = i % 768;
            const int r = rem / 12, seg = rem % 12;
            const __half* src = (arr == 0 ? bKh : arr == 1 ? bKl : bVh)
                                + (size_t)(kt * 64 + r) * HD + seg * 8;
            cpa16(sKh + arr * (64 * APAD * 2) + (r * APAD + seg * 8) * 2, src);
        }
    };

    // Q tiles (128 rows x 12 segs x 2 arrays)
    #pragma unroll
    for (int t = 0; t < 12; t++) {
        const int i = tid + t * 256;                     // < 3072
        const int arr = i / 1536, rem = i % 1536;
        const int r = rem / 12, seg = rem % 12;
        const __half* src = (arr == 0 ? bQh : bQl) + (size_t)(q0 + r) * HD + seg * 8;
        cpa16((arr == 0 ? sQh : sQl) + (r * APAD + seg * 8) * 2, src);
    }
    loadKV(0);
    CP_COMMIT();

    float m0v = -INFINITY, m1v = -INFINITY, l0 = 0.f, l1 = 0.f;
    float oacc[12][4];
    #pragma unroll
    for (int d = 0; d < 12; d++)
        #pragma unroll
        for (int c = 0; c < 4; c++) oacc[d][c] = 0.f;

    for (int kt = 0; kt < SEQ / 64; kt++) {
        CP_WAIT0();
        __syncthreads();

        // ---- S (log2-space: Q pre-scaled by log2e) = Q K^T, 3 products ----
        float sacc[8][4];
        #pragma unroll
        for (int n = 0; n < 8; n++)
            #pragma unroll
            for (int c = 0; c < 4; c++) sacc[n][c] = 0.f;

        #pragma unroll
        for (int kd = 0; kd < HD; kd += 16) {
            uint32_t qh4[4], ql4[4];
            const uint32_t qoff =
                ((wid * 16 + (midx & 1) * 8 + lrow) * APAD + kd + (midx >> 1) * 8) * 2;
            ldm4(qh4, sQh + qoff);
            ldm4(ql4, sQl + qoff);
            #pragma unroll
            for (int np = 0; np < 4; np++) {
                uint32_t kh4[4], kl4[4];
                const uint32_t koff =
                    ((np * 16 + (midx >> 1) * 8 + lrow) * APAD + kd + (midx & 1) * 8) * 2;
                ldm4(kh4, sKh + koff);
                ldm4(kl4, sKl + koff);
                #pragma unroll
                for (int h2 = 0; h2 < 2; h2++) {
                    const int nt = np * 2 + h2;
                    mma_f16(sacc[nt], qh4, kh4[h2 * 2], kh4[h2 * 2 + 1]);
                    mma_f16(sacc[nt], ql4, kh4[h2 * 2], kh4[h2 * 2 + 1]);
                    mma_f16(sacc[nt], qh4, kl4[h2 * 2], kl4[h2 * 2 + 1]);
                }
            }
        }

        // ---- online softmax in log2 space (4-lane row groups) ----
        float mx0 = -INFINITY, mx1 = -INFINITY;
        #pragma unroll
        for (int n = 0; n < 8; n++) {
            mx0 = fmaxf(mx0, fmaxf(sacc[n][0], sacc[n][1]));
            mx1 = fmaxf(mx1, fmaxf(sacc[n][2], sacc[n][3]));
        }
        mx0 = fmaxf(mx0, __shfl_xor_sync(0xffffffffu, mx0, 1));
        mx0 = fmaxf(mx0, __shfl_xor_sync(0xffffffffu, mx0, 2));
        mx1 = fmaxf(mx1, __shfl_xor_sync(0xffffffffu, mx1, 1));
        mx1 = fmaxf(mx1, __shfl_xor_sync(0xffffffffu, mx1, 2));

        const float mn0 = fmaxf(m0v, mx0), a0v = exp2f(m0v - mn0);
        const float mn1 = fmaxf(m1v, mx1), a1v = exp2f(m1v - mn1);
        m0v = mn0; m1v = mn1;

        float rs0 = 0.f, rs1 = 0.f;
        #pragma unroll
        for (int n = 0; n < 8; n++) {
            sacc[n][0] = exp2f(sacc[n][0] - mn0); rs0 += sacc[n][0];
            sacc[n][1] = exp2f(sacc[n][1] - mn0); rs0 += sacc[n][1];
            sacc[n][2] = exp2f(sacc[n][2] - mn1); rs1 += sacc[n][2];
            sacc[n][3] = exp2f(sacc[n][3] - mn1); rs1 += sacc[n][3];
        }
        rs0 += __shfl_xor_sync(0xffffffffu, rs0, 1);
        rs0 += __shfl_xor_sync(0xffffffffu, rs0, 2);
        rs1 += __shfl_xor_sync(0xffffffffu, rs1, 1);
        rs1 += __shfl_xor_sync(0xffffffffu, rs1, 2);
        l0 = l0 * a0v + rs0;
        l1 = l1 * a1v + rs1;

        #pragma unroll
        for (int d = 0; d < 12; d++) {
            oacc[d][0] *= a0v; oacc[d][1] *= a0v;
            oacc[d][2] *= a1v; oacc[d][3] *= a1v;
        }

        // ---- O += P V  (2 products, P split in-register) ----
        #pragma unroll
        for (int st = 0; st < 4; st++) {
            uint32_t ph[4], pl[4];
            split2h(sacc[2*st][0],   sacc[2*st][1],   ph[0], pl[0]);
            split2h(sacc[2*st][2],   sacc[2*st][3],   ph[1], pl[1]);
            split2h(sacc[2*st+1][0], sacc[2*st+1][1], ph[2], pl[2]);
            split2h(sacc[2*st+1][2], sacc[2*st+1][3], ph[3], pl[3]);
            #pragma unroll
            for (int dp = 0; dp < 6; dp++) {
                uint32_t vh4[4];
                const uint32_t voff =
                    ((st * 16 + (midx & 1) * 8 + lrow) * APAD + dp * 16 + (midx >> 1) * 8) * 2;
                ldm4t(vh4, sVh + voff);
                mma_f16(oacc[dp*2],   ph, vh4[0], vh4[1]);
                mma_f16(oacc[dp*2],   pl, vh4[0], vh4[1]);
                mma_f16(oacc[dp*2+1], ph, vh4[2], vh4[3]);
                mma_f16(oacc[dp*2+1], pl, vh4[2], vh4[3]);
            }
        }

        // single KV buffer: everyone done reading before refilling
        __syncthreads();
        if (kt + 1 < SEQ / 64) loadKV(kt + 1);
        CP_COMMIT();
    }

    // epilogue: /(l*sqrt(96)), write fp16 split directly into O-proj operand
    const float inv0 = 0.10206207261596577f / l0;
    const float inv1 = 0.10206207261596577f / l1;
    const int bb = bh >> 3, h = bh & 7;
    const int row0 = q0 + wid * 16 + (lane >> 2);
    __half* o0 = g_Oc + (size_t)(bb * SEQ + row0) * KC2 + h * HD + (lane & 3) * 2;
    __half* o1 = o0 + (size_t)8 * KC2;
    #pragma unroll
    for (int dp = 0; dp < 12; dp++) {
        float v0 = oacc[dp][0] * inv0, v1 = oacc[dp][1] * inv0;
        __half2 hh, ll;
        hh.x = __float2half(v0); hh.y = __float2half(v1);
        ll.x = __float2half(v0 - __half2float(hh.x));
        ll.y = __float2half(v1 - __half2float(hh.y));
        *(__half2*)(o0 + dp * 8)       = hh;
        *(__half2*)(o0 + EMB + dp * 8) = ll;
        v0 = oacc[dp][2] * inv1; v1 = oacc[dp][3] * inv1;
        hh.x = __float2half(v0); hh.y = __float2half(v1);
        ll.x = __float2half(v0 - __half2float(hh.x));
        ll.y = __float2half(v1 - __half2float(hh.y));
        *(__half2*)(o1 + dp * 8)       = hh;
        *(__half2*)(o1 + EMB + dp * 8) = ll;
    }
}

// ---------------------------------------------------------------------------
extern "C" void kernel_launch(void* const* d_in, const int* in_sizes, int n_in,
                              void* d_out, int out_size)
{
    const float* x  = (const float*)d_in[0];
    const float* Wq = (const float*)d_in[1];
    const float* bq = (const float*)d_in[2];
    const float* Wk = (const float*)d_in[3];
    const float* bk = (const float*)d_in[4];
    const float* Wv = (const float*)d_in[5];
    const float* bv = (const float*)d_in[6];
    const float* Wo = (const float*)d_in[7];
    const float* bo = (const float*)d_in[8];
    float* out = (float*)d_out;

    __half *xc, *oc, *wc, *qh, *ql, *kh, *kl, *vh;
    cudaGetSymbolAddress((void**)&xc, g_Xc);
    cudaGetSymbolAddress((void**)&oc, g_Oc);
    cudaGetSymbolAddress((void**)&wc, g_Wc);
    cudaGetSymbolAddress((void**)&qh, g_Qh);
    cudaGetSymbolAddress((void**)&ql, g_Ql);
    cudaGetSymbolAddress((void**)&kh, g_Kh);
    cudaGetSymbolAddress((void**)&kl, g_Kl);
    cudaGetSymbolAddress((void**)&vh, g_Vh);

    convert_cat<<<MTOT * 192 / 256, 256>>>(x, xc);
    wconvert_all<<<dim3(EMB / 32, EMB / 32, 4), dim3(32, 8)>>>(Wq, Wk, Wv, Wo, wc);

    cudaFuncSetAttribute(gemm_qkv, cudaFuncAttributeMaxDynamicSharedMemorySize, GEMM_SMEM);
    cudaFuncSetAttribute(gemm_o,   cudaFuncAttributeMaxDynamicSharedMemorySize, GEMM_SMEM);

    gemm_qkv<<<dim3(EMB / 128, MTOT / 128, 3), 256, GEMM_SMEM>>>(
        xc, wc, bq, bk, bv, qh, ql, kh, kl, vh);

    cudaFuncSetAttribute(attn_mma, cudaFuncAttributeMaxDynamicSharedMemorySize, ATTN_SMEM);
    attn_mma<<<dim3(SEQ / 128, BHN), 256, ATTN_SMEM>>>();

    __half* wco = wc + (size_t)3 * EMB * KC3;
    gemm_o<<<dim3(EMB / 128, MTOT / 128), 256, GEMM_SMEM>>>(oc, wco, bo, out);
}

// round 6
// speedup vs baseline: 4.7012x; 1.1036x over previous
#include <cuda_runtime.h>
#include <cuda_fp16.h>
#include <cstdint>
#include <math.h>

#define EMB   768
#define HEADS 8
#define HD    96
#define BATCH 4
#define SEQ   2048
#define BHN   (BATCH*HEADS)
#define MTOT  (BATCH*SEQ)
#define KC3   (3*EMB)        // 2304 (3-segment operands)
#define KC2   (2*EMB)        // 1536 (2-segment operands)
#define LOG2E 1.4426950408889634f

// ---------------- scratch globals (module-load allocated) -------------------
__device__ __half g_Xc[(size_t)MTOT * KC3];    // x split-concat [ah, al, ah]
__device__ __half g_Oc[(size_t)MTOT * KC2];    // attn-out split [oh, ol]
__device__ __half g_Wc[4][(size_t)EMB * KC3];  // W^T segs: QK=[bh,bh,bl], VO=[bh,bh]
__device__ __half g_Qh[(size_t)BHN * SEQ * HD];
__device__ __half g_Ql[(size_t)BHN * SEQ * HD];
__device__ __half g_Kh[(size_t)BHN * SEQ * HD];
__device__ __half g_Kl[(size_t)BHN * SEQ * HD];
__device__ __half g_Vh[(size_t)BHN * SEQ * HD];

// ---------------- helpers ---------------------------------------------------
__device__ __forceinline__ uint32_t smem_u32(const void* p) {
    uint32_t a;
    asm("{ .reg .u64 t; cvta.to.shared.u64 t, %1; cvt.u32.u64 %0, t; }" : "=r"(a) : "l"(p));
    return a;
}
__device__ __forceinline__ void cpa16(uint32_t d, const void* s) {
    asm volatile("cp.async.cg.shared.global [%0], [%1], 16;" :: "r"(d), "l"(s));
}
#define CP_COMMIT() asm volatile("cp.async.commit_group;")
#define CP_WAIT0()  asm volatile("cp.async.wait_group 0;")
#define CP_WAIT1()  asm volatile("cp.async.wait_group 1;")

__device__ __forceinline__ void ldm4(uint32_t* r, uint32_t addr) {
    asm volatile("ldmatrix.sync.aligned.m8n8.x4.shared.b16 {%0,%1,%2,%3}, [%4];"
        : "=r"(r[0]), "=r"(r[1]), "=r"(r[2]), "=r"(r[3]) : "r"(addr));
}
__device__ __forceinline__ void ldm4t(uint32_t* r, uint32_t addr) {
    asm volatile("ldmatrix.sync.aligned.m8n8.x4.trans.shared.b16 {%0,%1,%2,%3}, [%4];"
        : "=r"(r[0]), "=r"(r[1]), "=r"(r[2]), "=r"(r[3]) : "r"(addr));
}
__device__ __forceinline__ void mma_f16(float* c, const uint32_t* a, uint32_t b0, uint32_t b1) {
    asm volatile("mma.sync.aligned.m16n8k16.row.col.f32.f16.f16.f32 "
        "{%0,%1,%2,%3}, {%4,%5,%6,%7}, {%8,%9}, {%0,%1,%2,%3};"
        : "+f"(c[0]), "+f"(c[1]), "+f"(c[2]), "+f"(c[3])
        : "r"(a[0]), "r"(a[1]), "r"(a[2]), "r"(a[3]), "r"(b0), "r"(b1));
}
__device__ __forceinline__ void split2h(float x, float y, uint32_t& hi, uint32_t& lo) {
    __half2 h, l;
    h.x = __float2half(x);
    h.y = __float2half(y);
    l.x = __float2half(x - __half2float(h.x));
    l.y = __float2half(y - __half2float(h.y));
    hi = *(uint32_t*)&h;
    lo = *(uint32_t*)&l;
}

// ===========================================================================
// convert x: fp32 [M][768] -> fp16 [M][2304] segments (ah, al, ah)
// ===========================================================================
__global__ __launch_bounds__(256) void convert_cat(
    const float* __restrict__ in, __half* __restrict__ out)
{
    const int i = blockIdx.x * 256 + threadIdx.x;   // < MTOT*192
    const int row = i / 192, c = (i % 192) * 4;
    const float4 v = ((const float4*)in)[i];
    __half h[4], l[4];
    const float vv[4] = {v.x, v.y, v.z, v.w};
    #pragma unroll
    for (int j = 0; j < 4; j++) {
        h[j] = __float2half(vv[j]);
        l[j] = __float2half(vv[j] - __half2float(h[j]));
    }
    __half* o = out + (size_t)row * KC3 + c;
    *(uint2*)(o)         = *(uint2*)h;
    *(uint2*)(o + EMB)   = *(uint2*)l;
    *(uint2*)(o + 2*EMB) = *(uint2*)h;
}

// ===========================================================================
// all-weight transpose + split (z selects Wq/Wk/Wv/Wo)
// ===========================================================================
__global__ void wconvert_all(const float* __restrict__ Wq, const float* __restrict__ Wk,
                             const float* __restrict__ Wv, const float* __restrict__ Wo,
                             __half* __restrict__ wc)
{
    __shared__ float t[32][33];
    const int z = blockIdx.z;
    const float* W = (z == 0) ? Wq : (z == 1) ? Wk : (z == 2) ? Wv : Wo;
    __half* out = wc + (size_t)z * EMB * KC3;
    const int nseg = (z < 2) ? 3 : 2;
    const int stride = (z < 2) ? KC3 : KC2;

    const int tx = threadIdx.x, ty = threadIdx.y;
    const int x = blockIdx.x * 32 + tx;
    const int y0 = blockIdx.y * 32;
    #pragma unroll
    for (int i = ty; i < 32; i += 8)
        t[i][tx] = W[(size_t)(y0 + i) * EMB + x];
    __syncthreads();
    #pragma unroll
    for (int i = ty; i < 32; i += 8) {
        const int n = blockIdx.x * 32 + i;
        const int k = y0 + tx;
        const float v = t[tx][i];
        const __half h = __float2half(v);
        __half* o = out + (size_t)n * stride + k;
        o[0]   = h;
        o[EMB] = h;
        if (nseg == 3)
            o[2*EMB] = __float2half(v - __half2float(h));
    }
}

// ===========================================================================
// shared GEMM core: k-chunk 64, SW128-xor swizzle (no padding), 3-stage.
// Stage layout: rows 0-127 = A tile, rows 128-255 = B tile; 128B per row,
// 16B granule g at row r lives at r*128 + ((g ^ (r&7))*16).
// ===========================================================================
#define GSTAGE (256 * 128)                    // 32768 B per stage
#define GEMM_SMEM (3 * GSTAGE)                // 98304 B

__device__ __forceinline__ void gemm_core(
    const __half* __restrict__ A, const __half* __restrict__ B,
    int strideA, int strideB, int ktot, uint32_t sb,
    int tid, int wm, int wn, int midx, int lrow, int m0, int n0,
    float acc[4][4][4])
{
    auto load_chunk = [&](int c, int s) {
        const uint32_t base = sb + s * GSTAGE;
        #pragma unroll
        for (int t = 0; t < 8; t++) {
            const int idx = tid + t * 256;        // 0..2047
            const int row = idx >> 3, seg = idx & 7;
            const uint32_t dst = base + row * 128 + ((seg ^ (row & 7)) * 16);
            const __half* src = (row < 128)
                ? A + (size_t)(m0 + row) * strideA + c * 64 + seg * 8
                : B + (size_t)(n0 + row - 128) * strideB + c * 64 + seg * 8;
            cpa16(dst, src);
        }
    };

    auto compute = [&](int s) {
        const uint32_t base = sb + s * GSTAGE;
        #pragma unroll
        for (int kk8 = 0; kk8 < 8; kk8 += 2) {    // k in 8-half granules
            uint32_t af[4][4];
            const int sa = kk8 + (midx >> 1);
            #pragma unroll
            for (int mt = 0; mt < 4; mt++) {
                const int r = wm + mt * 16 + (midx & 1) * 8 + lrow;
                ldm4(af[mt], base + r * 128 + ((sa ^ (r & 7)) * 16));
            }
            const int sbg = kk8 + (midx & 1);
            #pragma unroll
            for (int np = 0; np < 2; np++) {
                uint32_t bf4[4];
                const int rb = wn + np * 16 + (midx >> 1) * 8 + lrow;
                ldm4(bf4, base + 16384 + rb * 128 + ((sbg ^ (rb & 7)) * 16));
                #pragma unroll
                for (int h2 = 0; h2 < 2; h2++) {
                    const int nt = np * 2 + h2;
                    #pragma unroll
                    for (int mt = 0; mt < 4; mt++)
                        mma_f16(acc[mt][nt], af[mt], bf4[h2 * 2], bf4[h2 * 2 + 1]);
                }
            }
        }
    };

    const int nch = ktot / 64;
    load_chunk(0, 0); CP_COMMIT();
    load_chunk(1, 1); CP_COMMIT();
    for (int c = 0; c < nch; c++) {
        CP_WAIT1();
        __syncthreads();
        if (c + 2 < nch) load_chunk(c + 2, (c + 2) % 3);
        CP_COMMIT();
        compute(c % 3);
    }
}

// ===========================================================================
// fused QKV projection: blockIdx.z = {0:Q, 1:K, 2:V}
// ===========================================================================
__global__ __launch_bounds__(256, 2) void gemm_qkv(
    const __half* __restrict__ A, const __half* __restrict__ wc,
    const float* __restrict__ bq, const float* __restrict__ bk,
    const float* __restrict__ bv,
    __half* __restrict__ qh, __half* __restrict__ ql,
    __half* __restrict__ kh, __half* __restrict__ kl,
    __half* __restrict__ vh)
{
    extern __shared__ __half gsm[];
    const uint32_t sbA = smem_u32(gsm);
    const int tid = threadIdx.x;
    const int wid = tid >> 5, lane = tid & 31;
    const int midx = lane >> 3, lrow = lane & 7;
    const int m0 = blockIdx.y * 128, n0 = blockIdx.x * 128;
    const int wm = (wid & 1) * 64, wn = (wid >> 1) * 32;
    const int z = blockIdx.z;

    const __half* B = wc + (size_t)z * EMB * KC3;
    const int strideB = (z < 2) ? KC3 : KC2;
    const int ktot    = (z < 2) ? KC3 : KC2;
    const float* bias = (z == 0) ? bq : (z == 1) ? bk : bv;
    __half* out0 = (z == 0) ? qh : (z == 1) ? kh : vh;
    __half* out1 = (z == 0) ? ql : kl;                  // unused for z==2
    const float scale = (z == 0) ? LOG2E : 1.0f;

    float acc[4][4][4];
    #pragma unroll
    for (int a = 0; a < 4; a++)
        #pragma unroll
        for (int b = 0; b < 4; b++)
            #pragma unroll
            for (int c = 0; c < 4; c++) acc[a][b][c] = 0.f;

    gemm_core(A, B, KC3, strideB, ktot, sbA, tid, wm, wn, midx, lrow, m0, n0, acc);

    #pragma unroll
    for (int mt = 0; mt < 4; mt++) {
        #pragma unroll
        for (int nt = 0; nt < 4; nt++) {
            const int r  = wm + mt * 16 + (lane >> 2);
            const int cc = n0 + wn + nt * 8 + (lane & 3) * 2;
            #pragma unroll
            for (int half = 0; half < 2; half++) {       // rows r, r+8
                const int m = m0 + r + half * 8;
                const float v0 = (acc[mt][nt][half * 2]     + bias[cc])     * scale;
                const float v1 = (acc[mt][nt][half * 2 + 1] + bias[cc + 1]) * scale;
                const int bb = m >> 11, nn = m & (SEQ - 1);
                const int h = cc / HD, d = cc % HD;       // pair stays in one head
                const size_t i0 = ((size_t)(bb * HEADS + h) * SEQ + nn) * HD + d;
                __half2 hh;
                hh.x = __float2half(v0);
                hh.y = __float2half(v1);
                *(__half2*)(out0 + i0) = hh;
                if (z < 2) {
                    __half2 ll;
                    ll.x = __float2half(v0 - __half2float(hh.x));
                    ll.y = __float2half(v1 - __half2float(hh.y));
                    *(__half2*)(out1 + i0) = ll;
                }
            }
        }
    }
}

// ===========================================================================
// output projection: fp32 natural [m][768]
// ===========================================================================
__global__ __launch_bounds__(256, 2) void gemm_o(
    const __half* __restrict__ A, const __half* __restrict__ B,
    const float* __restrict__ bias, float* __restrict__ outf)
{
    extern __shared__ __half gsm[];
    const uint32_t sbA = smem_u32(gsm);
    const int tid = threadIdx.x;
    const int wid = tid >> 5, lane = tid & 31;
    const int midx = lane >> 3, lrow = lane & 7;
    const int m0 = blockIdx.y * 128, n0 = blockIdx.x * 128;
    const int wm = (wid & 1) * 64, wn = (wid >> 1) * 32;

    float acc[4][4][4];
    #pragma unroll
    for (int a = 0; a < 4; a++)
        #pragma unroll
        for (int b = 0; b < 4; b++)
            #pragma unroll
            for (int c = 0; c < 4; c++) acc[a][b][c] = 0.f;

    gemm_core(A, B, KC2, KC2, KC2, sbA, tid, wm, wn, midx, lrow, m0, n0, acc);

    #pragma unroll
    for (int mt = 0; mt < 4; mt++) {
        #pragma unroll
        for (int nt = 0; nt < 4; nt++) {
            const int r  = wm + mt * 16 + (lane >> 2);
            const int cc = n0 + wn + nt * 8 + (lane & 3) * 2;
            #pragma unroll
            for (int half = 0; half < 2; half++) {
                const int m = m0 + r + half * 8;
                *(float2*)(outf + (size_t)m * EMB + cc) = make_float2(
                    acc[mt][nt][half * 2] + bias[cc],
                    acc[mt][nt][half * 2 + 1] + bias[cc + 1]);
            }
        }
    }
}

// ===========================================================================
// Flash attention (fp16 split, exp2 softmax), split-phase KV prefetch:
// K(kt+1) loads during softmax+PV; V(kt+1) loads during next S-phase.
// ===========================================================================
#define APAD 104
#define ATTN_SMEM (2 * 128 * APAD * 2 + 3 * 64 * APAD * 2)   // 93184 B

__global__ __launch_bounds__(256, 2) void attn_mma()
{
    extern __shared__ __half asmem[];
    const uint32_t sQh = smem_u32(asmem);
    const uint32_t sQl = sQh + 128 * APAD * 2;
    const uint32_t sKh = sQl + 128 * APAD * 2;
    const uint32_t sKl = sKh + 64 * APAD * 2;
    const uint32_t sVh = sKl + 64 * APAD * 2;

    const int tid = threadIdx.x;
    const int wid = tid >> 5, lane = tid & 31;
    const int midx = lane >> 3, lrow = lane & 7;
    const int q0 = blockIdx.x * 128;
    const int bh = blockIdx.y;

    const __half* bQh = g_Qh + (size_t)bh * SEQ * HD;
    const __half* bQl = g_Ql + (size_t)bh * SEQ * HD;
    const __half* bKh = g_Kh + (size_t)bh * SEQ * HD;
    const __half* bKl = g_Kl + (size_t)bh * SEQ * HD;
    const __half* bVh = g_Vh + (size_t)bh * SEQ * HD;

    auto loadK = [&](int kt) {                           // kh + kl
        #pragma unroll
        for (int t = 0; t < 6; t++) {
            const int i = tid + t * 256;                 // < 1536
            const int arr = i / 768, rem = i % 768;
            const int r = rem / 12, seg = rem % 12;
            const __half* src = (arr == 0 ? bKh : bKl) + (size_t)(kt * 64 + r) * HD + seg * 8;
            cpa16(sKh + arr * (64 * APAD * 2) + (r * APAD + seg * 8) * 2, src);
        }
    };
    auto loadV = [&](int kt) {                           // vh only
        #pragma unroll
        for (int t = 0; t < 3; t++) {
            const int i = tid + t * 256;                 // < 768
            const int r = i / 12, seg = i % 12;
            cpa16(sVh + (r * APAD + seg * 8) * 2, bVh + (size_t)(kt * 64 + r) * HD + seg * 8);
        }
    };

    // prologue: Q + K0 in group 0, V0 in group 1
    #pragma unroll
    for (int t = 0; t < 12; t++) {
        const int i = tid + t * 256;                     // < 3072
        const int arr = i / 1536, rem = i % 1536;
        const int r = rem / 12, seg = rem % 12;
        const __half* src = (arr == 0 ? bQh : bQl) + (size_t)(q0 + r) * HD + seg * 8;
        cpa16((arr == 0 ? sQh : sQl) + (r * APAD + seg * 8) * 2, src);
    }
    loadK(0);
    CP_COMMIT();
    loadV(0);
    CP_COMMIT();

    float m0v = -INFINITY, m1v = -INFINITY, l0 = 0.f, l1 = 0.f;
    float oacc[12][4];
    #pragma unroll
    for (int d = 0; d < 12; d++)
        #pragma unroll
        for (int c = 0; c < 4; c++) oacc[d][c] = 0.f;

    const int NT = SEQ / 64;
    for (int kt = 0; kt < NT; kt++) {
        CP_WAIT1();                      // K(kt) (+Q on first iter) ready
        __syncthreads();

        // ---- S (log2-space) = Q K^T, 3 products ----
        float sacc[8][4];
        #pragma unroll
        for (int n = 0; n < 8; n++)
            #pragma unroll
            for (int c = 0; c < 4; c++) sacc[n][c] = 0.f;

        #pragma unroll
        for (int kd = 0; kd < HD; kd += 16) {
            uint32_t qh4[4], ql4[4];
            const uint32_t qoff =
                ((wid * 16 + (midx & 1) * 8 + lrow) * APAD + kd + (midx >> 1) * 8) * 2;
            ldm4(qh4, sQh + qoff);
            ldm4(ql4, sQl + qoff);
            #pragma unroll
            for (int np = 0; np < 4; np++) {
                uint32_t kh4[4], kl4[4];
                const uint32_t koff =
                    ((np * 16 + (midx >> 1) * 8 + lrow) * APAD + kd + (midx & 1) * 8) * 2;
                ldm4(kh4, sKh + koff);
                ldm4(kl4, sKl + koff);
                #pragma unroll
                for (int h2 = 0; h2 < 2; h2++) {
                    const int nt = np * 2 + h2;
                    mma_f16(sacc[nt], qh4, kh4[h2 * 2], kh4[h2 * 2 + 1]);
                    mma_f16(sacc[nt], ql4, kh4[h2 * 2], kh4[h2 * 2 + 1]);
                    mma_f16(sacc[nt], qh4, kl4[h2 * 2], kl4[h2 * 2 + 1]);
                }
            }
        }

        __syncthreads();                 // all warps done reading K buffer
        if (kt + 1 < NT) loadK(kt + 1);  // overlaps softmax + PV below
        CP_COMMIT();

        // ---- online softmax in log2 space (4-lane row groups) ----
        float mx0 = -INFINITY, mx1 = -INFINITY;
        #pragma unroll
        for (int n = 0; n < 8; n++) {
            mx0 = fmaxf(mx0, fmaxf(sacc[n][0], sacc[n][1]));
            mx1 = fmaxf(mx1, fmaxf(sacc[n][2], sacc[n][3]));
        }
        mx0 = fmaxf(mx0, __shfl_xor_sync(0xffffffffu, mx0, 1));
        mx0 = fmaxf(mx0, __shfl_xor_sync(0xffffffffu, mx0, 2));
        mx1 = fmaxf(mx1, __shfl_xor_sync(0xffffffffu, mx1, 1));
        mx1 = fmaxf(mx1, __shfl_xor_sync(0xffffffffu, mx1, 2));

        const float mn0 = fmaxf(m0v, mx0), a0v = exp2f(m0v - mn0);
        const float mn1 = fmaxf(m1v, mx1), a1v = exp2f(m1v - mn1);
        m0v = mn0; m1v = mn1;

        float rs0 = 0.f, rs1 = 0.f;
        #pragma unroll
        for (int n = 0; n < 8; n++) {
            sacc[n][0] = exp2f(sacc[n][0] - mn0); rs0 += sacc[n][0];
            sacc[n][1] = exp2f(sacc[n][1] - mn0); rs0 += sacc[n][1];
            sacc[n][2] = exp2f(sacc[n][2] - mn1); rs1 += sacc[n][2];
            sacc[n][3] = exp2f(sacc[n][3] - mn1); rs1 += sacc[n][3];
        }
        rs0 += __shfl_xor_sync(0xffffffffu, rs0, 1);
        rs0 += __shfl_xor_sync(0xffffffffu, rs0, 2);
        rs1 += __shfl_xor_sync(0xffffffffu, rs1, 1);
        rs1 += __shfl_xor_sync(0xffffffffu, rs1, 2);
        l0 = l0 * a0v + rs0;
        l1 = l1 * a1v + rs1;

        #pragma unroll
        for (int d = 0; d < 12; d++) {
            oacc[d][0] *= a0v; oacc[d][1] *= a0v;
            oacc[d][2] *= a1v; oacc[d][3] *= a1v;
        }

        CP_WAIT1();                      // V(kt) ready (K(kt+1) still in flight)
        __syncthreads();

        // ---- O += P V  (2 products, P split in-register) ----
        #pragma unroll
        for (int st = 0; st < 4; st++) {
            uint32_t ph[4], pl[4];
            split2h(sacc[2*st][0],   sacc[2*st][1],   ph[0], pl[0]);
            split2h(sacc[2*st][2],   sacc[2*st][3],   ph[1], pl[1]);
            split2h(sacc[2*st+1][0], sacc[2*st+1][1], ph[2], pl[2]);
            split2h(sacc[2*st+1][2], sacc[2*st+1][3], ph[3], pl[3]);
            #pragma unroll
            for (int dp = 0; dp < 6; dp++) {
                uint32_t vh4[4];
                const uint32_t voff =
                    ((st * 16 + (midx & 1) * 8 + lrow) * APAD + dp * 16 + (midx >> 1) * 8) * 2;
                ldm4t(vh4, sVh + voff);
                mma_f16(oacc[dp*2],   ph, vh4[0], vh4[1]);
                mma_f16(oacc[dp*2],   pl, vh4[0], vh4[1]);
                mma_f16(oacc[dp*2+1], ph, vh4[2], vh4[3]);
                mma_f16(oacc[dp*2+1], pl, vh4[2], vh4[3]);
            }
        }

        __syncthreads();                 // all warps done reading V buffer
        if (kt + 1 < NT) loadV(kt + 1);  // overlaps next S-phase
        CP_COMMIT();
    }

    // epilogue: /(l*sqrt(96)), write fp16 split directly into O-proj operand
    const float inv0 = 0.10206207261596577f / l0;
    const float inv1 = 0.10206207261596577f / l1;
    const int bb = bh >> 3, h = bh & 7;
    const int row0 = q0 + wid * 16 + (lane >> 2);
    __half* o0 = g_Oc + (size_t)(bb * SEQ + row0) * KC2 + h * HD + (lane & 3) * 2;
    __half* o1 = o0 + (size_t)8 * KC2;
    #pragma unroll
    for (int dp = 0; dp < 12; dp++) {
        float v0 = oacc[dp][0] * inv0, v1 = oacc[dp][1] * inv0;
        __half2 hh, ll;
        hh.x = __float2half(v0); hh.y = __float2half(v1);
        ll.x = __float2half(v0 - __half2float(hh.x));
        ll.y = __float2half(v1 - __half2float(hh.y));
        *(__half2*)(o0 + dp * 8)       = hh;
        *(__half2*)(o0 + EMB + dp * 8) = ll;
        v0 = oacc[dp][2] * inv1; v1 = oacc[dp][3] * inv1;
        hh.x = __float2half(v0); hh.y = __float2half(v1);
        ll.x = __float2half(v0 - __half2float(hh.x));
        ll.y = __float2half(v1 - __half2float(hh.y));
        *(__half2*)(o1 + dp * 8)       = hh;
        *(__half2*)(o1 + EMB + dp * 8) = ll;
    }
}

// ---------------------------------------------------------------------------
extern "C" void kernel_launch(void* const* d_in, const int* in_sizes, int n_in,
                              void* d_out, int out_size)
{
    const float* x  = (const float*)d_in[0];
    const float* Wq = (const float*)d_in[1];
    const float* bq = (const float*)d_in[2];
    const float* Wk = (const float*)d_in[3];
    const float* bk = (const float*)d_in[4];
    const float* Wv = (const float*)d_in[5];
    const float* bv = (const float*)d_in[6];
    const float* Wo = (const float*)d_in[7];
    const float* bo = (const float*)d_in[8];
    float* out = (float*)d_out;

    __half *xc, *oc, *wc, *qh, *ql, *kh, *kl, *vh;
    cudaGetSymbolAddress((void**)&xc, g_Xc);
    cudaGetSymbolAddress((void**)&oc, g_Oc);
    cudaGetSymbolAddress((void**)&wc, g_Wc);
    cudaGetSymbolAddress((void**)&qh, g_Qh);
    cudaGetSymbolAddress((void**)&ql, g_Ql);
    cudaGetSymbolAddress((void**)&kh, g_Kh);
    cudaGetSymbolAddress((void**)&kl, g_Kl);
    cudaGetSymbolAddress((void**)&vh, g_Vh);

    convert_cat<<<MTOT * 192 / 256, 256>>>(x, xc);
    wconvert_all<<<dim3(EMB / 32, EMB / 32, 4), dim3(32, 8)>>>(Wq, Wk, Wv, Wo, wc);

    cudaFuncSetAttribute(gemm_qkv, cudaFuncAttributeMaxDynamicSharedMemorySize, GEMM_SMEM);
    cudaFuncSetAttribute(gemm_o,   cudaFuncAttributeMaxDynamicSharedMemorySize, GEMM_SMEM);

    gemm_qkv<<<dim3(EMB / 128, MTOT / 128, 3), 256, GEMM_SMEM>>>(
        xc, wc, bq, bk, bv, qh, ql, kh, kl, vh);

    cudaFuncSetAttribute(attn_mma, cudaFuncAttributeMaxDynamicSharedMemorySize, ATTN_SMEM);
    attn_mma<<<dim3(SEQ / 128, BHN), 256, ATTN_SMEM>>>();

    __half* wco = wc + (size_t)3 * EMB * KC3;
    gemm_o<<<dim3(EMB / 128, MTOT / 128), 256, GEMM_SMEM>>>(oc, wco, bo, out);
}

// round 7
// speedup vs baseline: 5.2619x; 1.1193x over previous
#include <cuda_runtime.h>
#include <cuda_fp16.h>
#include <cstdint>
#include <math.h>

#define EMB   768
#define HEADS 8
#define HD    96
#define BATCH 4
#define SEQ   2048
#define BHN   (BATCH*HEADS)
#define MTOT  (BATCH*SEQ)
#define KC3   (3*EMB)        // 2304 (3-segment operands)
#define KC2   (2*EMB)        // 1536 (2-segment operands)
#define LOG2E 1.4426950408889634f

// ---------------- scratch globals (module-load allocated) -------------------
__device__ __half g_Xc[(size_t)MTOT * KC3];    // x split-concat [ah, al, ah]
__device__ __half g_Oc[(size_t)MTOT * KC2];    // attn-out split [oh, ol]
__device__ __half g_Wc[4][(size_t)EMB * KC3];  // W^T segs: QK=[bh,bh,bl], VO=[bh,bh]
__device__ __half g_Qh[(size_t)BHN * SEQ * HD];
__device__ __half g_Ql[(size_t)BHN * SEQ * HD];
__device__ __half g_Kh[(size_t)BHN * SEQ * HD];
__device__ __half g_Kl[(size_t)BHN * SEQ * HD];
__device__ __half g_Vh[(size_t)BHN * SEQ * HD];

// ---------------- helpers ---------------------------------------------------
__device__ __forceinline__ uint32_t smem_u32(const void* p) {
    uint32_t a;
    asm("{ .reg .u64 t; cvta.to.shared.u64 t, %1; cvt.u32.u64 %0, t; }" : "=r"(a) : "l"(p));
    return a;
}
__device__ __forceinline__ void cpa16(uint32_t d, const void* s) {
    asm volatile("cp.async.cg.shared.global [%0], [%1], 16;" :: "r"(d), "l"(s));
}
#define CP_COMMIT() asm volatile("cp.async.commit_group;")
#define CP_WAIT0()  asm volatile("cp.async.wait_group 0;")
#define CP_WAIT1()  asm volatile("cp.async.wait_group 1;")

__device__ __forceinline__ void ldm4(uint32_t* r, uint32_t addr) {
    asm volatile("ldmatrix.sync.aligned.m8n8.x4.shared.b16 {%0,%1,%2,%3}, [%4];"
        : "=r"(r[0]), "=r"(r[1]), "=r"(r[2]), "=r"(r[3]) : "r"(addr));
}
__device__ __forceinline__ void ldm4t(uint32_t* r, uint32_t addr) {
    asm volatile("ldmatrix.sync.aligned.m8n8.x4.trans.shared.b16 {%0,%1,%2,%3}, [%4];"
        : "=r"(r[0]), "=r"(r[1]), "=r"(r[2]), "=r"(r[3]) : "r"(addr));
}
__device__ __forceinline__ void mma_f16(float* c, const uint32_t* a, uint32_t b0, uint32_t b1) {
    asm volatile("mma.sync.aligned.m16n8k16.row.col.f32.f16.f16.f32 "
        "{%0,%1,%2,%3}, {%4,%5,%6,%7}, {%8,%9}, {%0,%1,%2,%3};"
        : "+f"(c[0]), "+f"(c[1]), "+f"(c[2]), "+f"(c[3])
        : "r"(a[0]), "r"(a[1]), "r"(a[2]), "r"(a[3]), "r"(b0), "r"(b1));
}
// guaranteed-MUFU exp2
__device__ __forceinline__ float ex2f(float x) {
    float y;
    asm("ex2.approx.ftz.f32 %0, %1;" : "=f"(y) : "f"(x));
    return y;
}
// pack two fp32 -> fp16x2 {lo=x, hi=y} in one cvt
__device__ __forceinline__ uint32_t packh2(float x, float y) {
    uint32_t r;
    asm("cvt.rn.f16x2.f32 %0, %2, %1;" : "=r"(r) : "f"(x), "f"(y));
    return r;
}
__device__ __forceinline__ void split2h(float x, float y, uint32_t& hi, uint32_t& lo) {
    __half2 h, l;
    h.x = __float2half(x);
    h.y = __float2half(y);
    l.x = __float2half(x - __half2float(h.x));
    l.y = __float2half(y - __half2float(h.y));
    hi = *(uint32_t*)&h;
    lo = *(uint32_t*)&l;
}

// ===========================================================================
// convert x: fp32 [M][768] -> fp16 [M][2304] segments (ah, al, ah)
// ===========================================================================
__global__ __launch_bounds__(256) void convert_cat(
    const float* __restrict__ in, __half* __restrict__ out)
{
    const int i = blockIdx.x * 256 + threadIdx.x;   // < MTOT*192
    const int row = i / 192, c = (i % 192) * 4;
    const float4 v = ((const float4*)in)[i];
    __half h[4], l[4];
    const float vv[4] = {v.x, v.y, v.z, v.w};
    #pragma unroll
    for (int j = 0; j < 4; j++) {
        h[j] = __float2half(vv[j]);
        l[j] = __float2half(vv[j] - __half2float(h[j]));
    }
    __half* o = out + (size_t)row * KC3 + c;
    *(uint2*)(o)         = *(uint2*)h;
    *(uint2*)(o + EMB)   = *(uint2*)l;
    *(uint2*)(o + 2*EMB) = *(uint2*)h;
}

// ===========================================================================
// all-weight transpose + split (z selects Wq/Wk/Wv/Wo)
// ===========================================================================
__global__ void wconvert_all(const float* __restrict__ Wq, const float* __restrict__ Wk,
                             const float* __restrict__ Wv, const float* __restrict__ Wo,
                             __half* __restrict__ wc)
{
    __shared__ float t[32][33];
    const int z = blockIdx.z;
    const float* W = (z == 0) ? Wq : (z == 1) ? Wk : (z == 2) ? Wv : Wo;
    __half* out = wc + (size_t)z * EMB * KC3;
    const int nseg = (z < 2) ? 3 : 2;
    const int stride = (z < 2) ? KC3 : KC2;

    const int tx = threadIdx.x, ty = threadIdx.y;
    const int x = blockIdx.x * 32 + tx;
    const int y0 = blockIdx.y * 32;
    #pragma unroll
    for (int i = ty; i < 32; i += 8)
        t[i][tx] = W[(size_t)(y0 + i) * EMB + x];
    __syncthreads();
    #pragma unroll
    for (int i = ty; i < 32; i += 8) {
        const int n = blockIdx.x * 32 + i;
        const int k = y0 + tx;
        const float v = t[tx][i];
        const __half h = __float2half(v);
        __half* o = out + (size_t)n * stride + k;
        o[0]   = h;
        o[EMB] = h;
        if (nseg == 3)
            o[2*EMB] = __float2half(v - __half2float(h));
    }
}

// ===========================================================================
// shared GEMM core: k-chunk 64, SW128-xor swizzle (no padding), 3-stage.
// ===========================================================================
#define GSTAGE (256 * 128)                    // 32768 B per stage
#define GEMM_SMEM (3 * GSTAGE)                // 98304 B

__device__ __forceinline__ void gemm_core(
    const __half* __restrict__ A, const __half* __restrict__ B,
    int strideA, int strideB, int ktot, uint32_t sb,
    int tid, int wm, int wn, int midx, int lrow, int m0, int n0,
    float acc[4][4][4])
{
    auto load_chunk = [&](int c, int s) {
        const uint32_t base = sb + s * GSTAGE;
        #pragma unroll
        for (int t = 0; t < 8; t++) {
            const int idx = tid + t * 256;        // 0..2047
            const int row = idx >> 3, seg = idx & 7;
            const uint32_t dst = base + row * 128 + ((seg ^ (row & 7)) * 16);
            const __half* src = (row < 128)
                ? A + (size_t)(m0 + row) * strideA + c * 64 + seg * 8
                : B + (size_t)(n0 + row - 128) * strideB + c * 64 + seg * 8;
            cpa16(dst, src);
        }
    };

    auto compute = [&](int s) {
        const uint32_t base = sb + s * GSTAGE;
        #pragma unroll
        for (int kk8 = 0; kk8 < 8; kk8 += 2) {    // k in 8-half granules
            uint32_t af[4][4];
            const int sa = kk8 + (midx >> 1);
            #pragma unroll
            for (int mt = 0; mt < 4; mt++) {
                const int r = wm + mt * 16 + (midx & 1) * 8 + lrow;
                ldm4(af[mt], base + r * 128 + ((sa ^ (r & 7)) * 16));
            }
            const int sbg = kk8 + (midx & 1);
            #pragma unroll
            for (int np = 0; np < 2; np++) {
                uint32_t bf4[4];
                const int rb = wn + np * 16 + (midx >> 1) * 8 + lrow;
                ldm4(bf4, base + 16384 + rb * 128 + ((sbg ^ (rb & 7)) * 16));
                #pragma unroll
                for (int h2 = 0; h2 < 2; h2++) {
                    const int nt = np * 2 + h2;
                    #pragma unroll
                    for (int mt = 0; mt < 4; mt++)
                        mma_f16(acc[mt][nt], af[mt], bf4[h2 * 2], bf4[h2 * 2 + 1]);
                }
            }
        }
    };

    const int nch = ktot / 64;
    load_chunk(0, 0); CP_COMMIT();
    load_chunk(1, 1); CP_COMMIT();
    for (int c = 0; c < nch; c++) {
        CP_WAIT1();
        __syncthreads();
        if (c + 2 < nch) load_chunk(c + 2, (c + 2) % 3);
        CP_COMMIT();
        compute(c % 3);
    }
}

// ===========================================================================
// fused QKV projection: blockIdx.z = {0:Q, 1:K, 2:V}
// ===========================================================================
__global__ __launch_bounds__(256, 2) void gemm_qkv(
    const __half* __restrict__ A, const __half* __restrict__ wc,
    const float* __restrict__ bq, const float* __restrict__ bk,
    const float* __restrict__ bv,
    __half* __restrict__ qh, __half* __restrict__ ql,
    __half* __restrict__ kh, __half* __restrict__ kl,
    __half* __restrict__ vh)
{
    extern __shared__ __half gsm[];
    const uint32_t sbA = smem_u32(gsm);
    const int tid = threadIdx.x;
    const int wid = tid >> 5, lane = tid & 31;
    const int midx = lane >> 3, lrow = lane & 7;
    const int m0 = blockIdx.y * 128, n0 = blockIdx.x * 128;
    const int wm = (wid & 1) * 64, wn = (wid >> 1) * 32;
    const int z = blockIdx.z;

    const __half* B = wc + (size_t)z * EMB * KC3;
    const int strideB = (z < 2) ? KC3 : KC2;
    const int ktot    = (z < 2) ? KC3 : KC2;
    const float* bias = (z == 0) ? bq : (z == 1) ? bk : bv;
    __half* out0 = (z == 0) ? qh : (z == 1) ? kh : vh;
    __half* out1 = (z == 0) ? ql : kl;                  // unused for z==2
    const float scale = (z == 0) ? LOG2E : 1.0f;

    float acc[4][4][4];
    #pragma unroll
    for (int a = 0; a < 4; a++)
        #pragma unroll
        for (int b = 0; b < 4; b++)
            #pragma unroll
            for (int c = 0; c < 4; c++) acc[a][b][c] = 0.f;

    gemm_core(A, B, KC3, strideB, ktot, sbA, tid, wm, wn, midx, lrow, m0, n0, acc);

    #pragma unroll
    for (int mt = 0; mt < 4; mt++) {
        #pragma unroll
        for (int nt = 0; nt < 4; nt++) {
            const int r  = wm + mt * 16 + (lane >> 2);
            const int cc = n0 + wn + nt * 8 + (lane & 3) * 2;
            #pragma unroll
            for (int half = 0; half < 2; half++) {       // rows r, r+8
                const int m = m0 + r + half * 8;
                const float v0 = (acc[mt][nt][half * 2]     + bias[cc])     * scale;
                const float v1 = (acc[mt][nt][half * 2 + 1] + bias[cc + 1]) * scale;
                const int bb = m >> 11, nn = m & (SEQ - 1);
                const int h = cc / HD, d = cc % HD;       // pair stays in one head
                const size_t i0 = ((size_t)(bb * HEADS + h) * SEQ + nn) * HD + d;
                __half2 hh;
                hh.x = __float2half(v0);
                hh.y = __float2half(v1);
                *(__half2*)(out0 + i0) = hh;
                if (z < 2) {
                    __half2 ll;
                    ll.x = __float2half(v0 - __half2float(hh.x));
                    ll.y = __float2half(v1 - __half2float(hh.y));
                    *(__half2*)(out1 + i0) = ll;
                }
            }
        }
    }
}

// ===========================================================================
// output projection: fp32 natural [m][768]
// ===========================================================================
__global__ __launch_bounds__(256, 2) void gemm_o(
    const __half* __restrict__ A, const __half* __restrict__ B,
    const float* __restrict__ bias, float* __restrict__ outf)
{
    extern __shared__ __half gsm[];
    const uint32_t sbA = smem_u32(gsm);
    const int tid = threadIdx.x;
    const int wid = tid >> 5, lane = tid & 31;
    const int midx = lane >> 3, lrow = lane & 7;
    const int m0 = blockIdx.y * 128, n0 = blockIdx.x * 128;
    const int wm = (wid & 1) * 64, wn = (wid >> 1) * 32;

    float acc[4][4][4];
    #pragma unroll
    for (int a = 0; a < 4; a++)
        #pragma unroll
        for (int b = 0; b < 4; b++)
            #pragma unroll
            for (int c = 0; c < 4; c++) acc[a][b][c] = 0.f;

    gemm_core(A, B, KC2, KC2, KC2, sbA, tid, wm, wn, midx, lrow, m0, n0, acc);

    #pragma unroll
    for (int mt = 0; mt < 4; mt++) {
        #pragma unroll
        for (int nt = 0; nt < 4; nt++) {
            const int r  = wm + mt * 16 + (lane >> 2);
            const int cc = n0 + wn + nt * 8 + (lane & 3) * 2;
            #pragma unroll
            for (int half = 0; half < 2; half++) {
                const int m = m0 + r + half * 8;
                *(float2*)(outf + (size_t)m * EMB + cc) = make_float2(
                    acc[mt][nt][half * 2] + bias[cc],
                    acc[mt][nt][half * 2 + 1] + bias[cc + 1]);
            }
        }
    }
}

// ===========================================================================
// Flash attention (fp16 split QK 3-product, fp16 PV single-product,
// MUFU exp2 softmax), split-phase KV prefetch.
// ===========================================================================
#define APAD 104
#define ATTN_SMEM (2 * 128 * APAD * 2 + 3 * 64 * APAD * 2)   // 93184 B

__global__ __launch_bounds__(256, 2) void attn_mma()
{
    extern __shared__ __half asmem[];
    const uint32_t sQh = smem_u32(asmem);
    const uint32_t sQl = sQh + 128 * APAD * 2;
    const uint32_t sKh = sQl + 128 * APAD * 2;
    const uint32_t sKl = sKh + 64 * APAD * 2;
    const uint32_t sVh = sKl + 64 * APAD * 2;

    const int tid = threadIdx.x;
    const int wid = tid >> 5, lane = tid & 31;
    const int midx = lane >> 3, lrow = lane & 7;
    const int q0 = blockIdx.x * 128;
    const int bh = blockIdx.y;

    const __half* bQh = g_Qh + (size_t)bh * SEQ * HD;
    const __half* bQl = g_Ql + (size_t)bh * SEQ * HD;
    const __half* bKh = g_Kh + (size_t)bh * SEQ * HD;
    const __half* bKl = g_Kl + (size_t)bh * SEQ * HD;
    const __half* bVh = g_Vh + (size_t)bh * SEQ * HD;

    auto loadK = [&](int kt) {                           // kh + kl
        #pragma unroll
        for (int t = 0; t < 6; t++) {
            const int i = tid + t * 256;                 // < 1536
            const int arr = i / 768, rem = i % 768;
            const int r = rem / 12, seg = rem % 12;
            const __half* src = (arr == 0 ? bKh : bKl) + (size_t)(kt * 64 + r) * HD + seg * 8;
            cpa16(sKh + arr * (64 * APAD * 2) + (r * APAD + seg * 8) * 2, src);
        }
    };
    auto loadV = [&](int kt) {                           // vh only
        #pragma unroll
        for (int t = 0; t < 3; t++) {
            const int i = tid + t * 256;                 // < 768
            const int r = i / 12, seg = i % 12;
            cpa16(sVh + (r * APAD + seg * 8) * 2, bVh + (size_t)(kt * 64 + r) * HD + seg * 8);
        }
    };

    // prologue: Q + K0 in group 0, V0 in group 1
    #pragma unroll
    for (int t = 0; t < 12; t++) {
        const int i = tid + t * 256;                     // < 3072
        const int arr = i / 1536, rem = i % 1536;
        const int r = rem / 12, seg = rem % 12;
        const __half* src = (arr == 0 ? bQh : bQl) + (size_t)(q0 + r) * HD + seg * 8;
        cpa16((arr == 0 ? sQh : sQl) + (r * APAD + seg * 8) * 2, src);
    }
    loadK(0);
    CP_COMMIT();
    loadV(0);
    CP_COMMIT();

    float m0v = -INFINITY, m1v = -INFINITY, l0 = 0.f, l1 = 0.f;
    float oacc[12][4];
    #pragma unroll
    for (int d = 0; d < 12; d++)
        #pragma unroll
        for (int c = 0; c < 4; c++) oacc[d][c] = 0.f;

    const int NT = SEQ / 64;
    for (int kt = 0; kt < NT; kt++) {
        CP_WAIT1();                      // K(kt) (+Q on first iter) ready
        __syncthreads();

        // ---- S (log2-space) = Q K^T, 3 products ----
        float sacc[8][4];
        #pragma unroll
        for (int n = 0; n < 8; n++)
            #pragma unroll
            for (int c = 0; c < 4; c++) sacc[n][c] = 0.f;

        #pragma unroll
        for (int kd = 0; kd < HD; kd += 16) {
            uint32_t qh4[4], ql4[4];
            const uint32_t qoff =
                ((wid * 16 + (midx & 1) * 8 + lrow) * APAD + kd + (midx >> 1) * 8) * 2;
            ldm4(qh4, sQh + qoff);
            ldm4(ql4, sQl + qoff);
            #pragma unroll
            for (int np = 0; np < 4; np++) {
                uint32_t kh4[4], kl4[4];
                const uint32_t koff =
                    ((np * 16 + (midx >> 1) * 8 + lrow) * APAD + kd + (midx & 1) * 8) * 2;
                ldm4(kh4, sKh + koff);
                ldm4(kl4, sKl + koff);
                #pragma unroll
                for (int h2 = 0; h2 < 2; h2++) {
                    const int nt = np * 2 + h2;
                    mma_f16(sacc[nt], qh4, kh4[h2 * 2], kh4[h2 * 2 + 1]);
                    mma_f16(sacc[nt], ql4, kh4[h2 * 2], kh4[h2 * 2 + 1]);
                    mma_f16(sacc[nt], qh4, kl4[h2 * 2], kl4[h2 * 2 + 1]);
                }
            }
        }

        __syncthreads();                 // all warps done reading K buffer
        if (kt + 1 < NT) loadK(kt + 1);  // overlaps softmax + PV below
        CP_COMMIT();

        // ---- online softmax in log2 space (MUFU ex2; 4-lane row groups) ----
        float mx0 = -INFINITY, mx1 = -INFINITY;
        #pragma unroll
        for (int n = 0; n < 8; n++) {
            mx0 = fmaxf(mx0, fmaxf(sacc[n][0], sacc[n][1]));
            mx1 = fmaxf(mx1, fmaxf(sacc[n][2], sacc[n][3]));
        }
        mx0 = fmaxf(mx0, __shfl_xor_sync(0xffffffffu, mx0, 1));
        mx0 = fmaxf(mx0, __shfl_xor_sync(0xffffffffu, mx0, 2));
        mx1 = fmaxf(mx1, __shfl_xor_sync(0xffffffffu, mx1, 1));
        mx1 = fmaxf(mx1, __shfl_xor_sync(0xffffffffu, mx1, 2));

        const float mn0 = fmaxf(m0v, mx0), a0v = ex2f(m0v - mn0);
        const float mn1 = fmaxf(m1v, mx1), a1v = ex2f(m1v - mn1);
        m0v = mn0; m1v = mn1;

        float rs0 = 0.f, rs1 = 0.f;
        #pragma unroll
        for (int n = 0; n < 8; n++) {
            sacc[n][0] = ex2f(sacc[n][0] - mn0); rs0 += sacc[n][0];
            sacc[n][1] = ex2f(sacc[n][1] - mn0); rs0 += sacc[n][1];
            sacc[n][2] = ex2f(sacc[n][2] - mn1); rs1 += sacc[n][2];
            sacc[n][3] = ex2f(sacc[n][3] - mn1); rs1 += sacc[n][3];
        }
        rs0 += __shfl_xor_sync(0xffffffffu, rs0, 1);
        rs0 += __shfl_xor_sync(0xffffffffu, rs0, 2);
        rs1 += __shfl_xor_sync(0xffffffffu, rs1, 1);
        rs1 += __shfl_xor_sync(0xffffffffu, rs1, 2);
        l0 = l0 * a0v + rs0;
        l1 = l1 * a1v + rs1;

        #pragma unroll
        for (int d = 0; d < 12; d++) {
            oacc[d][0] *= a0v; oacc[d][1] *= a0v;
            oacc[d][2] *= a1v; oacc[d][3] *= a1v;
        }

        CP_WAIT1();                      // V(kt) ready (K(kt+1) still in flight)
        __syncthreads();

        // ---- O += P V  (single fp16 product; P packed via one cvt) ----
        #pragma unroll
        for (int st = 0; st < 4; st++) {
            uint32_t ph[4];
            ph[0] = packh2(sacc[2*st][0],   sacc[2*st][1]);
            ph[1] = packh2(sacc[2*st][2],   sacc[2*st][3]);
            ph[2] = packh2(sacc[2*st+1][0], sacc[2*st+1][1]);
            ph[3] = packh2(sacc[2*st+1][2], sacc[2*st+1][3]);
            #pragma unroll
            for (int dp = 0; dp < 6; dp++) {
                uint32_t vh4[4];
                const uint32_t voff =
                    ((st * 16 + (midx & 1) * 8 + lrow) * APAD + dp * 16 + (midx >> 1) * 8) * 2;
                ldm4t(vh4, sVh + voff);
                mma_f16(oacc[dp*2],   ph, vh4[0], vh4[1]);
                mma_f16(oacc[dp*2+1], ph, vh4[2], vh4[3]);
            }
        }

        __syncthreads();                 // all warps done reading V buffer
        if (kt + 1 < NT) loadV(kt + 1);  // overlaps next S-phase
        CP_COMMIT();
    }

    // epilogue: /(l*sqrt(96)), write fp16 split directly into O-proj operand
    const float inv0 = 0.10206207261596577f / l0;
    const float inv1 = 0.10206207261596577f / l1;
    const int bb = bh >> 3, h = bh & 7;
    const int row0 = q0 + wid * 16 + (lane >> 2);
    __half* o0 = g_Oc + (size_t)(bb * SEQ + row0) * KC2 + h * HD + (lane & 3) * 2;
    __half* o1 = o0 + (size_t)8 * KC2;
    #pragma unroll
    for (int dp = 0; dp < 12; dp++) {
        float v0 = oacc[dp][0] * inv0, v1 = oacc[dp][1] * inv0;
        uint32_t hh, ll;
        split2h(v0, v1, hh, ll);
        *(uint32_t*)(o0 + dp * 8)       = hh;
        *(uint32_t*)(o0 + EMB + dp * 8) = ll;
        v0 = oacc[dp][2] * inv1; v1 = oacc[dp][3] * inv1;
        split2h(v0, v1, hh, ll);
        *(uint32_t*)(o1 + dp * 8)       = hh;
        *(uint32_t*)(o1 + EMB + dp * 8) = ll;
    }
}

// ---------------------------------------------------------------------------
extern "C" void kernel_launch(void* const* d_in, const int* in_sizes, int n_in,
                              void* d_out, int out_size)
{
    const float* x  = (const float*)d_in[0];
    const float* Wq = (const float*)d_in[1];
    const float* bq = (const float*)d_in[2];
    const float* Wk = (const float*)d_in[3];
    const float* bk = (const float*)d_in[4];
    const float* Wv = (const float*)d_in[5];
    const float* bv = (const float*)d_in[6];
    const float* Wo = (const float*)d_in[7];
    const float* bo = (const float*)d_in[8];
    float* out = (float*)d_out;

    __half *xc, *oc, *wc, *qh, *ql, *kh, *kl, *vh;
    cudaGetSymbolAddress((void**)&xc, g_Xc);
    cudaGetSymbolAddress((void**)&oc, g_Oc);
    cudaGetSymbolAddress((void**)&wc, g_Wc);
    cudaGetSymbolAddress((void**)&qh, g_Qh);
    cudaGetSymbolAddress((void**)&ql, g_Ql);
    cudaGetSymbolAddress((void**)&kh, g_Kh);
    cudaGetSymbolAddress((void**)&kl, g_Kl);
    cudaGetSymbolAddress((void**)&vh, g_Vh);

    convert_cat<<<MTOT * 192 / 256, 256>>>(x, xc);
    wconvert_all<<<dim3(EMB / 32, EMB / 32, 4), dim3(32, 8)>>>(Wq, Wk, Wv, Wo, wc);

    cudaFuncSetAttribute(gemm_qkv, cudaFuncAttributeMaxDynamicSharedMemorySize, GEMM_SMEM);
    cudaFuncSetAttribute(gemm_o,   cudaFuncAttributeMaxDynamicSharedMemorySize, GEMM_SMEM);

    gemm_qkv<<<dim3(EMB / 128, MTOT / 128, 3), 256, GEMM_SMEM>>>(
        xc, wc, bq, bk, bv, qh, ql, kh, kl, vh);

    cudaFuncSetAttribute(attn_mma, cudaFuncAttributeMaxDynamicSharedMemorySize, ATTN_SMEM);
    attn_mma<<<dim3(SEQ / 128, BHN), 256, ATTN_SMEM>>>();

    __half* wco = wc + (size_t)3 * EMB * KC3;
    gemm_o<<<dim3(EMB / 128, MTOT / 128), 256, GEMM_SMEM>>>(oc, wco, bo, out);
}

// round 8
// speedup vs baseline: 6.3560x; 1.2079x over previous
#include <cuda_runtime.h>
#include <cuda_fp16.h>
#include <cstdint>
#include <math.h>

#define EMB   768
#define HEADS 8
#define HD    96
#define BATCH 4
#define SEQ   2048
#define BHN   (BATCH*HEADS)
#define MTOT  (BATCH*SEQ)
#define KC3   (3*EMB)        // 2304 (3-segment operands)
#define KC2   (2*EMB)        // 1536 (2-segment operands)
#define LOG2E 1.4426950408889634f

// ---------------- scratch globals (module-load allocated) -------------------
__device__ __half g_Xc[(size_t)MTOT * KC3];    // x split-concat [ah, al, ah]
__device__ __half g_Oc[(size_t)MTOT * KC2];    // attn-out split [oh, ol]
__device__ __half g_Wc[4][(size_t)EMB * KC3];  // W^T segs: Q=[bh,bh,bl], K/V/O=[bh,bh]
__device__ __half g_Qh[(size_t)BHN * SEQ * HD];
__device__ __half g_Ql[(size_t)BHN * SEQ * HD];
__device__ __half g_Kh[(size_t)BHN * SEQ * HD];
__device__ __half g_Vh[(size_t)BHN * SEQ * HD];

// ---------------- helpers ---------------------------------------------------
__device__ __forceinline__ uint32_t smem_u32(const void* p) {
    uint32_t a;
    asm("{ .reg .u64 t; cvta.to.shared.u64 t, %1; cvt.u32.u64 %0, t; }" : "=r"(a) : "l"(p));
    return a;
}
__device__ __forceinline__ void cpa16(uint32_t d, const void* s) {
    asm volatile("cp.async.cg.shared.global [%0], [%1], 16;" :: "r"(d), "l"(s));
}
#define CP_COMMIT() asm volatile("cp.async.commit_group;")
#define CP_WAIT0()  asm volatile("cp.async.wait_group 0;")
#define CP_WAIT1()  asm volatile("cp.async.wait_group 1;")

__device__ __forceinline__ void ldm4(uint32_t* r, uint32_t addr) {
    asm volatile("ldmatrix.sync.aligned.m8n8.x4.shared.b16 {%0,%1,%2,%3}, [%4];"
        : "=r"(r[0]), "=r"(r[1]), "=r"(r[2]), "=r"(r[3]) : "r"(addr));
}
__device__ __forceinline__ void ldm4t(uint32_t* r, uint32_t addr) {
    asm volatile("ldmatrix.sync.aligned.m8n8.x4.trans.shared.b16 {%0,%1,%2,%3}, [%4];"
        : "=r"(r[0]), "=r"(r[1]), "=r"(r[2]), "=r"(r[3]) : "r"(addr));
}
__device__ __forceinline__ void mma_f16(float* c, const uint32_t* a, uint32_t b0, uint32_t b1) {
    asm volatile("mma.sync.aligned.m16n8k16.row.col.f32.f16.f16.f32 "
        "{%0,%1,%2,%3}, {%4,%5,%6,%7}, {%8,%9}, {%0,%1,%2,%3};"
        : "+f"(c[0]), "+f"(c[1]), "+f"(c[2]), "+f"(c[3])
        : "r"(a[0]), "r"(a[1]), "r"(a[2]), "r"(a[3]), "r"(b0), "r"(b1));
}
// guaranteed-MUFU exp2
__device__ __forceinline__ float ex2f(float x) {
    float y;
    asm("ex2.approx.ftz.f32 %0, %1;" : "=f"(y) : "f"(x));
    return y;
}
// pack two fp32 -> fp16x2 {lo=x, hi=y} in one cvt
__device__ __forceinline__ uint32_t packh2(float x, float y) {
    uint32_t r;
    asm("cvt.rn.f16x2.f32 %0, %2, %1;" : "=r"(r) : "f"(x), "f"(y));
    return r;
}
__device__ __forceinline__ void split2h(float x, float y, uint32_t& hi, uint32_t& lo) {
    __half2 h, l;
    h.x = __float2half(x);
    h.y = __float2half(y);
    l.x = __float2half(x - __half2float(h.x));
    l.y = __float2half(y - __half2float(h.y));
    hi = *(uint32_t*)&h;
    lo = *(uint32_t*)&l;
}

// ===========================================================================
// convert x: fp32 [M][768] -> fp16 [M][2304] segments (ah, al, ah)
// ===========================================================================
__global__ __launch_bounds__(256) void convert_cat(
    const float* __restrict__ in, __half* __restrict__ out)
{
    const int i = blockIdx.x * 256 + threadIdx.x;   // < MTOT*192
    const int row = i / 192, c = (i % 192) * 4;
    const float4 v = ((const float4*)in)[i];
    __half h[4], l[4];
    const float vv[4] = {v.x, v.y, v.z, v.w};
    #pragma unroll
    for (int j = 0; j < 4; j++) {
        h[j] = __float2half(vv[j]);
        l[j] = __float2half(vv[j] - __half2float(h[j]));
    }
    __half* o = out + (size_t)row * KC3 + c;
    *(uint2*)(o)         = *(uint2*)h;
    *(uint2*)(o + EMB)   = *(uint2*)l;
    *(uint2*)(o + 2*EMB) = *(uint2*)h;
}

// ===========================================================================
// all-weight transpose + split (z selects Wq/Wk/Wv/Wo)
// z==0 (Q): (bh, bh, bl) stride 2304 ; else: (bh, bh) stride 1536
// ===========================================================================
__global__ void wconvert_all(const float* __restrict__ Wq, const float* __restrict__ Wk,
                             const float* __restrict__ Wv, const float* __restrict__ Wo,
                             __half* __restrict__ wc)
{
    __shared__ float t[32][33];
    const int z = blockIdx.z;
    const float* W = (z == 0) ? Wq : (z == 1) ? Wk : (z == 2) ? Wv : Wo;
    __half* out = wc + (size_t)z * EMB * KC3;
    const int nseg = (z == 0) ? 3 : 2;
    const int stride = (z == 0) ? KC3 : KC2;

    const int tx = threadIdx.x, ty = threadIdx.y;
    const int x = blockIdx.x * 32 + tx;
    const int y0 = blockIdx.y * 32;
    #pragma unroll
    for (int i = ty; i < 32; i += 8)
        t[i][tx] = W[(size_t)(y0 + i) * EMB + x];
    __syncthreads();
    #pragma unroll
    for (int i = ty; i < 32; i += 8) {
        const int n = blockIdx.x * 32 + i;
        const int k = y0 + tx;
        const float v = t[tx][i];
        const __half h = __float2half(v);
        __half* o = out + (size_t)n * stride + k;
        o[0]   = h;
        o[EMB] = h;
        if (nseg == 3)
            o[2*EMB] = __float2half(v - __half2float(h));
    }
}

// ===========================================================================
// shared GEMM core: k-chunk 64, SW128-xor swizzle (no padding), 3-stage.
// ===========================================================================
#define GSTAGE (256 * 128)                    // 32768 B per stage
#define GEMM_SMEM (3 * GSTAGE)                // 98304 B

__device__ __forceinline__ void gemm_core(
    const __half* __restrict__ A, const __half* __restrict__ B,
    int strideA, int strideB, int ktot, uint32_t sb,
    int tid, int wm, int wn, int midx, int lrow, int m0, int n0,
    float acc[4][4][4])
{
    auto load_chunk = [&](int c, int s) {
        const uint32_t base = sb + s * GSTAGE;
        #pragma unroll
        for (int t = 0; t < 8; t++) {
            const int idx = tid + t * 256;        // 0..2047
            const int row = idx >> 3, seg = idx & 7;
            const uint32_t dst = base + row * 128 + ((seg ^ (row & 7)) * 16);
            const __half* src = (row < 128)
                ? A + (size_t)(m0 + row) * strideA + c * 64 + seg * 8
                : B + (size_t)(n0 + row - 128) * strideB + c * 64 + seg * 8;
            cpa16(dst, src);
        }
    };

    auto compute = [&](int s) {
        const uint32_t base = sb + s * GSTAGE;
        #pragma unroll
        for (int kk8 = 0; kk8 < 8; kk8 += 2) {    // k in 8-half granules
            uint32_t af[4][4];
            const int sa = kk8 + (midx >> 1);
            #pragma unroll
            for (int mt = 0; mt < 4; mt++) {
                const int r = wm + mt * 16 + (midx & 1) * 8 + lrow;
                ldm4(af[mt], base + r * 128 + ((sa ^ (r & 7)) * 16));
            }
            const int sbg = kk8 + (midx & 1);
            #pragma unroll
            for (int np = 0; np < 2; np++) {
                uint32_t bf4[4];
                const int rb = wn + np * 16 + (midx >> 1) * 8 + lrow;
                ldm4(bf4, base + 16384 + rb * 128 + ((sbg ^ (rb & 7)) * 16));
                #pragma unroll
                for (int h2 = 0; h2 < 2; h2++) {
                    const int nt = np * 2 + h2;
                    #pragma unroll
                    for (int mt = 0; mt < 4; mt++)
                        mma_f16(acc[mt][nt], af[mt], bf4[h2 * 2], bf4[h2 * 2 + 1]);
                }
            }
        }
    };

    const int nch = ktot / 64;
    load_chunk(0, 0); CP_COMMIT();
    load_chunk(1, 1); CP_COMMIT();
    for (int c = 0; c < nch; c++) {
        CP_WAIT1();
        __syncthreads();
        if (c + 2 < nch) load_chunk(c + 2, (c + 2) % 3);
        CP_COMMIT();
        compute(c % 3);
    }
}

// ===========================================================================
// fused QKV projection: blockIdx.z = {0:Q, 1:K, 2:V}
// Q: 3-segment K-depth, epilogue pre-scaled by log2(e), hi+lo outputs.
// K, V: 2-segment K-depth, hi-only outputs.
// ===========================================================================
__global__ __launch_bounds__(256, 2) void gemm_qkv(
    const __half* __restrict__ A, const __half* __restrict__ wc,
    const float* __restrict__ bq, const float* __restrict__ bk,
    const float* __restrict__ bv,
    __half* __restrict__ qh, __half* __restrict__ ql,
    __half* __restrict__ kh, __half* __restrict__ vh)
{
    extern __shared__ __half gsm[];
    const uint32_t sbA = smem_u32(gsm);
    const int tid = threadIdx.x;
    const int wid = tid >> 5, lane = tid & 31;
    const int midx = lane >> 3, lrow = lane & 7;
    const int m0 = blockIdx.y * 128, n0 = blockIdx.x * 128;
    const int wm = (wid & 1) * 64, wn = (wid >> 1) * 32;
    const int z = blockIdx.z;

    const __half* B = wc + (size_t)z * EMB * KC3;
    const int kdep = (z == 0) ? KC3 : KC2;
    const float* bias = (z == 0) ? bq : (z == 1) ? bk : bv;
    __half* out0 = (z == 0) ? qh : (z == 1) ? kh : vh;
    const float scale = (z == 0) ? LOG2E : 1.0f;

    float acc[4][4][4];
    #pragma unroll
    for (int a = 0; a < 4; a++)
        #pragma unroll
        for (int b = 0; b < 4; b++)
            #pragma unroll
            for (int c = 0; c < 4; c++) acc[a][b][c] = 0.f;

    gemm_core(A, B, KC3, kdep, kdep, sbA, tid, wm, wn, midx, lrow, m0, n0, acc);

    #pragma unroll
    for (int mt = 0; mt < 4; mt++) {
        #pragma unroll
        for (int nt = 0; nt < 4; nt++) {
            const int r  = wm + mt * 16 + (lane >> 2);
            const int cc = n0 + wn + nt * 8 + (lane & 3) * 2;
            #pragma unroll
            for (int half = 0; half < 2; half++) {       // rows r, r+8
                const int m = m0 + r + half * 8;
                const float v0 = (acc[mt][nt][half * 2]     + bias[cc])     * scale;
                const float v1 = (acc[mt][nt][half * 2 + 1] + bias[cc + 1]) * scale;
                const int bb = m >> 11, nn = m & (SEQ - 1);
                const int h = cc / HD, d = cc % HD;       // pair stays in one head
                const size_t i0 = ((size_t)(bb * HEADS + h) * SEQ + nn) * HD + d;
                __half2 hh;
                hh.x = __float2half(v0);
                hh.y = __float2half(v1);
                *(__half2*)(out0 + i0) = hh;
                if (z == 0) {
                    __half2 ll;
                    ll.x = __float2half(v0 - __half2float(hh.x));
                    ll.y = __float2half(v1 - __half2float(hh.y));
                    *(__half2*)(ql + i0) = ll;
                }
            }
        }
    }
}

// ===========================================================================
// output projection: fp32 natural [m][768]
// ===========================================================================
__global__ __launch_bounds__(256, 2) void gemm_o(
    const __half* __restrict__ A, const __half* __restrict__ B,
    const float* __restrict__ bias, float* __restrict__ outf)
{
    extern __shared__ __half gsm[];
    const uint32_t sbA = smem_u32(gsm);
    const int tid = threadIdx.x;
    const int wid = tid >> 5, lane = tid & 31;
    const int midx = lane >> 3, lrow = lane & 7;
    const int m0 = blockIdx.y * 128, n0 = blockIdx.x * 128;
    const int wm = (wid & 1) * 64, wn = (wid >> 1) * 32;

    float acc[4][4][4];
    #pragma unroll
    for (int a = 0; a < 4; a++)
        #pragma unroll
        for (int b = 0; b < 4; b++)
            #pragma unroll
            for (int c = 0; c < 4; c++) acc[a][b][c] = 0.f;

    gemm_core(A, B, KC2, KC2, KC2, sbA, tid, wm, wn, midx, lrow, m0, n0, acc);

    #pragma unroll
    for (int mt = 0; mt < 4; mt++) {
        #pragma unroll
        for (int nt = 0; nt < 4; nt++) {
            const int r  = wm + mt * 16 + (lane >> 2);
            const int cc = n0 + wn + nt * 8 + (lane & 3) * 2;
            #pragma unroll
            for (int half = 0; half < 2; half++) {
                const int m = m0 + r + half * 8;
                *(float2*)(outf + (size_t)m * EMB + cc) = make_float2(
                    acc[mt][nt][half * 2] + bias[cc],
                    acc[mt][nt][half * 2 + 1] + bias[cc + 1]);
            }
        }
    }
}

// ===========================================================================
// Flash attention: S = (qh+ql)·kh (2 products, K single-fp16),
// PV single-product, MUFU exp2, split-phase K/V prefetch.
// ===========================================================================
#define APAD 104
#define ATTN_SMEM ((2 * 128 + 2 * 64) * APAD * 2)        // 79872 B

__global__ __launch_bounds__(256, 2) void attn_mma()
{
    extern __shared__ __half asmem[];
    const uint32_t sQh = smem_u32(asmem);
    const uint32_t sQl = sQh + 128 * APAD * 2;
    const uint32_t sKh = sQl + 128 * APAD * 2;
    const uint32_t sVh = sKh + 64 * APAD * 2;

    const int tid = threadIdx.x;
    const int wid = tid >> 5, lane = tid & 31;
    const int midx = lane >> 3, lrow = lane & 7;
    const int q0 = blockIdx.x * 128;
    const int bh = blockIdx.y;

    const __half* bQh = g_Qh + (size_t)bh * SEQ * HD;
    const __half* bQl = g_Ql + (size_t)bh * SEQ * HD;
    const __half* bKh = g_Kh + (size_t)bh * SEQ * HD;
    const __half* bVh = g_Vh + (size_t)bh * SEQ * HD;

    auto loadK = [&](int kt) {                           // kh only
        #pragma unroll
        for (int t = 0; t < 3; t++) {
            const int i = tid + t * 256;                 // < 768
            const int r = i / 12, seg = i % 12;
            cpa16(sKh + (r * APAD + seg * 8) * 2, bKh + (size_t)(kt * 64 + r) * HD + seg * 8);
        }
    };
    auto loadV = [&](int kt) {                           // vh only
        #pragma unroll
        for (int t = 0; t < 3; t++) {
            const int i = tid + t * 256;                 // < 768
            const int r = i / 12, seg = i % 12;
            cpa16(sVh + (r * APAD + seg * 8) * 2, bVh + (size_t)(kt * 64 + r) * HD + seg * 8);
        }
    };

    // prologue: Q + K0 in group 0, V0 in group 1
    #pragma unroll
    for (int t = 0; t < 12; t++) {
        const int i = tid + t * 256;                     // < 3072
        const int arr = i / 1536, rem = i % 1536;
        const int r = rem / 12, seg = rem % 12;
        const __half* src = (arr == 0 ? bQh : bQl) + (size_t)(q0 + r) * HD + seg * 8;
        cpa16((arr == 0 ? sQh : sQl) + (r * APAD + seg * 8) * 2, src);
    }
    loadK(0);
    CP_COMMIT();
    loadV(0);
    CP_COMMIT();

    float m0v = -INFINITY, m1v = -INFINITY, l0 = 0.f, l1 = 0.f;
    float oacc[12][4];
    #pragma unroll
    for (int d = 0; d < 12; d++)
        #pragma unroll
        for (int c = 0; c < 4; c++) oacc[d][c] = 0.f;

    const int NT = SEQ / 64;
    for (int kt = 0; kt < NT; kt++) {
        CP_WAIT1();                      // K(kt) (+Q on first iter) ready
        __syncthreads();

        // ---- S (log2-space) = (Qh+Ql) Kh^T, 2 products ----
        float sacc[8][4];
        #pragma unroll
        for (int n = 0; n < 8; n++)
            #pragma unroll
            for (int c = 0; c < 4; c++) sacc[n][c] = 0.f;

        #pragma unroll
        for (int kd = 0; kd < HD; kd += 16) {
            uint32_t qh4[4], ql4[4];
            const uint32_t qoff =
                ((wid * 16 + (midx & 1) * 8 + lrow) * APAD + kd + (midx >> 1) * 8) * 2;
            ldm4(qh4, sQh + qoff);
            ldm4(ql4, sQl + qoff);
            #pragma unroll
            for (int np = 0; np < 4; np++) {
                uint32_t kh4[4];
                const uint32_t koff =
                    ((np * 16 + (midx >> 1) * 8 + lrow) * APAD + kd + (midx & 1) * 8) * 2;
                ldm4(kh4, sKh + koff);
                #pragma unroll
                for (int h2 = 0; h2 < 2; h2++) {
                    const int nt = np * 2 + h2;
                    mma_f16(sacc[nt], qh4, kh4[h2 * 2], kh4[h2 * 2 + 1]);
                    mma_f16(sacc[nt], ql4, kh4[h2 * 2], kh4[h2 * 2 + 1]);
                }
            }
        }

        __syncthreads();                 // all warps done reading K buffer
        if (kt + 1 < NT) loadK(kt + 1);  // overlaps softmax + PV below
        CP_COMMIT();

        // ---- online softmax in log2 space (MUFU ex2; 4-lane row groups) ----
        float mx0 = -INFINITY, mx1 = -INFINITY;
        #pragma unroll
        for (int n = 0; n < 8; n++) {
            mx0 = fmaxf(mx0, fmaxf(sacc[n][0], sacc[n][1]));
            mx1 = fmaxf(mx1, fmaxf(sacc[n][2], sacc[n][3]));
        }
        mx0 = fmaxf(mx0, __shfl_xor_sync(0xffffffffu, mx0, 1));
        mx0 = fmaxf(mx0, __shfl_xor_sync(0xffffffffu, mx0, 2));
        mx1 = fmaxf(mx1, __shfl_xor_sync(0xffffffffu, mx1, 1));
        mx1 = fmaxf(mx1, __shfl_xor_sync(0xffffffffu, mx1, 2));

        const float mn0 = fmaxf(m0v, mx0), a0v = ex2f(m0v - mn0);
        const float mn1 = fmaxf(m1v, mx1), a1v = ex2f(m1v - mn1);
        m0v = mn0; m1v = mn1;

        float rs0 = 0.f, rs1 = 0.f;
        #pragma unroll
        for (int n = 0; n < 8; n++) {
            sacc[n][0] = ex2f(sacc[n][0] - mn0); rs0 += sacc[n][0];
            sacc[n][1] = ex2f(sacc[n][1] - mn0); rs0 += sacc[n][1];
            sacc[n][2] = ex2f(sacc[n][2] - mn1); rs1 += sacc[n][2];
            sacc[n][3] = ex2f(sacc[n][3] - mn1); rs1 += sacc[n][3];
        }
        rs0 += __shfl_xor_sync(0xffffffffu, rs0, 1);
        rs0 += __shfl_xor_sync(0xffffffffu, rs0, 2);
        rs1 += __shfl_xor_sync(0xffffffffu, rs1, 1);
        rs1 += __shfl_xor_sync(0xffffffffu, rs1, 2);
        l0 = l0 * a0v + rs0;
        l1 = l1 * a1v + rs1;

        #pragma unroll
        for (int d = 0; d < 12; d++) {
            oacc[d][0] *= a0v; oacc[d][1] *= a0v;
            oacc[d][2] *= a1v; oacc[d][3] *= a1v;
        }

        CP_WAIT1();                      // V(kt) ready (K(kt+1) still in flight)
        __syncthreads();

        // ---- O += P V  (single fp16 product; P packed via one cvt) ----
        #pragma unroll
        for (int st = 0; st < 4; st++) {
            uint32_t ph[4];
            ph[0] = packh2(sacc[2*st][0],   sacc[2*st][1]);
            ph[1] = packh2(sacc[2*st][2],   sacc[2*st][3]);
            ph[2] = packh2(sacc[2*st+1][0], sacc[2*st+1][1]);
            ph[3] = packh2(sacc[2*st+1][2], sacc[2*st+1][3]);
            #pragma unroll
            for (int dp = 0; dp < 6; dp++) {
                uint32_t vh4[4];
                const uint32_t voff =
                    ((st * 16 + (midx & 1) * 8 + lrow) * APAD + dp * 16 + (midx >> 1) * 8) * 2;
                ldm4t(vh4, sVh + voff);
                mma_f16(oacc[dp*2],   ph, vh4[0], vh4[1]);
                mma_f16(oacc[dp*2+1], ph, vh4[2], vh4[3]);
            }
        }

        __syncthreads();                 // all warps done reading V buffer
        if (kt + 1 < NT) loadV(kt + 1);  // overlaps next S-phase
        CP_COMMIT();
    }

    // epilogue: /(l*sqrt(96)), write fp16 split directly into O-proj operand
    const float inv0 = 0.10206207261596577f / l0;
    const float inv1 = 0.10206207261596577f / l1;
    const int bb = bh >> 3, h = bh & 7;
    const int row0 = q0 + wid * 16 + (lane >> 2);
    __half* o0 = g_Oc + (size_t)(bb * SEQ + row0) * KC2 + h * HD + (lane & 3) * 2;
    __half* o1 = o0 + (size_t)8 * KC2;
    #pragma unroll
    for (int dp = 0; dp < 12; dp++) {
        float v0 = oacc[dp][0] * inv0, v1 = oacc[dp][1] * inv0;
        uint32_t hh, ll;
        split2h(v0, v1, hh, ll);
        *(uint32_t*)(o0 + dp * 8)       = hh;
        *(uint32_t*)(o0 + EMB + dp * 8) = ll;
        v0 = oacc[dp][2] * inv1; v1 = oacc[dp][3] * inv1;
        split2h(v0, v1, hh, ll);
        *(uint32_t*)(o1 + dp * 8)       = hh;
        *(uint32_t*)(o1 + EMB + dp * 8) = ll;
    }
}

// ---------------------------------------------------------------------------
extern "C" void kernel_launch(void* const* d_in, const int* in_sizes, int n_in,
                              void* d_out, int out_size)
{
    const float* x  = (const float*)d_in[0];
    const float* Wq = (const float*)d_in[1];
    const float* bq = (const float*)d_in[2];
    const float* Wk = (const float*)d_in[3];
    const float* bk = (const float*)d_in[4];
    const float* Wv = (const float*)d_in[5];
    const float* bv = (const float*)d_in[6];
    const float* Wo = (const float*)d_in[7];
    const float* bo = (const float*)d_in[8];
    float* out = (float*)d_out;

    __half *xc, *oc, *wc, *qh, *ql, *kh, *vh;
    cudaGetSymbolAddress((void**)&xc, g_Xc);
    cudaGetSymbolAddress((void**)&oc, g_Oc);
    cudaGetSymbolAddress((void**)&wc, g_Wc);
    cudaGetSymbolAddress((void**)&qh, g_Qh);
    cudaGetSymbolAddress((void**)&ql, g_Ql);
    cudaGetSymbolAddress((void**)&kh, g_Kh);
    cudaGetSymbolAddress((void**)&vh, g_Vh);

    convert_cat<<<MTOT * 192 / 256, 256>>>(x, xc);
    wconvert_all<<<dim3(EMB / 32, EMB / 32, 4), dim3(32, 8)>>>(Wq, Wk, Wv, Wo, wc);

    cudaFuncSetAttribute(gemm_qkv, cudaFuncAttributeMaxDynamicSharedMemorySize, GEMM_SMEM);
    cudaFuncSetAttribute(gemm_o,   cudaFuncAttributeMaxDynamicSharedMemorySize, GEMM_SMEM);

    gemm_qkv<<<dim3(EMB / 128, MTOT / 128, 3), 256, GEMM_SMEM>>>(
        xc, wc, bq, bk, bv, qh, ql, kh, vh);

    cudaFuncSetAttribute(attn_mma, cudaFuncAttributeMaxDynamicSharedMemorySize, ATTN_SMEM);
    attn_mma<<<dim3(SEQ / 128, BHN), 256, ATTN_SMEM>>>();

    __half* wco = wc + (size_t)3 * EMB * KC3;
    gemm_o<<<dim3(EMB / 128, MTOT / 128), 256, GEMM_SMEM>>>(oc, wco, bo, out);
}

// round 9
// speedup vs baseline: 7.9018x; 1.2432x over previous
#include <cuda_runtime.h>
#include <cuda_fp16.h>
#include <cstdint>
#include <math.h>

#define EMB   768
#define HEADS 8
#define HD    96
#define BATCH 4
#define SEQ   2048
#define BHN   (BATCH*HEADS)
#define MTOT  (BATCH*SEQ)
#define KC2   (2*EMB)        // 1536 (2-segment operands)
#define LOG2E 1.4426950408889634f

// ---------------- scratch globals (module-load allocated) -------------------
__device__ __half g_Xc[(size_t)MTOT * KC2];    // x split [ah, al]
__device__ __half g_Oc[(size_t)MTOT * KC2];    // attn-out split [oh, ol]
__device__ __half g_Wc[4][(size_t)EMB * KC2];  // W^T segs [bh, bh]
__device__ __half g_Qh[(size_t)BHN * SEQ * HD];
__device__ __half g_Kh[(size_t)BHN * SEQ * HD];
__device__ __half g_Vh[(size_t)BHN * SEQ * HD];

// ---------------- helpers ---------------------------------------------------
__device__ __forceinline__ uint32_t smem_u32(const void* p) {
    uint32_t a;
    asm("{ .reg .u64 t; cvta.to.shared.u64 t, %1; cvt.u32.u64 %0, t; }" : "=r"(a) : "l"(p));
    return a;
}
__device__ __forceinline__ void cpa16(uint32_t d, const void* s) {
    asm volatile("cp.async.cg.shared.global [%0], [%1], 16;" :: "r"(d), "l"(s));
}
#define CP_COMMIT() asm volatile("cp.async.commit_group;")
#define CP_WAIT0()  asm volatile("cp.async.wait_group 0;")
#define CP_WAIT1()  asm volatile("cp.async.wait_group 1;")

__device__ __forceinline__ void ldm4(uint32_t* r, uint32_t addr) {
    asm volatile("ldmatrix.sync.aligned.m8n8.x4.shared.b16 {%0,%1,%2,%3}, [%4];"
        : "=r"(r[0]), "=r"(r[1]), "=r"(r[2]), "=r"(r[3]) : "r"(addr));
}
__device__ __forceinline__ void ldm4t(uint32_t* r, uint32_t addr) {
    asm volatile("ldmatrix.sync.aligned.m8n8.x4.trans.shared.b16 {%0,%1,%2,%3}, [%4];"
        : "=r"(r[0]), "=r"(r[1]), "=r"(r[2]), "=r"(r[3]) : "r"(addr));
}
__device__ __forceinline__ void mma_f16(float* c, const uint32_t* a, uint32_t b0, uint32_t b1) {
    asm volatile("mma.sync.aligned.m16n8k16.row.col.f32.f16.f16.f32 "
        "{%0,%1,%2,%3}, {%4,%5,%6,%7}, {%8,%9}, {%0,%1,%2,%3};"
        : "+f"(c[0]), "+f"(c[1]), "+f"(c[2]), "+f"(c[3])
        : "r"(a[0]), "r"(a[1]), "r"(a[2]), "r"(a[3]), "r"(b0), "r"(b1));
}
// guaranteed-MUFU exp2
__device__ __forceinline__ float ex2f(float x) {
    float y;
    asm("ex2.approx.ftz.f32 %0, %1;" : "=f"(y) : "f"(x));
    return y;
}
// pack two fp32 -> fp16x2 {lo=x, hi=y} in one cvt
__device__ __forceinline__ uint32_t packh2(float x, float y) {
    uint32_t r;
    asm("cvt.rn.f16x2.f32 %0, %2, %1;" : "=r"(r) : "f"(x), "f"(y));
    return r;
}
__device__ __forceinline__ void split2h(float x, float y, uint32_t& hi, uint32_t& lo) {
    __half2 h, l;
    h.x = __float2half(x);
    h.y = __float2half(y);
    l.x = __float2half(x - __half2float(h.x));
    l.y = __float2half(y - __half2float(h.y));
    hi = *(uint32_t*)&h;
    lo = *(uint32_t*)&l;
}

// ===========================================================================
// convert x: fp32 [M][768] -> fp16 [M][1536] segments (ah, al)
// ===========================================================================
__global__ __launch_bounds__(256) void convert_cat(
    const float* __restrict__ in, __half* __restrict__ out)
{
    const int i = blockIdx.x * 256 + threadIdx.x;   // < MTOT*192
    const int row = i / 192, c = (i % 192) * 4;
    const float4 v = ((const float4*)in)[i];
    __half h[4], l[4];
    const float vv[4] = {v.x, v.y, v.z, v.w};
    #pragma unroll
    for (int j = 0; j < 4; j++) {
        h[j] = __float2half(vv[j]);
        l[j] = __float2half(vv[j] - __half2float(h[j]));
    }
    __half* o = out + (size_t)row * KC2 + c;
    *(uint2*)(o)       = *(uint2*)h;
    *(uint2*)(o + EMB) = *(uint2*)l;
}

// ===========================================================================
// all-weight transpose + fp16 duplicate: W [k][n] fp32 -> Wc [n][1536] (bh,bh)
// ===========================================================================
__global__ void wconvert_all(const float* __restrict__ Wq, const float* __restrict__ Wk,
                             const float* __restrict__ Wv, const float* __restrict__ Wo,
                             __half* __restrict__ wc)
{
    __shared__ float t[32][33];
    const int z = blockIdx.z;
    const float* W = (z == 0) ? Wq : (z == 1) ? Wk : (z == 2) ? Wv : Wo;
    __half* out = wc + (size_t)z * EMB * KC2;

    const int tx = threadIdx.x, ty = threadIdx.y;
    const int x = blockIdx.x * 32 + tx;
    const int y0 = blockIdx.y * 32;
    #pragma unroll
    for (int i = ty; i < 32; i += 8)
        t[i][tx] = W[(size_t)(y0 + i) * EMB + x];
    __syncthreads();
    #pragma unroll
    for (int i = ty; i < 32; i += 8) {
        const int n = blockIdx.x * 32 + i;
        const int k = y0 + tx;
        const __half h = __float2half(t[tx][i]);
        __half* o = out + (size_t)n * KC2 + k;
        o[0]   = h;
        o[EMB] = h;
    }
}

// ===========================================================================
// shared GEMM core: k-chunk 64, SW128-xor swizzle (no padding), 3-stage.
// ===========================================================================
#define GSTAGE (256 * 128)                    // 32768 B per stage
#define GEMM_SMEM (3 * GSTAGE)                // 98304 B

__device__ __forceinline__ void gemm_core(
    const __half* __restrict__ A, const __half* __restrict__ B,
    int strideA, int strideB, int ktot, uint32_t sb,
    int tid, int wm, int wn, int midx, int lrow, int m0, int n0,
    float acc[4][4][4])
{
    auto load_chunk = [&](int c, int s) {
        const uint32_t base = sb + s * GSTAGE;
        #pragma unroll
        for (int t = 0; t < 8; t++) {
            const int idx = tid + t * 256;        // 0..2047
            const int row = idx >> 3, seg = idx & 7;
            const uint32_t dst = base + row * 128 + ((seg ^ (row & 7)) * 16);
            const __half* src = (row < 128)
                ? A + (size_t)(m0 + row) * strideA + c * 64 + seg * 8
                : B + (size_t)(n0 + row - 128) * strideB + c * 64 + seg * 8;
            cpa16(dst, src);
        }
    };

    auto compute = [&](int s) {
        const uint32_t base = sb + s * GSTAGE;
        #pragma unroll
        for (int kk8 = 0; kk8 < 8; kk8 += 2) {    // k in 8-half granules
            uint32_t af[4][4];
            const int sa = kk8 + (midx >> 1);
            #pragma unroll
            for (int mt = 0; mt < 4; mt++) {
                const int r = wm + mt * 16 + (midx & 1) * 8 + lrow;
                ldm4(af[mt], base + r * 128 + ((sa ^ (r & 7)) * 16));
            }
            const int sbg = kk8 + (midx & 1);
            #pragma unroll
            for (int np = 0; np < 2; np++) {
                uint32_t bf4[4];
                const int rb = wn + np * 16 + (midx >> 1) * 8 + lrow;
                ldm4(bf4, base + 16384 + rb * 128 + ((sbg ^ (rb & 7)) * 16));
                #pragma unroll
                for (int h2 = 0; h2 < 2; h2++) {
                    const int nt = np * 2 + h2;
                    #pragma unroll
                    for (int mt = 0; mt < 4; mt++)
                        mma_f16(acc[mt][nt], af[mt], bf4[h2 * 2], bf4[h2 * 2 + 1]);
                }
            }
        }
    };

    const int nch = ktot / 64;
    load_chunk(0, 0); CP_COMMIT();
    load_chunk(1, 1); CP_COMMIT();
    for (int c = 0; c < nch; c++) {
        CP_WAIT1();
        __syncthreads();
        if (c + 2 < nch) load_chunk(c + 2, (c + 2) % 3);
        CP_COMMIT();
        compute(c % 3);
    }
}

// ===========================================================================
// fused QKV projection: blockIdx.z = {0:Q, 1:K, 2:V}; all K-depth 1536,
// hi-only fp16 outputs [bh][n][96]; Q pre-scaled by log2(e).
// ===========================================================================
__global__ __launch_bounds__(256, 2) void gemm_qkv(
    const __half* __restrict__ A, const __half* __restrict__ wc,
    const float* __restrict__ bq, const float* __restrict__ bk,
    const float* __restrict__ bv,
    __half* __restrict__ qh, __half* __restrict__ kh, __half* __restrict__ vh)
{
    extern __shared__ __half gsm[];
    const uint32_t sbA = smem_u32(gsm);
    const int tid = threadIdx.x;
    const int wid = tid >> 5, lane = tid & 31;
    const int midx = lane >> 3, lrow = lane & 7;
    const int m0 = blockIdx.y * 128, n0 = blockIdx.x * 128;
    const int wm = (wid & 1) * 64, wn = (wid >> 1) * 32;
    const int z = blockIdx.z;

    const __half* B = wc + (size_t)z * EMB * KC2;
    const float* bias = (z == 0) ? bq : (z == 1) ? bk : bv;
    __half* out0 = (z == 0) ? qh : (z == 1) ? kh : vh;
    const float scale = (z == 0) ? LOG2E : 1.0f;

    float acc[4][4][4];
    #pragma unroll
    for (int a = 0; a < 4; a++)
        #pragma unroll
        for (int b = 0; b < 4; b++)
            #pragma unroll
            for (int c = 0; c < 4; c++) acc[a][b][c] = 0.f;

    gemm_core(A, B, KC2, KC2, KC2, sbA, tid, wm, wn, midx, lrow, m0, n0, acc);

    #pragma unroll
    for (int mt = 0; mt < 4; mt++) {
        #pragma unroll
        for (int nt = 0; nt < 4; nt++) {
            const int r  = wm + mt * 16 + (lane >> 2);
            const int cc = n0 + wn + nt * 8 + (lane & 3) * 2;
            #pragma unroll
            for (int half = 0; half < 2; half++) {       // rows r, r+8
                const int m = m0 + r + half * 8;
                const float v0 = (acc[mt][nt][half * 2]     + bias[cc])     * scale;
                const float v1 = (acc[mt][nt][half * 2 + 1] + bias[cc + 1]) * scale;
                const int bb = m >> 11, nn = m & (SEQ - 1);
                const int h = cc / HD, d = cc % HD;       // pair stays in one head
                const size_t i0 = ((size_t)(bb * HEADS + h) * SEQ + nn) * HD + d;
                *(uint32_t*)(out0 + i0) = packh2(v0, v1);
            }
        }
    }
}

// ===========================================================================
// output projection: fp32 natural [m][768]
// ===========================================================================
__global__ __launch_bounds__(256, 2) void gemm_o(
    const __half* __restrict__ A, const __half* __restrict__ B,
    const float* __restrict__ bias, float* __restrict__ outf)
{
    extern __shared__ __half gsm[];
    const uint32_t sbA = smem_u32(gsm);
    const int tid = threadIdx.x;
    const int wid = tid >> 5, lane = tid & 31;
    const int midx = lane >> 3, lrow = lane & 7;
    const int m0 = blockIdx.y * 128, n0 = blockIdx.x * 128;
    const int wm = (wid & 1) * 64, wn = (wid >> 1) * 32;

    float acc[4][4][4];
    #pragma unroll
    for (int a = 0; a < 4; a++)
        #pragma unroll
        for (int b = 0; b < 4; b++)
            #pragma unroll
            for (int c = 0; c < 4; c++) acc[a][b][c] = 0.f;

    gemm_core(A, B, KC2, KC2, KC2, sbA, tid, wm, wn, midx, lrow, m0, n0, acc);

    #pragma unroll
    for (int mt = 0; mt < 4; mt++) {
        #pragma unroll
        for (int nt = 0; nt < 4; nt++) {
            const int r  = wm + mt * 16 + (lane >> 2);
            const int cc = n0 + wn + nt * 8 + (lane & 3) * 2;
            #pragma unroll
            for (int half = 0; half < 2; half++) {
                const int m = m0 + r + half * 8;
                *(float2*)(outf + (size_t)m * EMB + cc) = make_float2(
                    acc[mt][nt][half * 2] + bias[cc],
                    acc[mt][nt][half * 2 + 1] + bias[cc + 1]);
            }
        }
    }
}

// ===========================================================================
// Flash attention: S = qh·kh (single fp16 product each side),
// PV single-product, MUFU exp2, split-phase K/V prefetch.
// ===========================================================================
#define APAD 104
#define ATTN_SMEM ((128 + 2 * 64) * APAD * 2)            // 53248 B

__global__ __launch_bounds__(256, 2) void attn_mma()
{
    extern __shared__ __half asmem[];
    const uint32_t sQh = smem_u32(asmem);
    const uint32_t sKh = sQh + 128 * APAD * 2;
    const uint32_t sVh = sKh + 64 * APAD * 2;

    const int tid = threadIdx.x;
    const int wid = tid >> 5, lane = tid & 31;
    const int midx = lane >> 3, lrow = lane & 7;
    const int q0 = blockIdx.x * 128;
    const int bh = blockIdx.y;

    const __half* bQh = g_Qh + (size_t)bh * SEQ * HD;
    const __half* bKh = g_Kh + (size_t)bh * SEQ * HD;
    const __half* bVh = g_Vh + (size_t)bh * SEQ * HD;

    auto loadK = [&](int kt) {
        #pragma unroll
        for (int t = 0; t < 3; t++) {
            const int i = tid + t * 256;                 // < 768
            const int r = i / 12, seg = i % 12;
            cpa16(sKh + (r * APAD + seg * 8) * 2, bKh + (size_t)(kt * 64 + r) * HD + seg * 8);
        }
    };
    auto loadV = [&](int kt) {
        #pragma unroll
        for (int t = 0; t < 3; t++) {
            const int i = tid + t * 256;                 // < 768
            const int r = i / 12, seg = i % 12;
            cpa16(sVh + (r * APAD + seg * 8) * 2, bVh + (size_t)(kt * 64 + r) * HD + seg * 8);
        }
    };

    // prologue: Q + K0 in group 0, V0 in group 1
    #pragma unroll
    for (int t = 0; t < 6; t++) {
        const int i = tid + t * 256;                     // < 1536
        const int r = i / 12, seg = i % 12;
        cpa16(sQh + (r * APAD + seg * 8) * 2, bQh + (size_t)(q0 + r) * HD + seg * 8);
    }
    loadK(0);
    CP_COMMIT();
    loadV(0);
    CP_COMMIT();

    float m0v = -INFINITY, m1v = -INFINITY, l0 = 0.f, l1 = 0.f;
    float oacc[12][4];
    #pragma unroll
    for (int d = 0; d < 12; d++)
        #pragma unroll
        for (int c = 0; c < 4; c++) oacc[d][c] = 0.f;

    const int NT = SEQ / 64;
    for (int kt = 0; kt < NT; kt++) {
        CP_WAIT1();                      // K(kt) (+Q on first iter) ready
        __syncthreads();

        // ---- S (log2-space) = Qh Kh^T, single product ----
        float sacc[8][4];
        #pragma unroll
        for (int n = 0; n < 8; n++)
            #pragma unroll
            for (int c = 0; c < 4; c++) sacc[n][c] = 0.f;

        #pragma unroll
        for (int kd = 0; kd < HD; kd += 16) {
            uint32_t qh4[4];
            const uint32_t qoff =
                ((wid * 16 + (midx & 1) * 8 + lrow) * APAD + kd + (midx >> 1) * 8) * 2;
            ldm4(qh4, sQh + qoff);
            #pragma unroll
            for (int np = 0; np < 4; np++) {
                uint32_t kh4[4];
                const uint32_t koff =
                    ((np * 16 + (midx >> 1) * 8 + lrow) * APAD + kd + (midx & 1) * 8) * 2;
                ldm4(kh4, sKh + koff);
                #pragma unroll
                for (int h2 = 0; h2 < 2; h2++)
                    mma_f16(sacc[np * 2 + h2], qh4, kh4[h2 * 2], kh4[h2 * 2 + 1]);
            }
        }

        __syncthreads();                 // all warps done reading K buffer
        if (kt + 1 < NT) loadK(kt + 1);  // overlaps softmax + PV below
        CP_COMMIT();

        // ---- online softmax in log2 space (MUFU ex2; 4-lane row groups) ----
        float mx0 = -INFINITY, mx1 = -INFINITY;
        #pragma unroll
        for (int n = 0; n < 8; n++) {
            mx0 = fmaxf(mx0, fmaxf(sacc[n][0], sacc[n][1]));
            mx1 = fmaxf(mx1, fmaxf(sacc[n][2], sacc[n][3]));
        }
        mx0 = fmaxf(mx0, __shfl_xor_sync(0xffffffffu, mx0, 1));
        mx0 = fmaxf(mx0, __shfl_xor_sync(0xffffffffu, mx0, 2));
        mx1 = fmaxf(mx1, __shfl_xor_sync(0xffffffffu, mx1, 1));
        mx1 = fmaxf(mx1, __shfl_xor_sync(0xffffffffu, mx1, 2));

        const float mn0 = fmaxf(m0v, mx0), a0v = ex2f(m0v - mn0);
        const float mn1 = fmaxf(m1v, mx1), a1v = ex2f(m1v - mn1);
        m0v = mn0; m1v = mn1;

        float rs0 = 0.f, rs1 = 0.f;
        #pragma unroll
        for (int n = 0; n < 8; n++) {
            sacc[n][0] = ex2f(sacc[n][0] - mn0); rs0 += sacc[n][0];
            sacc[n][1] = ex2f(sacc[n][1] - mn0); rs0 += sacc[n][1];
            sacc[n][2] = ex2f(sacc[n][2] - mn1); rs1 += sacc[n][2];
            sacc[n][3] = ex2f(sacc[n][3] - mn1); rs1 += sacc[n][3];
        }
        rs0 += __shfl_xor_sync(0xffffffffu, rs0, 1);
        rs0 += __shfl_xor_sync(0xffffffffu, rs0, 2);
        rs1 += __shfl_xor_sync(0xffffffffu, rs1, 1);
        rs1 += __shfl_xor_sync(0xffffffffu, rs1, 2);
        l0 = l0 * a0v + rs0;
        l1 = l1 * a1v + rs1;

        #pragma unroll
        for (int d = 0; d < 12; d++) {
            oacc[d][0] *= a0v; oacc[d][1] *= a0v;
            oacc[d][2] *= a1v; oacc[d][3] *= a1v;
        }

        CP_WAIT1();                      // V(kt) ready (K(kt+1) still in flight)
        __syncthreads();

        // ---- O += P V  (single fp16 product; P packed via one cvt) ----
        #pragma unroll
        for (int st = 0; st < 4; st++) {
            uint32_t ph[4];
            ph[0] = packh2(sacc[2*st][0],   sacc[2*st][1]);
            ph[1] = packh2(sacc[2*st][2],   sacc[2*st][3]);
            ph[2] = packh2(sacc[2*st+1][0], sacc[2*st+1][1]);
            ph[3] = packh2(sacc[2*st+1][2], sacc[2*st+1][3]);
            #pragma unroll
            for (int dp = 0; dp < 6; dp++) {
                uint32_t vh4[4];
                const uint32_t voff =
                    ((st * 16 + (midx & 1) * 8 + lrow) * APAD + dp * 16 + (midx >> 1) * 8) * 2;
                ldm4t(vh4, sVh + voff);
                mma_f16(oacc[dp*2],   ph, vh4[0], vh4[1]);
                mma_f16(oacc[dp*2+1], ph, vh4[2], vh4[3]);
            }
        }

        __syncthreads();                 // all warps done reading V buffer
        if (kt + 1 < NT) loadV(kt + 1);  // overlaps next S-phase
        CP_COMMIT();
    }

    // epilogue: /(l*sqrt(96)), write fp16 split directly into O-proj operand
    const float inv0 = 0.10206207261596577f / l0;
    const float inv1 = 0.10206207261596577f / l1;
    const int bb = bh >> 3, h = bh & 7;
    const int row0 = q0 + wid * 16 + (lane >> 2);
    __half* o0 = g_Oc + (size_t)(bb * SEQ + row0) * KC2 + h * HD + (lane & 3) * 2;
    __half* o1 = o0 + (size_t)8 * KC2;
    #pragma unroll
    for (int dp = 0; dp < 12; dp++) {
        float v0 = oacc[dp][0] * inv0, v1 = oacc[dp][1] * inv0;
        uint32_t hh, ll;
        split2h(v0, v1, hh, ll);
        *(uint32_t*)(o0 + dp * 8)       = hh;
        *(uint32_t*)(o0 + EMB + dp * 8) = ll;
        v0 = oacc[dp][2] * inv1; v1 = oacc[dp][3] * inv1;
        split2h(v0, v1, hh, ll);
        *(uint32_t*)(o1 + dp * 8)       = hh;
        *(uint32_t*)(o1 + EMB + dp * 8) = ll;
    }
}

// ---------------------------------------------------------------------------
extern "C" void kernel_launch(void* const* d_in, const int* in_sizes, int n_in,
                              void* d_out, int out_size)
{
    const float* x  = (const float*)d_in[0];
    const float* Wq = (const float*)d_in[1];
    const float* bq = (const float*)d_in[2];
    const float* Wk = (const float*)d_in[3];
    const float* bk = (const float*)d_in[4];
    const float* Wv = (const float*)d_in[5];
    const float* bv = (const float*)d_in[6];
    const float* Wo = (const float*)d_in[7];
    const float* bo = (const float*)d_in[8];
    float* out = (float*)d_out;

    __half *xc, *oc, *wc, *qh, *kh, *vh;
    cudaGetSymbolAddress((void**)&xc, g_Xc);
    cudaGetSymbolAddress((void**)&oc, g_Oc);
    cudaGetSymbolAddress((void**)&wc, g_Wc);
    cudaGetSymbolAddress((void**)&qh, g_Qh);
    cudaGetSymbolAddress((void**)&kh, g_Kh);
    cudaGetSymbolAddress((void**)&vh, g_Vh);

    convert_cat<<<MTOT * 192 / 256, 256>>>(x, xc);
    wconvert_all<<<dim3(EMB / 32, EMB / 32, 4), dim3(32, 8)>>>(Wq, Wk, Wv, Wo, wc);

    cudaFuncSetAttribute(gemm_qkv, cudaFuncAttributeMaxDynamicSharedMemorySize, GEMM_SMEM);
    cudaFuncSetAttribute(gemm_o,   cudaFuncAttributeMaxDynamicSharedMemorySize, GEMM_SMEM);

    gemm_qkv<<<dim3(EMB / 128, MTOT / 128, 3), 256, GEMM_SMEM>>>(
        xc, wc, bq, bk, bv, qh, kh, vh);

    cudaFuncSetAttribute(attn_mma, cudaFuncAttributeMaxDynamicSharedMemorySize, ATTN_SMEM);
    attn_mma<<<dim3(SEQ / 128, BHN), 256, ATTN_SMEM>>>();

    __half* wco = wc + (size_t)3 * EMB * KC2;
    gemm_o<<<dim3(EMB / 128, MTOT / 128), 256, GEMM_SMEM>>>(oc, wco, bo, out);
}

// round 10
// speedup vs baseline: 8.9726x; 1.1355x over previous
#include <cuda_runtime.h>
#include <cuda_fp16.h>
#include <cstdint>
#include <math.h>

#define EMB   768
#define HEADS 8
#define HD    96
#define BATCH 4
#define SEQ   2048
#define BHN   (BATCH*HEADS)
#define MTOT  (BATCH*SEQ)
#define KC2   (2*EMB)        // 1536 (compensated operands: Q, K)
#define LOG2E 1.4426950408889634f

// ---------------- scratch globals (module-load allocated) -------------------
__device__ __half g_Xc[(size_t)MTOT * KC2];    // x split [ah, al]
__device__ __half g_Oc[(size_t)MTOT * EMB];    // attn-out hi-only fp16
__device__ __half g_Wc[4][(size_t)EMB * KC2];  // W^T: Q/K=[bh,bh] str 1536, V/O=[bh] str 768
__device__ __half g_Qh[(size_t)BHN * SEQ * HD];
__device__ __half g_Kh[(size_t)BHN * SEQ * HD];
__device__ __half g_Vh[(size_t)BHN * SEQ * HD];

// ---------------- helpers ---------------------------------------------------
__device__ __forceinline__ uint32_t smem_u32(const void* p) {
    uint32_t a;
    asm("{ .reg .u64 t; cvta.to.shared.u64 t, %1; cvt.u32.u64 %0, t; }" : "=r"(a) : "l"(p));
    return a;
}
__device__ __forceinline__ void cpa16(uint32_t d, const void* s) {
    asm volatile("cp.async.cg.shared.global [%0], [%1], 16;" :: "r"(d), "l"(s));
}
#define CP_COMMIT() asm volatile("cp.async.commit_group;")
#define CP_WAIT0()  asm volatile("cp.async.wait_group 0;")
#define CP_WAIT1()  asm volatile("cp.async.wait_group 1;")

__device__ __forceinline__ void ldm4(uint32_t* r, uint32_t addr) {
    asm volatile("ldmatrix.sync.aligned.m8n8.x4.shared.b16 {%0,%1,%2,%3}, [%4];"
        : "=r"(r[0]), "=r"(r[1]), "=r"(r[2]), "=r"(r[3]) : "r"(addr));
}
__device__ __forceinline__ void ldm4t(uint32_t* r, uint32_t addr) {
    asm volatile("ldmatrix.sync.aligned.m8n8.x4.trans.shared.b16 {%0,%1,%2,%3}, [%4];"
        : "=r"(r[0]), "=r"(r[1]), "=r"(r[2]), "=r"(r[3]) : "r"(addr));
}
__device__ __forceinline__ void mma_f16(float* c, const uint32_t* a, uint32_t b0, uint32_t b1) {
    asm volatile("mma.sync.aligned.m16n8k16.row.col.f32.f16.f16.f32 "
        "{%0,%1,%2,%3}, {%4,%5,%6,%7}, {%8,%9}, {%0,%1,%2,%3};"
        : "+f"(c[0]), "+f"(c[1]), "+f"(c[2]), "+f"(c[3])
        : "r"(a[0]), "r"(a[1]), "r"(a[2]), "r"(a[3]), "r"(b0), "r"(b1));
}
// guaranteed-MUFU exp2
__device__ __forceinline__ float ex2f(float x) {
    float y;
    asm("ex2.approx.ftz.f32 %0, %1;" : "=f"(y) : "f"(x));
    return y;
}
// pack two fp32 -> fp16x2 {lo=x, hi=y} in one cvt
__device__ __forceinline__ uint32_t packh2(float x, float y) {
    uint32_t r;
    asm("cvt.rn.f16x2.f32 %0, %2, %1;" : "=r"(r) : "f"(x), "f"(y));
    return r;
}

// ===========================================================================
// convert x: fp32 [M][768] -> fp16 [M][1536] segments (ah, al)
// ===========================================================================
__global__ __launch_bounds__(256) void convert_cat(
    const float* __restrict__ in, __half* __restrict__ out)
{
    const int i = blockIdx.x * 256 + threadIdx.x;   // < MTOT*192
    const int row = i / 192, c = (i % 192) * 4;
    const float4 v = ((const float4*)in)[i];
    __half h[4], l[4];
    const float vv[4] = {v.x, v.y, v.z, v.w};
    #pragma unroll
    for (int j = 0; j < 4; j++) {
        h[j] = __float2half(vv[j]);
        l[j] = __float2half(vv[j] - __half2float(h[j]));
    }
    __half* o = out + (size_t)row * KC2 + c;
    *(uint2*)(o)       = *(uint2*)h;
    *(uint2*)(o + EMB) = *(uint2*)l;
}

// ===========================================================================
// all-weight transpose to fp16. z<2 (Q,K): duplicated (bh,bh) stride 1536;
// z>=2 (V,O): single (bh) stride 768.
// ===========================================================================
__global__ void wconvert_all(const float* __restrict__ Wq, const float* __restrict__ Wk,
                             const float* __restrict__ Wv, const float* __restrict__ Wo,
                             __half* __restrict__ wc)
{
    __shared__ float t[32][33];
    const int z = blockIdx.z;
    const float* W = (z == 0) ? Wq : (z == 1) ? Wk : (z == 2) ? Wv : Wo;
    __half* out = wc + (size_t)z * EMB * KC2;
    const int stride = (z < 2) ? KC2 : EMB;

    const int tx = threadIdx.x, ty = threadIdx.y;
    const int x = blockIdx.x * 32 + tx;
    const int y0 = blockIdx.y * 32;
    #pragma unroll
    for (int i = ty; i < 32; i += 8)
        t[i][tx] = W[(size_t)(y0 + i) * EMB + x];
    __syncthreads();
    #pragma unroll
    for (int i = ty; i < 32; i += 8) {
        const int n = blockIdx.x * 32 + i;
        const int k = y0 + tx;
        const __half h = __float2half(t[tx][i]);
        __half* o = out + (size_t)n * stride + k;
        o[0] = h;
        if (z < 2) o[EMB] = h;
    }
}

// ===========================================================================
// shared GEMM core: k-chunk 64, SW128-xor swizzle (no padding), 3-stage.
// ===========================================================================
#define GSTAGE (256 * 128)                    // 32768 B per stage
#define GEMM_SMEM (3 * GSTAGE)                // 98304 B

__device__ __forceinline__ void gemm_core(
    const __half* __restrict__ A, const __half* __restrict__ B,
    int strideA, int strideB, int ktot, uint32_t sb,
    int tid, int wm, int wn, int midx, int lrow, int m0, int n0,
    float acc[4][4][4])
{
    auto load_chunk = [&](int c, int s) {
        const uint32_t base = sb + s * GSTAGE;
        #pragma unroll
        for (int t = 0; t < 8; t++) {
            const int idx = tid + t * 256;        // 0..2047
            const int row = idx >> 3, seg = idx & 7;
            const uint32_t dst = base + row * 128 + ((seg ^ (row & 7)) * 16);
            const __half* src = (row < 128)
                ? A + (size_t)(m0 + row) * strideA + c * 64 + seg * 8
                : B + (size_t)(n0 + row - 128) * strideB + c * 64 + seg * 8;
            cpa16(dst, src);
        }
    };

    auto compute = [&](int s) {
        const uint32_t base = sb + s * GSTAGE;
        #pragma unroll
        for (int kk8 = 0; kk8 < 8; kk8 += 2) {    // k in 8-half granules
            uint32_t af[4][4];
            const int sa = kk8 + (midx >> 1);
            #pragma unroll
            for (int mt = 0; mt < 4; mt++) {
                const int r = wm + mt * 16 + (midx & 1) * 8 + lrow;
                ldm4(af[mt], base + r * 128 + ((sa ^ (r & 7)) * 16));
            }
            const int sbg = kk8 + (midx & 1);
            #pragma unroll
            for (int np = 0; np < 2; np++) {
                uint32_t bf4[4];
                const int rb = wn + np * 16 + (midx >> 1) * 8 + lrow;
                ldm4(bf4, base + 16384 + rb * 128 + ((sbg ^ (rb & 7)) * 16));
                #pragma unroll
                for (int h2 = 0; h2 < 2; h2++) {
                    const int nt = np * 2 + h2;
                    #pragma unroll
                    for (int mt = 0; mt < 4; mt++)
                        mma_f16(acc[mt][nt], af[mt], bf4[h2 * 2], bf4[h2 * 2 + 1]);
                }
            }
        }
    };

    const int nch = ktot / 64;
    load_chunk(0, 0); CP_COMMIT();
    load_chunk(1, 1); CP_COMMIT();
    for (int c = 0; c < nch; c++) {
        CP_WAIT1();
        __syncthreads();
        if (c + 2 < nch) load_chunk(c + 2, (c + 2) % 3);
        CP_COMMIT();
        compute(c % 3);
    }
}

// ===========================================================================
// fused QKV projection: blockIdx.z = {0:Q, 1:K, 2:V}
// Q/K: K-depth 1536 compensated; V: K-depth 768 single product.
// hi-only fp16 outputs [bh][n][96]; Q pre-scaled by log2(e).
// ===========================================================================
__global__ __launch_bounds__(256, 2) void gemm_qkv(
    const __half* __restrict__ A, const __half* __restrict__ wc,
    const float* __restrict__ bq, const float* __restrict__ bk,
    const float* __restrict__ bv,
    __half* __restrict__ qh, __half* __restrict__ kh, __half* __restrict__ vh)
{
    extern __shared__ __half gsm[];
    const uint32_t sbA = smem_u32(gsm);
    const int tid = threadIdx.x;
    const int wid = tid >> 5, lane = tid & 31;
    const int midx = lane >> 3, lrow = lane & 7;
    const int m0 = blockIdx.y * 128, n0 = blockIdx.x * 128;
    const int wm = (wid & 1) * 64, wn = (wid >> 1) * 32;
    const int z = blockIdx.z;

    const __half* B = wc + (size_t)z * EMB * KC2;
    const int kdep = (z < 2) ? KC2 : EMB;
    const float* bias = (z == 0) ? bq : (z == 1) ? bk : bv;
    __half* out0 = (z == 0) ? qh : (z == 1) ? kh : vh;
    const float scale = (z == 0) ? LOG2E : 1.0f;

    float acc[4][4][4];
    #pragma unroll
    for (int a = 0; a < 4; a++)
        #pragma unroll
        for (int b = 0; b < 4; b++)
            #pragma unroll
            for (int c = 0; c < 4; c++) acc[a][b][c] = 0.f;

    gemm_core(A, B, KC2, kdep, kdep, sbA, tid, wm, wn, midx, lrow, m0, n0, acc);

    #pragma unroll
    for (int mt = 0; mt < 4; mt++) {
        #pragma unroll
        for (int nt = 0; nt < 4; nt++) {
            const int r  = wm + mt * 16 + (lane >> 2);
            const int cc = n0 + wn + nt * 8 + (lane & 3) * 2;
            #pragma unroll
            for (int half = 0; half < 2; half++) {       // rows r, r+8
                const int m = m0 + r + half * 8;
                const float v0 = (acc[mt][nt][half * 2]     + bias[cc])     * scale;
                const float v1 = (acc[mt][nt][half * 2 + 1] + bias[cc + 1]) * scale;
                const int bb = m >> 11, nn = m & (SEQ - 1);
                const int h = cc / HD, d = cc % HD;       // pair stays in one head
                const size_t i0 = ((size_t)(bb * HEADS + h) * SEQ + nn) * HD + d;
                *(uint32_t*)(out0 + i0) = packh2(v0, v1);
            }
        }
    }
}

// ===========================================================================
// output projection: K-depth 768 single product, fp32 natural [m][768]
// ===========================================================================
__global__ __launch_bounds__(256, 2) void gemm_o(
    const __half* __restrict__ A, const __half* __restrict__ B,
    const float* __restrict__ bias, float* __restrict__ outf)
{
    extern __shared__ __half gsm[];
    const uint32_t sbA = smem_u32(gsm);
    const int tid = threadIdx.x;
    const int wid = tid >> 5, lane = tid & 31;
    const int midx = lane >> 3, lrow = lane & 7;
    const int m0 = blockIdx.y * 128, n0 = blockIdx.x * 128;
    const int wm = (wid & 1) * 64, wn = (wid >> 1) * 32;

    float acc[4][4][4];
    #pragma unroll
    for (int a = 0; a < 4; a++)
        #pragma unroll
        for (int b = 0; b < 4; b++)
            #pragma unroll
            for (int c = 0; c < 4; c++) acc[a][b][c] = 0.f;

    gemm_core(A, B, EMB, EMB, EMB, sbA, tid, wm, wn, midx, lrow, m0, n0, acc);

    #pragma unroll
    for (int mt = 0; mt < 4; mt++) {
        #pragma unroll
        for (int nt = 0; nt < 4; nt++) {
            const int r  = wm + mt * 16 + (lane >> 2);
            const int cc = n0 + wn + nt * 8 + (lane & 3) * 2;
            #pragma unroll
            for (int half = 0; half < 2; half++) {
                const int m = m0 + r + half * 8;
                *(float2*)(outf + (size_t)m * EMB + cc) = make_float2(
                    acc[mt][nt][half * 2] + bias[cc],
                    acc[mt][nt][half * 2 + 1] + bias[cc + 1]);
            }
        }
    }
}

// ===========================================================================
// Flash attention: S = qh·kh, PV single-product, MUFU exp2,
// split-phase K/V prefetch, conditional oacc rescale.
// ===========================================================================
#define APAD 104
#define ATTN_SMEM ((128 + 2 * 64) * APAD * 2)            // 53248 B

__global__ __launch_bounds__(256, 2) void attn_mma()
{
    extern __shared__ __half asmem[];
    const uint32_t sQh = smem_u32(asmem);
    const uint32_t sKh = sQh + 128 * APAD * 2;
    const uint32_t sVh = sKh + 64 * APAD * 2;

    const int tid = threadIdx.x;
    const int wid = tid >> 5, lane = tid & 31;
    const int midx = lane >> 3, lrow = lane & 7;
    const int q0 = blockIdx.x * 128;
    const int bh = blockIdx.y;

    const __half* bQh = g_Qh + (size_t)bh * SEQ * HD;
    const __half* bKh = g_Kh + (size_t)bh * SEQ * HD;
    const __half* bVh = g_Vh + (size_t)bh * SEQ * HD;

    auto loadK = [&](int kt) {
        #pragma unroll
        for (int t = 0; t < 3; t++) {
            const int i = tid + t * 256;                 // < 768
            const int r = i / 12, seg = i % 12;
            cpa16(sKh + (r * APAD + seg * 8) * 2, bKh + (size_t)(kt * 64 + r) * HD + seg * 8);
        }
    };
    auto loadV = [&](int kt) {
        #pragma unroll
        for (int t = 0; t < 3; t++) {
            const int i = tid + t * 256;                 // < 768
            const int r = i / 12, seg = i % 12;
            cpa16(sVh + (r * APAD + seg * 8) * 2, bVh + (size_t)(kt * 64 + r) * HD + seg * 8);
        }
    };

    // prologue: Q + K0 in group 0, V0 in group 1
    #pragma unroll
    for (int t = 0; t < 6; t++) {
        const int i = tid + t * 256;                     // < 1536
        const int r = i / 12, seg = i % 12;
        cpa16(sQh + (r * APAD + seg * 8) * 2, bQh + (size_t)(q0 + r) * HD + seg * 8);
    }
    loadK(0);
    CP_COMMIT();
    loadV(0);
    CP_COMMIT();

    float m0v = -INFINITY, m1v = -INFINITY, l0 = 0.f, l1 = 0.f;
    float oacc[12][4];
    #pragma unroll
    for (int d = 0; d < 12; d++)
        #pragma unroll
        for (int c = 0; c < 4; c++) oacc[d][c] = 0.f;

    const int NT = SEQ / 64;
    for (int kt = 0; kt < NT; kt++) {
        CP_WAIT1();                      // K(kt) (+Q on first iter) ready
        __syncthreads();

        // ---- S (log2-space) = Qh Kh^T, single product ----
        float sacc[8][4];
        #pragma unroll
        for (int n = 0; n < 8; n++)
            #pragma unroll
            for (int c = 0; c < 4; c++) sacc[n][c] = 0.f;

        #pragma unroll
        for (int kd = 0; kd < HD; kd += 16) {
            uint32_t qh4[4];
            const uint32_t qoff =
                ((wid * 16 + (midx & 1) * 8 + lrow) * APAD + kd + (midx >> 1) * 8) * 2;
            ldm4(qh4, sQh + qoff);
            #pragma unroll
            for (int np = 0; np < 4; np++) {
                uint32_t kh4[4];
                const uint32_t koff =
                    ((np * 16 + (midx >> 1) * 8 + lrow) * APAD + kd + (midx & 1) * 8) * 2;
                ldm4(kh4, sKh + koff);
                #pragma unroll
                for (int h2 = 0; h2 < 2; h2++)
                    mma_f16(sacc[np * 2 + h2], qh4, kh4[h2 * 2], kh4[h2 * 2 + 1]);
            }
        }

        __syncthreads();                 // all warps done reading K buffer
        if (kt + 1 < NT) loadK(kt + 1);  // overlaps softmax + PV below
        CP_COMMIT();

        // ---- online softmax in log2 space (MUFU ex2; 4-lane row groups) ----
        float mx0 = -INFINITY, mx1 = -INFINITY;
        #pragma unroll
        for (int n = 0; n < 8; n++) {
            mx0 = fmaxf(mx0, fmaxf(sacc[n][0], sacc[n][1]));
            mx1 = fmaxf(mx1, fmaxf(sacc[n][2], sacc[n][3]));
        }
        mx0 = fmaxf(mx0, __shfl_xor_sync(0xffffffffu, mx0, 1));
        mx0 = fmaxf(mx0, __shfl_xor_sync(0xffffffffu, mx0, 2));
        mx1 = fmaxf(mx1, __shfl_xor_sync(0xffffffffu, mx1, 1));
        mx1 = fmaxf(mx1, __shfl_xor_sync(0xffffffffu, mx1, 2));

        const float mn0 = fmaxf(m0v, mx0), a0v = ex2f(m0v - mn0);
        const float mn1 = fmaxf(m1v, mx1), a1v = ex2f(m1v - mn1);
        m0v = mn0; m1v = mn1;

        float rs0 = 0.f, rs1 = 0.f;
        #pragma unroll
        for (int n = 0; n < 8; n++) {
            sacc[n][0] = ex2f(sacc[n][0] - mn0); rs0 += sacc[n][0];
            sacc[n][1] = ex2f(sacc[n][1] - mn0); rs0 += sacc[n][1];
            sacc[n][2] = ex2f(sacc[n][2] - mn1); rs1 += sacc[n][2];
            sacc[n][3] = ex2f(sacc[n][3] - mn1); rs1 += sacc[n][3];
        }
        rs0 += __shfl_xor_sync(0xffffffffu, rs0, 1);
        rs0 += __shfl_xor_sync(0xffffffffu, rs0, 2);
        rs1 += __shfl_xor_sync(0xffffffffu, rs1, 1);
        rs1 += __shfl_xor_sync(0xffffffffu, rs1, 2);
        l0 = l0 * a0v + rs0;
        l1 = l1 * a1v + rs1;

        // rescale only when the running max actually moved (alpha < 1)
        if (a0v != 1.f || a1v != 1.f) {
            #pragma unroll
            for (int d = 0; d < 12; d++) {
                oacc[d][0] *= a0v; oacc[d][1] *= a0v;
                oacc[d][2] *= a1v; oacc[d][3] *= a1v;
            }
        }

        CP_WAIT1();                      // V(kt) ready (K(kt+1) still in flight)
        __syncthreads();

        // ---- O += P V  (single fp16 product; P packed via one cvt) ----
        #pragma unroll
        for (int st = 0; st < 4; st++) {
            uint32_t ph[4];
            ph[0] = packh2(sacc[2*st][0],   sacc[2*st][1]);
            ph[1] = packh2(sacc[2*st][2],   sacc[2*st][3]);
            ph[2] = packh2(sacc[2*st+1][0], sacc[2*st+1][1]);
            ph[3] = packh2(sacc[2*st+1][2], sacc[2*st+1][3]);
            #pragma unroll
            for (int dp = 0; dp < 6; dp++) {
                uint32_t vh4[4];
                const uint32_t voff =
                    ((st * 16 + (midx & 1) * 8 + lrow) * APAD + dp * 16 + (midx >> 1) * 8) * 2;
                ldm4t(vh4, sVh + voff);
                mma_f16(oacc[dp*2],   ph, vh4[0], vh4[1]);
                mma_f16(oacc[dp*2+1], ph, vh4[2], vh4[3]);
            }
        }

        __syncthreads();                 // all warps done reading V buffer
        if (kt + 1 < NT) loadV(kt + 1);  // overlaps next S-phase
        CP_COMMIT();
    }

    // epilogue: /(l*sqrt(96)), hi-only fp16 into O-projection operand
    const float inv0 = 0.10206207261596577f / l0;
    const float inv1 = 0.10206207261596577f / l1;
    const int bb = bh >> 3, h = bh & 7;
    const int row0 = q0 + wid * 16 + (lane >> 2);
    __half* o0 = g_Oc + (size_t)(bb * SEQ + row0) * EMB + h * HD + (lane & 3) * 2;
    __half* o1 = o0 + (size_t)8 * EMB;
    #pragma unroll
    for (int dp = 0; dp < 12; dp++) {
        *(uint32_t*)(o0 + dp * 8) = packh2(oacc[dp][0] * inv0, oacc[dp][1] * inv0);
        *(uint32_t*)(o1 + dp * 8) = packh2(oacc[dp][2] * inv1, oacc[dp][3] * inv1);
    }
}

// ---------------------------------------------------------------------------
extern "C" void kernel_launch(void* const* d_in, const int* in_sizes, int n_in,
                              void* d_out, int out_size)
{
    const float* x  = (const float*)d_in[0];
    const float* Wq = (const float*)d_in[1];
    const float* bq = (const float*)d_in[2];
    const float* Wk = (const float*)d_in[3];
    const float* bk = (const float*)d_in[4];
    const float* Wv = (const float*)d_in[5];
    const float* bv = (const float*)d_in[6];
    const float* Wo = (const float*)d_in[7];
    const float* bo = (const float*)d_in[8];
    float* out = (float*)d_out;

    __half *xc, *oc, *wc, *qh, *kh, *vh;
    cudaGetSymbolAddress((void**)&xc, g_Xc);
    cudaGetSymbolAddress((void**)&oc, g_Oc);
    cudaGetSymbolAddress((void**)&wc, g_Wc);
    cudaGetSymbolAddress((void**)&qh, g_Qh);
    cudaGetSymbolAddress((void**)&kh, g_Kh);
    cudaGetSymbolAddress((void**)&vh, g_Vh);

    convert_cat<<<MTOT * 192 / 256, 256>>>(x, xc);
    wconvert_all<<<dim3(EMB / 32, EMB / 32, 4), dim3(32, 8)>>>(Wq, Wk, Wv, Wo, wc);

    cudaFuncSetAttribute(gemm_qkv, cudaFuncAttributeMaxDynamicSharedMemorySize, GEMM_SMEM);
    cudaFuncSetAttribute(gemm_o,   cudaFuncAttributeMaxDynamicSharedMemorySize, GEMM_SMEM);

    gemm_qkv<<<dim3(EMB / 128, MTOT / 128, 3), 256, GEMM_SMEM>>>(
        xc, wc, bq, bk, bv, qh, kh, vh);

    cudaFuncSetAttribute(attn_mma, cudaFuncAttributeMaxDynamicSharedMemorySize, ATTN_SMEM);
    attn_mma<<<dim3(SEQ / 128, BHN), 256, ATTN_SMEM>>>();

    __half* wco = wc + (size_t)3 * EMB * KC2;
    gemm_o<<<dim3(EMB / 128, MTOT / 128), 256, GEMM_SMEM>>>(oc, wco, bo, out);
}